// round 1
// baseline (speedup 1.0000x reference)
#include <cuda_runtime.h>
#include <cuda_bf16.h>
#include <math.h>

// Problem constants
#define BATCH   4
#define SEQ     2048
#define DMODEL  1024
#define NHEADS  16
#define HDIM    64
#define MTOT    (BATCH * SEQ)          // 8192 rows

// ---------------------------------------------------------------------------
// Scratch (static __device__ — no allocations allowed)
// ---------------------------------------------------------------------------
__device__ float g_q[MTOT * DMODEL];
__device__ float g_k[MTOT * DMODEL];
__device__ float g_v[MTOT * DMODEL];
__device__ float g_att[MTOT * DMODEL];

// ---------------------------------------------------------------------------
// SGEMM:  C[m,n] = sum_k A[m,k] * W[n,k] + bias[n]
// A: [M,K] row-major, W: [N,K] row-major (i.e. C = A @ W^T + b)
// Tiles: BM=BN=128, BK=16, 256 threads, 8x8 per-thread microtile.
// M=8192, N=1024, K=1024 — all exact multiples, no bounds checks.
// ---------------------------------------------------------------------------
#define GBM 128
#define GBN 128
#define GBK 16
#define GLDS 132   // padded row length for transposed smem tiles

__global__ __launch_bounds__(256, 2)
void sgemm_tn(const float* __restrict__ A, const float* __restrict__ W,
              const float* __restrict__ bias, float* __restrict__ C,
              int M, int N, int K)
{
    __shared__ __align__(16) float As[GBK * GLDS];
    __shared__ __align__(16) float Ws[GBK * GLDS];

    const int tid = threadIdx.x;
    const int m0 = blockIdx.y * GBM;
    const int n0 = blockIdx.x * GBN;
    const int tx = tid & 15;   // n-direction (8 cols)
    const int ty = tid >> 4;   // m-direction (8 rows)

    float acc[8][8];
#pragma unroll
    for (int i = 0; i < 8; i++)
#pragma unroll
        for (int j = 0; j < 8; j++) acc[i][j] = 0.f;

    for (int k0 = 0; k0 < K; k0 += GBK) {
        // Load 128x16 A tile and 128x16 W tile, store transposed [k][row].
#pragma unroll
        for (int t = 0; t < 2; t++) {
            int idx = tid + t * 256;            // 0..511
            int row = idx >> 2;                 // 0..127
            int c4  = (idx & 3) << 2;           // 0,4,8,12
            float4 a = *(const float4*)&A[(size_t)(m0 + row) * K + k0 + c4];
            As[(c4 + 0) * GLDS + row] = a.x;
            As[(c4 + 1) * GLDS + row] = a.y;
            As[(c4 + 2) * GLDS + row] = a.z;
            As[(c4 + 3) * GLDS + row] = a.w;
            float4 w = *(const float4*)&W[(size_t)(n0 + row) * K + k0 + c4];
            Ws[(c4 + 0) * GLDS + row] = w.x;
            Ws[(c4 + 1) * GLDS + row] = w.y;
            Ws[(c4 + 2) * GLDS + row] = w.z;
            Ws[(c4 + 3) * GLDS + row] = w.w;
        }
        __syncthreads();

#pragma unroll
        for (int kk = 0; kk < GBK; kk++) {
            float4 a0 = *(const float4*)&As[kk * GLDS + ty * 8];
            float4 a1 = *(const float4*)&As[kk * GLDS + ty * 8 + 4];
            float4 b0 = *(const float4*)&Ws[kk * GLDS + tx * 8];
            float4 b1 = *(const float4*)&Ws[kk * GLDS + tx * 8 + 4];
            float av[8] = {a0.x, a0.y, a0.z, a0.w, a1.x, a1.y, a1.z, a1.w};
            float bv[8] = {b0.x, b0.y, b0.z, b0.w, b1.x, b1.y, b1.z, b1.w};
#pragma unroll
            for (int i = 0; i < 8; i++)
#pragma unroll
                for (int j = 0; j < 8; j++)
                    acc[i][j] += av[i] * bv[j];
        }
        __syncthreads();
    }

    // Epilogue: add bias, store.
#pragma unroll
    for (int i = 0; i < 8; i++) {
        int m = m0 + ty * 8 + i;
#pragma unroll
        for (int j4 = 0; j4 < 2; j4++) {
            int n = n0 + tx * 8 + j4 * 4;
            float4 o;
            o.x = acc[i][j4 * 4 + 0] + bias[n + 0];
            o.y = acc[i][j4 * 4 + 1] + bias[n + 1];
            o.z = acc[i][j4 * 4 + 2] + bias[n + 2];
            o.w = acc[i][j4 * 4 + 3] + bias[n + 3];
            *(float4*)&C[(size_t)m * N + n] = o;
        }
    }
}

// ---------------------------------------------------------------------------
// Causal flash attention, fp32.
// q/k/v/out all row-major [B*T, 1024]; head h occupies columns h*64..h*64+63.
// Grid: (T/64, B*H). Block: 256 threads.
// Thread (r = tid>>2, c4 = tid&3):
//   scores : owns keys  key = c4 + 4*kk (kk=0..15)  [interleaved -> conflict-free K reads]
//   output : owns dims  d   = c4*16 + dd (dd=0..15) [contiguous  -> float4 V reads]
// Smem stride 68 floats everywhere (float4-aligned, bank-spread).
// ---------------------------------------------------------------------------
#define AKS 68

__global__ __launch_bounds__(256, 2)
void attn_causal(const float* __restrict__ q, const float* __restrict__ k,
                 const float* __restrict__ v, float* __restrict__ out)
{
    extern __shared__ __align__(16) float sm[];
    float* Qs  = sm;                    // 64*68
    float* Ksm = Qs  + 64 * AKS;        // 64*68
    float* Vs  = Ksm + 64 * AKS;        // 64*68
    float* Ps  = Vs  + 64 * AKS;        // 64*68

    const int tid = threadIdx.x;
    const int r   = tid >> 2;           // query row within tile (0..63)
    const int c4  = tid & 3;            // 4-way split of keys/dims

    const int qt = blockIdx.x;          // query tile (0..31)
    const int bh = blockIdx.y;          // 0..63
    const int b  = bh >> 4;
    const int h  = bh & 15;

    const int q0 = qt * 64;
    const size_t base = (size_t)b * SEQ * DMODEL + (size_t)h * HDIM;
    const float* qb = q + base;
    const float* kb = k + base;
    const float* vb = v + base;

    // Load Q tile (64 rows x 64 floats) into Qs (stride 68)
    for (int i = tid; i < 64 * 16; i += 256) {
        int row = i >> 4;
        int c   = (i & 15) << 2;
        *(float4*)&Qs[row * AKS + c] =
            *(const float4*)&qb[(size_t)(q0 + row) * DMODEL + c];
    }

    float mrow = -1e30f;
    float lrow = 0.f;
    float O[16];
#pragma unroll
    for (int d = 0; d < 16; d++) O[d] = 0.f;

    const int qi = q0 + r;
    const float scale = 0.125f;        // 1/sqrt(64)

    for (int j = 0; j <= qt; j++) {
        const int k0 = j * 64;
        // Load K,V tiles
        for (int i = tid; i < 64 * 16; i += 256) {
            int row = i >> 4;
            int c   = (i & 15) << 2;
            *(float4*)&Ksm[row * AKS + c] =
                *(const float4*)&kb[(size_t)(k0 + row) * DMODEL + c];
            *(float4*)&Vs[row * AKS + c] =
                *(const float4*)&vb[(size_t)(k0 + row) * DMODEL + c];
        }
        __syncthreads();

        // scores: s[kk] = q_row . k_{c4+4kk}
        float s[16];
#pragma unroll
        for (int kk = 0; kk < 16; kk++) s[kk] = 0.f;
#pragma unroll
        for (int d4 = 0; d4 < 16; d4++) {
            float4 q4 = *(const float4*)&Qs[r * AKS + d4 * 4];
#pragma unroll
            for (int kk = 0; kk < 16; kk++) {
                float4 k4 = *(const float4*)&Ksm[(c4 + 4 * kk) * AKS + d4 * 4];
                s[kk] += q4.x * k4.x + q4.y * k4.y + q4.z * k4.z + q4.w * k4.w;
            }
        }

        // mask + online softmax
        float tmax = -1e30f;
#pragma unroll
        for (int kk = 0; kk < 16; kk++) {
            int kj = k0 + c4 + 4 * kk;
            s[kk] = (kj <= qi) ? s[kk] * scale : -1e30f;
            tmax = fmaxf(tmax, s[kk]);
        }
        tmax = fmaxf(tmax, __shfl_xor_sync(0xffffffffu, tmax, 1));
        tmax = fmaxf(tmax, __shfl_xor_sync(0xffffffffu, tmax, 2));
        float mnew  = fmaxf(mrow, tmax);
        float alpha = __expf(mrow - mnew);
        float lsum = 0.f;
#pragma unroll
        for (int kk = 0; kk < 16; kk++) {
            float p = __expf(s[kk] - mnew);
            lsum += p;
            Ps[r * AKS + c4 + 4 * kk] = p;
        }
        lsum += __shfl_xor_sync(0xffffffffu, lsum, 1);
        lsum += __shfl_xor_sync(0xffffffffu, lsum, 2);
        lrow = lrow * alpha + lsum;
        mrow = mnew;
#pragma unroll
        for (int d = 0; d < 16; d++) O[d] *= alpha;
        __syncthreads();   // Ps visible to all

        // O += P @ V  (thread dims: c4*16 + dd, dd=0..15)
#pragma unroll 8
        for (int key = 0; key < 64; key++) {
            float p = Ps[r * AKS + key];
#pragma unroll
            for (int d4 = 0; d4 < 4; d4++) {
                float4 v4 = *(const float4*)&Vs[key * AKS + c4 * 16 + d4 * 4];
                O[d4 * 4 + 0] += p * v4.x;
                O[d4 * 4 + 1] += p * v4.y;
                O[d4 * 4 + 2] += p * v4.z;
                O[d4 * 4 + 3] += p * v4.w;
            }
        }
        __syncthreads();   // before next tile overwrites K/V/Ps
    }

    float inv_l = 1.f / lrow;
    float* ob = out + base + (size_t)qi * DMODEL + c4 * 16;
#pragma unroll
    for (int d4 = 0; d4 < 4; d4++) {
        float4 o;
        o.x = O[d4 * 4 + 0] * inv_l;
        o.y = O[d4 * 4 + 1] * inv_l;
        o.z = O[d4 * 4 + 2] * inv_l;
        o.w = O[d4 * 4 + 3] * inv_l;
        *(float4*)&ob[d4 * 4] = o;
    }
}

// ---------------------------------------------------------------------------
// Launch
// ---------------------------------------------------------------------------
extern "C" void kernel_launch(void* const* d_in, const int* in_sizes, int n_in,
                              void* d_out, int out_size)
{
    const float* x  = (const float*)d_in[0];
    const float* Wq = (const float*)d_in[1];
    const float* bq = (const float*)d_in[2];
    const float* Wk = (const float*)d_in[3];
    const float* bk = (const float*)d_in[4];
    const float* Wv = (const float*)d_in[5];
    const float* bv = (const float*)d_in[6];
    const float* Wo = (const float*)d_in[7];
    const float* bo = (const float*)d_in[8];
    float* out = (float*)d_out;

    float *q, *k, *v, *att;
    cudaGetSymbolAddress((void**)&q,   g_q);
    cudaGetSymbolAddress((void**)&k,   g_k);
    cudaGetSymbolAddress((void**)&v,   g_v);
    cudaGetSymbolAddress((void**)&att, g_att);

    dim3 gg(DMODEL / GBN, MTOT / GBM);   // (8, 64)
    sgemm_tn<<<gg, 256>>>(x, Wq, bq, q, MTOT, DMODEL, DMODEL);
    sgemm_tn<<<gg, 256>>>(x, Wk, bk, k, MTOT, DMODEL, DMODEL);
    sgemm_tn<<<gg, 256>>>(x, Wv, bv, v, MTOT, DMODEL, DMODEL);

    const int smem = 4 * 64 * AKS * sizeof(float);  // 69632 B
    cudaFuncSetAttribute(attn_causal, cudaFuncAttributeMaxDynamicSharedMemorySize, smem);
    attn_causal<<<dim3(SEQ / 64, BATCH * NHEADS), 256, smem>>>(q, k, v, att);

    sgemm_tn<<<gg, 256>>>(att, Wo, bo, out, MTOT, DMODEL, DMODEL);
}

// round 2
// speedup vs baseline: 2.9214x; 2.9214x over previous
#include <cuda_runtime.h>
#include <cuda_bf16.h>
#include <math.h>

// Problem constants
#define BATCH   4
#define SEQ     2048
#define DMODEL  1024
#define NHEADS  16
#define HDIM    64
#define MTOT    (BATCH * SEQ)          // 8192 rows

// ---------------------------------------------------------------------------
// Scratch (static __device__ — no allocations allowed)
// ---------------------------------------------------------------------------
__device__ float g_q[MTOT * DMODEL];
__device__ float g_k[MTOT * DMODEL];
__device__ float g_v[MTOT * DMODEL];
__device__ float g_att[MTOT * DMODEL];

// ---------------------------------------------------------------------------
// SGEMM:  C[m,n] = sum_k A[m,k] * W[n,k] + bias[n]
// (unchanged from R1 — FMA-bound, 1:16 LDS:FMA ratio)
// ---------------------------------------------------------------------------
#define GBM 128
#define GBN 128
#define GBK 16
#define GLDS 132

__global__ __launch_bounds__(256, 2)
void sgemm_tn(const float* __restrict__ A, const float* __restrict__ W,
              const float* __restrict__ bias, float* __restrict__ C,
              int M, int N, int K)
{
    __shared__ __align__(16) float As[GBK * GLDS];
    __shared__ __align__(16) float Ws[GBK * GLDS];

    const int tid = threadIdx.x;
    const int m0 = blockIdx.y * GBM;
    const int n0 = blockIdx.x * GBN;
    const int tx = tid & 15;
    const int ty = tid >> 4;

    float acc[8][8];
#pragma unroll
    for (int i = 0; i < 8; i++)
#pragma unroll
        for (int j = 0; j < 8; j++) acc[i][j] = 0.f;

    for (int k0 = 0; k0 < K; k0 += GBK) {
#pragma unroll
        for (int t = 0; t < 2; t++) {
            int idx = tid + t * 256;
            int row = idx >> 2;
            int c4  = (idx & 3) << 2;
            float4 a = *(const float4*)&A[(size_t)(m0 + row) * K + k0 + c4];
            As[(c4 + 0) * GLDS + row] = a.x;
            As[(c4 + 1) * GLDS + row] = a.y;
            As[(c4 + 2) * GLDS + row] = a.z;
            As[(c4 + 3) * GLDS + row] = a.w;
            float4 w = *(const float4*)&W[(size_t)(n0 + row) * K + k0 + c4];
            Ws[(c4 + 0) * GLDS + row] = w.x;
            Ws[(c4 + 1) * GLDS + row] = w.y;
            Ws[(c4 + 2) * GLDS + row] = w.z;
            Ws[(c4 + 3) * GLDS + row] = w.w;
        }
        __syncthreads();

#pragma unroll
        for (int kk = 0; kk < GBK; kk++) {
            float4 a0 = *(const float4*)&As[kk * GLDS + ty * 8];
            float4 a1 = *(const float4*)&As[kk * GLDS + ty * 8 + 4];
            float4 b0 = *(const float4*)&Ws[kk * GLDS + tx * 8];
            float4 b1 = *(const float4*)&Ws[kk * GLDS + tx * 8 + 4];
            float av[8] = {a0.x, a0.y, a0.z, a0.w, a1.x, a1.y, a1.z, a1.w};
            float bv[8] = {b0.x, b0.y, b0.z, b0.w, b1.x, b1.y, b1.z, b1.w};
#pragma unroll
            for (int i = 0; i < 8; i++)
#pragma unroll
                for (int j = 0; j < 8; j++)
                    acc[i][j] += av[i] * bv[j];
        }
        __syncthreads();
    }

#pragma unroll
    for (int i = 0; i < 8; i++) {
        int m = m0 + ty * 8 + i;
#pragma unroll
        for (int j4 = 0; j4 < 2; j4++) {
            int n = n0 + tx * 8 + j4 * 4;
            float4 o;
            o.x = acc[i][j4 * 4 + 0] + bias[n + 0];
            o.y = acc[i][j4 * 4 + 1] + bias[n + 1];
            o.z = acc[i][j4 * 4 + 2] + bias[n + 2];
            o.w = acc[i][j4 * 4 + 3] + bias[n + 3];
            *(float4*)&C[(size_t)m * N + n] = o;
        }
    }
}

// ---------------------------------------------------------------------------
// Causal flash attention, fp32 — register-tiled (4x4 microtiles).
// Thread grid 16x16 over the 64q x 64k tile.
//   tx = tid&15, ty = tid>>4
//   Score phase: thread owns queries q = ty+16i (i<4), keys k = tx+16j (j<4)
//                per 4-dim step: 4 Q ld.128 + 4 K ld.128 -> 64 FMA  (1:8)
//   PV phase:    thread owns queries q = ty+16i,  dims d = tx*4..tx*4+3
//                per 4-key group:   4 P ld.128 + 4 V ld.128 -> 64 FMA (1:8)
// Smem rows stride 68 floats = 17 x 16B units (odd -> superbank spread).
// ---------------------------------------------------------------------------
#define AKS 68

__global__ __launch_bounds__(256, 2)
void attn_causal(const float* __restrict__ q, const float* __restrict__ k,
                 const float* __restrict__ v, float* __restrict__ out)
{
    extern __shared__ __align__(16) float sm[];
    float* Qs  = sm;                    // 64*68
    float* Ksm = Qs  + 64 * AKS;
    float* Vs  = Ksm + 64 * AKS;
    float* Ps  = Vs  + 64 * AKS;

    const int tid = threadIdx.x;
    const int tx  = tid & 15;
    const int ty  = tid >> 4;

    const int qt = blockIdx.x;
    const int bh = blockIdx.y;
    const int b  = bh >> 4;
    const int h  = bh & 15;

    const int q0 = qt * 64;
    const size_t base = (size_t)b * SEQ * DMODEL + (size_t)h * HDIM;
    const float* qb = q + base;
    const float* kb = k + base;
    const float* vb = v + base;

    // Load Q tile
    for (int i = tid; i < 64 * 16; i += 256) {
        int row = i >> 4;
        int c   = (i & 15) << 2;
        *(float4*)&Qs[row * AKS + c] =
            *(const float4*)&qb[(size_t)(q0 + row) * DMODEL + c];
    }

    float m[4], l[4], O[4][4];
#pragma unroll
    for (int i = 0; i < 4; i++) {
        m[i] = -1e30f; l[i] = 0.f;
#pragma unroll
        for (int e = 0; e < 4; e++) O[i][e] = 0.f;
    }

    const float scale = 0.125f;        // 1/sqrt(64)

    for (int j = 0; j <= qt; j++) {
        const int k0 = j * 64;
        // Load K,V tiles
        for (int i = tid; i < 64 * 16; i += 256) {
            int row = i >> 4;
            int c   = (i & 15) << 2;
            *(float4*)&Ksm[row * AKS + c] =
                *(const float4*)&kb[(size_t)(k0 + row) * DMODEL + c];
            *(float4*)&Vs[row * AKS + c] =
                *(const float4*)&vb[(size_t)(k0 + row) * DMODEL + c];
        }
        __syncthreads();

        // ---- Score phase: s[i][jj] = q_{ty+16i} . k_{tx+16jj}
        float s[4][4];
#pragma unroll
        for (int i = 0; i < 4; i++)
#pragma unroll
            for (int jj = 0; jj < 4; jj++) s[i][jj] = 0.f;

#pragma unroll
        for (int d4 = 0; d4 < 16; d4++) {
            float4 qf[4], kf[4];
#pragma unroll
            for (int i = 0; i < 4; i++)
                qf[i] = *(const float4*)&Qs[(ty + 16 * i) * AKS + d4 * 4];
#pragma unroll
            for (int jj = 0; jj < 4; jj++)
                kf[jj] = *(const float4*)&Ksm[(tx + 16 * jj) * AKS + d4 * 4];
#pragma unroll
            for (int i = 0; i < 4; i++)
#pragma unroll
                for (int jj = 0; jj < 4; jj++) {
                    s[i][jj] += qf[i].x * kf[jj].x + qf[i].y * kf[jj].y
                              + qf[i].z * kf[jj].z + qf[i].w * kf[jj].w;
                }
        }

        // ---- Mask + online softmax (row groups of 16 lanes share ty)
        const bool diag = (j == qt);
#pragma unroll
        for (int i = 0; i < 4; i++) {
            const int qi = q0 + ty + 16 * i;
            float tmax = -1e30f;
#pragma unroll
            for (int jj = 0; jj < 4; jj++) {
                if (diag) {
                    int kj = k0 + tx + 16 * jj;
                    s[i][jj] = (kj <= qi) ? s[i][jj] * scale : -1e30f;
                } else {
                    s[i][jj] *= scale;
                }
                tmax = fmaxf(tmax, s[i][jj]);
            }
            tmax = fmaxf(tmax, __shfl_xor_sync(0xffffffffu, tmax, 1));
            tmax = fmaxf(tmax, __shfl_xor_sync(0xffffffffu, tmax, 2));
            tmax = fmaxf(tmax, __shfl_xor_sync(0xffffffffu, tmax, 4));
            tmax = fmaxf(tmax, __shfl_xor_sync(0xffffffffu, tmax, 8));
            float mnew  = fmaxf(m[i], tmax);
            float alpha = __expf(m[i] - mnew);
            float lsum = 0.f;
#pragma unroll
            for (int jj = 0; jj < 4; jj++) {
                float p = __expf(s[i][jj] - mnew);
                lsum += p;
                Ps[(ty + 16 * i) * AKS + tx + 16 * jj] = p;
            }
            lsum += __shfl_xor_sync(0xffffffffu, lsum, 1);
            lsum += __shfl_xor_sync(0xffffffffu, lsum, 2);
            lsum += __shfl_xor_sync(0xffffffffu, lsum, 4);
            lsum += __shfl_xor_sync(0xffffffffu, lsum, 8);
            l[i] = l[i] * alpha + lsum;
            m[i] = mnew;
#pragma unroll
            for (int e = 0; e < 4; e++) O[i][e] *= alpha;
        }
        __syncthreads();   // Ps visible

        // ---- PV phase: O[i][:] += sum_key P[q][key] * V[key][tx*4..]
#pragma unroll
        for (int k4 = 0; k4 < 16; k4++) {
            float4 pf[4];
#pragma unroll
            for (int i = 0; i < 4; i++)
                pf[i] = *(const float4*)&Ps[(ty + 16 * i) * AKS + k4 * 4];
#pragma unroll
            for (int e = 0; e < 4; e++) {
                float4 vf = *(const float4*)&Vs[(k4 * 4 + e) * AKS + tx * 4];
                float pe[4] = { pf[0].x, pf[1].x, pf[2].x, pf[3].x };
                if (e == 1) { pe[0]=pf[0].y; pe[1]=pf[1].y; pe[2]=pf[2].y; pe[3]=pf[3].y; }
                if (e == 2) { pe[0]=pf[0].z; pe[1]=pf[1].z; pe[2]=pf[2].z; pe[3]=pf[3].z; }
                if (e == 3) { pe[0]=pf[0].w; pe[1]=pf[1].w; pe[2]=pf[2].w; pe[3]=pf[3].w; }
#pragma unroll
                for (int i = 0; i < 4; i++) {
                    O[i][0] += pe[i] * vf.x;
                    O[i][1] += pe[i] * vf.y;
                    O[i][2] += pe[i] * vf.z;
                    O[i][3] += pe[i] * vf.w;
                }
            }
        }
        __syncthreads();   // before next tile overwrites K/V/Ps
    }

    // ---- Final store: out[q][h*64 + tx*4 .. +3]
#pragma unroll
    for (int i = 0; i < 4; i++) {
        const int qi = q0 + ty + 16 * i;
        float inv_l = 1.f / l[i];
        float4 o;
        o.x = O[i][0] * inv_l;
        o.y = O[i][1] * inv_l;
        o.z = O[i][2] * inv_l;
        o.w = O[i][3] * inv_l;
        *(float4*)&out[base + (size_t)qi * DMODEL + tx * 4] = o;
    }
}

// ---------------------------------------------------------------------------
// Launch
// ---------------------------------------------------------------------------
extern "C" void kernel_launch(void* const* d_in, const int* in_sizes, int n_in,
                              void* d_out, int out_size)
{
    const float* x  = (const float*)d_in[0];
    const float* Wq = (const float*)d_in[1];
    const float* bq = (const float*)d_in[2];
    const float* Wk = (const float*)d_in[3];
    const float* bk = (const float*)d_in[4];
    const float* Wv = (const float*)d_in[5];
    const float* bv = (const float*)d_in[6];
    const float* Wo = (const float*)d_in[7];
    const float* bo = (const float*)d_in[8];
    float* out = (float*)d_out;

    float *q, *k, *v, *att;
    cudaGetSymbolAddress((void**)&q,   g_q);
    cudaGetSymbolAddress((void**)&k,   g_k);
    cudaGetSymbolAddress((void**)&v,   g_v);
    cudaGetSymbolAddress((void**)&att, g_att);

    dim3 gg(DMODEL / GBN, MTOT / GBM);   // (8, 64)
    sgemm_tn<<<gg, 256>>>(x, Wq, bq, q, MTOT, DMODEL, DMODEL);
    sgemm_tn<<<gg, 256>>>(x, Wk, bk, k, MTOT, DMODEL, DMODEL);
    sgemm_tn<<<gg, 256>>>(x, Wv, bv, v, MTOT, DMODEL, DMODEL);

    const int smem = 4 * 64 * AKS * sizeof(float);  // 69632 B
    cudaFuncSetAttribute(attn_causal, cudaFuncAttributeMaxDynamicSharedMemorySize, smem);
    attn_causal<<<dim3(SEQ / 64, BATCH * NHEADS), 256, smem>>>(q, k, v, att);

    sgemm_tn<<<gg, 256>>>(att, Wo, bo, out, MTOT, DMODEL, DMODEL);
}

// round 4
// speedup vs baseline: 4.3419x; 1.4862x over previous
#include <cuda_runtime.h>
#include <cuda_bf16.h>
#include <cstdint>
#include <math.h>

// Problem constants
#define BATCH   4
#define SEQ     2048
#define DMODEL  1024
#define NHEADS  16
#define HDIM    64
#define MTOT    (BATCH * SEQ)          // 8192 rows

// ---------------------------------------------------------------------------
// Scratch (static __device__ — no allocations allowed)
// ---------------------------------------------------------------------------
__device__ float g_q[MTOT * DMODEL];
__device__ float g_k[MTOT * DMODEL];
__device__ float g_v[MTOT * DMODEL];
__device__ float g_att[MTOT * DMODEL];

__device__ __nv_bfloat16 g_xh[MTOT * DMODEL];
__device__ __nv_bfloat16 g_xl[MTOT * DMODEL];
__device__ __nv_bfloat16 g_ath[MTOT * DMODEL];
__device__ __nv_bfloat16 g_atl[MTOT * DMODEL];
__device__ __nv_bfloat16 g_wh[4][DMODEL * DMODEL];
__device__ __nv_bfloat16 g_wl[4][DMODEL * DMODEL];

// ---------------------------------------------------------------------------
// mma.sync / ldmatrix helpers (target-portable PTX, valid on plain sm_103)
// ---------------------------------------------------------------------------
__device__ __forceinline__ uint32_t smem_to_u32(const void* p) {
    uint32_t a;
    asm("{ .reg .u64 t; cvta.to.shared.u64 t, %1; cvt.u32.u64 %0, t; }" : "=r"(a) : "l"(p));
    return a;
}

__device__ __forceinline__ void ldsm4(uint32_t* d, uint32_t addr) {
    asm volatile("ldmatrix.sync.aligned.m8n8.x4.shared.b16 {%0,%1,%2,%3}, [%4];"
                 : "=r"(d[0]), "=r"(d[1]), "=r"(d[2]), "=r"(d[3]) : "r"(addr));
}

__device__ __forceinline__ void mma16816(float* c, const uint32_t* a, const uint32_t* b) {
    asm volatile("mma.sync.aligned.m16n8k16.row.col.f32.bf16.bf16.f32 "
                 "{%0,%1,%2,%3}, {%4,%5,%6,%7}, {%8,%9}, {%0,%1,%2,%3};"
                 : "+f"(c[0]), "+f"(c[1]), "+f"(c[2]), "+f"(c[3])
                 : "r"(a[0]), "r"(a[1]), "r"(a[2]), "r"(a[3]), "r"(b[0]), "r"(b[1]));
}

// SW64-style swizzle for 64B rows: XOR bits[5:4] with bits[8:7]
#define SWZ64(o) ((o) ^ (((o) >> 3) & 0x30))

// ---------------------------------------------------------------------------
// bf16 hi/lo split:  hi = bf16(x), lo = bf16(x - hi)
// ---------------------------------------------------------------------------
__global__ void split_bf16(const float* __restrict__ in,
                           __nv_bfloat16* __restrict__ hi,
                           __nv_bfloat16* __restrict__ lo, int n4)
{
    int i = blockIdx.x * blockDim.x + threadIdx.x;
    if (i >= n4) return;
    float4 x = ((const float4*)in)[i];
    __nv_bfloat16 h0 = __float2bfloat16(x.x);
    __nv_bfloat16 h1 = __float2bfloat16(x.y);
    __nv_bfloat16 h2 = __float2bfloat16(x.z);
    __nv_bfloat16 h3 = __float2bfloat16(x.w);
    __nv_bfloat162 hh0; hh0.x = h0; hh0.y = h1;
    __nv_bfloat162 hh1; hh1.x = h2; hh1.y = h3;
    ((__nv_bfloat162*)hi)[i * 2 + 0] = hh0;
    ((__nv_bfloat162*)hi)[i * 2 + 1] = hh1;
    __nv_bfloat162 ll0, ll1;
    ll0.x = __float2bfloat16(x.x - __bfloat162float(h0));
    ll0.y = __float2bfloat16(x.y - __bfloat162float(h1));
    ll1.x = __float2bfloat16(x.z - __bfloat162float(h2));
    ll1.y = __float2bfloat16(x.w - __bfloat162float(h3));
    ((__nv_bfloat162*)lo)[i * 2 + 0] = ll0;
    ((__nv_bfloat162*)lo)[i * 2 + 1] = ll1;
}

// ---------------------------------------------------------------------------
// HMMA bf16-split GEMM:  C[m,n] = sum_k A[m,k]*W[n,k] + bias[n]
//   C ≈ Ah·Wh^T + Ah·Wl^T + Al·Wh^T, fp32 accumulated.
// CTA 128x128, 8 warps (2m x 4n), warp tile 64x32, mma m16n8k16.
// K-chunk 32; stage = {Ah,Al,Bh,Bl} tiles of 128x32 bf16 (64B rows,
// SW64 swizzle), double buffered. LDG->reg->STS pipeline, 1 sync/chunk.
// ---------------------------------------------------------------------------
#define BK 32
#define NCHUNK (DMODEL / BK)           // 32
#define TILE_BYTES (128 * 64)          // 8 KB
#define STAGE_BYTES (4 * TILE_BYTES)   // 32 KB
#define GEMM_SMEM (2 * STAGE_BYTES)    // 64 KB

__global__ __launch_bounds__(256)
void gemm_hmma_split(const __nv_bfloat16* __restrict__ Ah, const __nv_bfloat16* __restrict__ Al,
                     const __nv_bfloat16* __restrict__ Bh, const __nv_bfloat16* __restrict__ Bl,
                     const float* __restrict__ bias, float* __restrict__ C)
{
    extern __shared__ __align__(16) char smem[];
    const uint32_t smem_u = smem_to_u32(smem);

    const int tid  = threadIdx.x;
    const int wid  = tid >> 5;
    const int lane = tid & 31;
    const int wm   = wid & 1;          // 0..1
    const int wn   = wid >> 1;         // 0..3
    const int m0 = blockIdx.y * 128;
    const int n0 = blockIdx.x * 128;

    const __nv_bfloat16* srcs[4] = { Ah, Al, Bh, Bl };

    // Per-thread ldmatrix offsets (within one tile).
    // A (x4 over 16m x 16k): lanes 0-7: m0..7/k0; 8-15: m8..15/k0; 16-23: m0..7/k8; 24-31: m8..15/k8
    uint32_t offA[4][2];
    {
        int rowA = (lane & 7) + ((lane >> 3) & 1) * 8;
        int chi  = (lane >> 4) & 1;
#pragma unroll
        for (int mt = 0; mt < 4; mt++)
#pragma unroll
            for (int kt = 0; kt < 2; kt++) {
                int row = wm * 64 + mt * 16 + rowA;
                int off = row * 64 + (kt * 2 + chi) * 16;
                offA[mt][kt] = SWZ64(off);
            }
    }
    // B (x4 over two 8n x 16k frags): lanes 0-7: nt0/k0; 8-15: nt0/k8; 16-23: nt1/k0; 24-31: nt1/k8
    uint32_t offB[2][2];
    {
        int rb  = (lane & 7) + ((lane >> 4) & 1) * 8;
        int chi = (lane >> 3) & 1;
#pragma unroll
        for (int np = 0; np < 2; np++)
#pragma unroll
            for (int kt = 0; kt < 2; kt++) {
                int row = wn * 32 + np * 16 + rb;
                int off = row * 64 + (kt * 2 + chi) * 16;
                offB[np][kt] = SWZ64(off);
            }
    }

    float acc[4][4][4];
#pragma unroll
    for (int mt = 0; mt < 4; mt++)
#pragma unroll
        for (int nt = 0; nt < 4; nt++)
#pragma unroll
            for (int e = 0; e < 4; e++) acc[mt][nt][e] = 0.f;

    float4 buf[8];

    auto ldg = [&](int c) {
        const int k0 = c * BK;
#pragma unroll
        for (int t = 0; t < 4; t++) {
            const __nv_bfloat16* src = srcs[t];
            const int r0 = (t < 2) ? m0 : n0;
#pragma unroll
            for (int i = 0; i < 2; i++) {
                int fid = tid + i * 256;
                int row = fid >> 2, cc = fid & 3;
                buf[t * 2 + i] = *(const float4*)(src + (size_t)(r0 + row) * DMODEL + k0 + cc * 8);
            }
        }
    };
    auto sts = [&](int s) {
        char* st = smem + s * STAGE_BYTES;
#pragma unroll
        for (int t = 0; t < 4; t++) {
            char* dst = st + t * TILE_BYTES;
#pragma unroll
            for (int i = 0; i < 2; i++) {
                int fid = tid + i * 256;
                int row = fid >> 2, cc = fid & 3;
                int off = row * 64 + cc * 16;
                *(float4*)(dst + SWZ64(off)) = buf[t * 2 + i];
            }
        }
    };
    auto mma_chunk = [&](int s) {
        const uint32_t sb = smem_u + s * STAGE_BYTES;
#pragma unroll
        for (int kt = 0; kt < 2; kt++) {
            uint32_t bh[8], bl[8];
#pragma unroll
            for (int np = 0; np < 2; np++) {
                ldsm4(&bh[np * 4], sb + 2 * TILE_BYTES + offB[np][kt]);
                ldsm4(&bl[np * 4], sb + 3 * TILE_BYTES + offB[np][kt]);
            }
            uint32_t a[4][4];
#pragma unroll
            for (int mt = 0; mt < 4; mt++)
                ldsm4(a[mt], sb + offA[mt][kt]);
#pragma unroll
            for (int mt = 0; mt < 4; mt++)
#pragma unroll
                for (int nt = 0; nt < 4; nt++) {
                    mma16816(acc[mt][nt], a[mt], &bh[(nt >> 1) * 4 + (nt & 1) * 2]);
                    mma16816(acc[mt][nt], a[mt], &bl[(nt >> 1) * 4 + (nt & 1) * 2]);
                }
#pragma unroll
            for (int mt = 0; mt < 4; mt++)
                ldsm4(a[mt], sb + TILE_BYTES + offA[mt][kt]);
#pragma unroll
            for (int mt = 0; mt < 4; mt++)
#pragma unroll
                for (int nt = 0; nt < 4; nt++)
                    mma16816(acc[mt][nt], a[mt], &bh[(nt >> 1) * 4 + (nt & 1) * 2]);
        }
    };

    ldg(0); sts(0);
    __syncthreads();
    for (int c = 0; c < NCHUNK; c++) {
        if (c + 1 < NCHUNK) ldg(c + 1);
        mma_chunk(c & 1);
        if (c + 1 < NCHUNK) sts((c + 1) & 1);
        __syncthreads();
    }

    // Epilogue: acc (m16n8 frag layout) + bias -> C
    const int g = lane >> 2;
    const int t2 = (lane & 3) * 2;
#pragma unroll
    for (int mt = 0; mt < 4; mt++) {
#pragma unroll
        for (int nt = 0; nt < 4; nt++) {
            int row = m0 + wm * 64 + mt * 16 + g;
            int col = n0 + wn * 32 + nt * 8 + t2;
            float2 b = *(const float2*)&bias[col];
            float2 o0, o1;
            o0.x = acc[mt][nt][0] + b.x;  o0.y = acc[mt][nt][1] + b.y;
            o1.x = acc[mt][nt][2] + b.x;  o1.y = acc[mt][nt][3] + b.y;
            *(float2*)&C[(size_t)row * DMODEL + col] = o0;
            *(float2*)&C[(size_t)(row + 8) * DMODEL + col] = o1;
        }
    }
}

// ---------------------------------------------------------------------------
// Causal flash attention, fp32 — register-tiled 4x4 microtiles (R2, unchanged)
// ---------------------------------------------------------------------------
#define AKS 68

__global__ __launch_bounds__(256, 2)
void attn_causal(const float* __restrict__ q, const float* __restrict__ k,
                 const float* __restrict__ v, float* __restrict__ out)
{
    extern __shared__ __align__(16) float sm[];
    float* Qs  = sm;
    float* Ksm = Qs  + 64 * AKS;
    float* Vs  = Ksm + 64 * AKS;
    float* Ps  = Vs  + 64 * AKS;

    const int tid = threadIdx.x;
    const int tx  = tid & 15;
    const int ty  = tid >> 4;

    const int qt = blockIdx.x;
    const int bh = blockIdx.y;
    const int b  = bh >> 4;
    const int h  = bh & 15;

    const int q0 = qt * 64;
    const size_t base = (size_t)b * SEQ * DMODEL + (size_t)h * HDIM;
    const float* qb = q + base;
    const float* kb = k + base;
    const float* vb = v + base;

    for (int i = tid; i < 64 * 16; i += 256) {
        int row = i >> 4;
        int c   = (i & 15) << 2;
        *(float4*)&Qs[row * AKS + c] =
            *(const float4*)&qb[(size_t)(q0 + row) * DMODEL + c];
    }

    float m[4], l[4], O[4][4];
#pragma unroll
    for (int i = 0; i < 4; i++) {
        m[i] = -1e30f; l[i] = 0.f;
#pragma unroll
        for (int e = 0; e < 4; e++) O[i][e] = 0.f;
    }

    const float scale = 0.125f;

    for (int j = 0; j <= qt; j++) {
        const int k0 = j * 64;
        for (int i = tid; i < 64 * 16; i += 256) {
            int row = i >> 4;
            int c   = (i & 15) << 2;
            *(float4*)&Ksm[row * AKS + c] =
                *(const float4*)&kb[(size_t)(k0 + row) * DMODEL + c];
            *(float4*)&Vs[row * AKS + c] =
                *(const float4*)&vb[(size_t)(k0 + row) * DMODEL + c];
        }
        __syncthreads();

        float s[4][4];
#pragma unroll
        for (int i = 0; i < 4; i++)
#pragma unroll
            for (int jj = 0; jj < 4; jj++) s[i][jj] = 0.f;

#pragma unroll
        for (int d4 = 0; d4 < 16; d4++) {
            float4 qf[4], kf[4];
#pragma unroll
            for (int i = 0; i < 4; i++)
                qf[i] = *(const float4*)&Qs[(ty + 16 * i) * AKS + d4 * 4];
#pragma unroll
            for (int jj = 0; jj < 4; jj++)
                kf[jj] = *(const float4*)&Ksm[(tx + 16 * jj) * AKS + d4 * 4];
#pragma unroll
            for (int i = 0; i < 4; i++)
#pragma unroll
                for (int jj = 0; jj < 4; jj++) {
                    s[i][jj] += qf[i].x * kf[jj].x + qf[i].y * kf[jj].y
                              + qf[i].z * kf[jj].z + qf[i].w * kf[jj].w;
                }
        }

        const bool diag = (j == qt);
#pragma unroll
        for (int i = 0; i < 4; i++) {
            const int qi = q0 + ty + 16 * i;
            float tmax = -1e30f;
#pragma unroll
            for (int jj = 0; jj < 4; jj++) {
                if (diag) {
                    int kj = k0 + tx + 16 * jj;
                    s[i][jj] = (kj <= qi) ? s[i][jj] * scale : -1e30f;
                } else {
                    s[i][jj] *= scale;
                }
                tmax = fmaxf(tmax, s[i][jj]);
            }
            tmax = fmaxf(tmax, __shfl_xor_sync(0xffffffffu, tmax, 1));
            tmax = fmaxf(tmax, __shfl_xor_sync(0xffffffffu, tmax, 2));
            tmax = fmaxf(tmax, __shfl_xor_sync(0xffffffffu, tmax, 4));
            tmax = fmaxf(tmax, __shfl_xor_sync(0xffffffffu, tmax, 8));
            float mnew  = fmaxf(m[i], tmax);
            float alpha = __expf(m[i] - mnew);
            float lsum = 0.f;
#pragma unroll
            for (int jj = 0; jj < 4; jj++) {
                float p = __expf(s[i][jj] - mnew);
                lsum += p;
                Ps[(ty + 16 * i) * AKS + tx + 16 * jj] = p;
            }
            lsum += __shfl_xor_sync(0xffffffffu, lsum, 1);
            lsum += __shfl_xor_sync(0xffffffffu, lsum, 2);
            lsum += __shfl_xor_sync(0xffffffffu, lsum, 4);
            lsum += __shfl_xor_sync(0xffffffffu, lsum, 8);
            l[i] = l[i] * alpha + lsum;
            m[i] = mnew;
#pragma unroll
            for (int e = 0; e < 4; e++) O[i][e] *= alpha;
        }
        __syncthreads();

#pragma unroll
        for (int k4 = 0; k4 < 16; k4++) {
            float4 pf[4];
#pragma unroll
            for (int i = 0; i < 4; i++)
                pf[i] = *(const float4*)&Ps[(ty + 16 * i) * AKS + k4 * 4];
#pragma unroll
            for (int e = 0; e < 4; e++) {
                float4 vf = *(const float4*)&Vs[(k4 * 4 + e) * AKS + tx * 4];
                float pe[4] = { pf[0].x, pf[1].x, pf[2].x, pf[3].x };
                if (e == 1) { pe[0]=pf[0].y; pe[1]=pf[1].y; pe[2]=pf[2].y; pe[3]=pf[3].y; }
                if (e == 2) { pe[0]=pf[0].z; pe[1]=pf[1].z; pe[2]=pf[2].z; pe[3]=pf[3].z; }
                if (e == 3) { pe[0]=pf[0].w; pe[1]=pf[1].w; pe[2]=pf[2].w; pe[3]=pf[3].w; }
#pragma unroll
                for (int i = 0; i < 4; i++) {
                    O[i][0] += pe[i] * vf.x;
                    O[i][1] += pe[i] * vf.y;
                    O[i][2] += pe[i] * vf.z;
                    O[i][3] += pe[i] * vf.w;
                }
            }
        }
        __syncthreads();
    }

#pragma unroll
    for (int i = 0; i < 4; i++) {
        const int qi = q0 + ty + 16 * i;
        float inv_l = 1.f / l[i];
        float4 o;
        o.x = O[i][0] * inv_l;
        o.y = O[i][1] * inv_l;
        o.z = O[i][2] * inv_l;
        o.w = O[i][3] * inv_l;
        *(float4*)&out[base + (size_t)qi * DMODEL + tx * 4] = o;
    }
}

// ---------------------------------------------------------------------------
// Launch
// ---------------------------------------------------------------------------
extern "C" void kernel_launch(void* const* d_in, const int* in_sizes, int n_in,
                              void* d_out, int out_size)
{
    const float* x  = (const float*)d_in[0];
    const float* Wq = (const float*)d_in[1];
    const float* bq = (const float*)d_in[2];
    const float* Wk = (const float*)d_in[3];
    const float* bk = (const float*)d_in[4];
    const float* Wv = (const float*)d_in[5];
    const float* bv = (const float*)d_in[6];
    const float* Wo = (const float*)d_in[7];
    const float* bo = (const float*)d_in[8];
    float* out = (float*)d_out;

    float *q, *k, *v, *att;
    cudaGetSymbolAddress((void**)&q,   g_q);
    cudaGetSymbolAddress((void**)&k,   g_k);
    cudaGetSymbolAddress((void**)&v,   g_v);
    cudaGetSymbolAddress((void**)&att, g_att);
    __nv_bfloat16 *xh, *xl, *ath, *atl, *wh, *wl;
    cudaGetSymbolAddress((void**)&xh,  g_xh);
    cudaGetSymbolAddress((void**)&xl,  g_xl);
    cudaGetSymbolAddress((void**)&ath, g_ath);
    cudaGetSymbolAddress((void**)&atl, g_atl);
    cudaGetSymbolAddress((void**)&wh,  g_wh);
    cudaGetSymbolAddress((void**)&wl,  g_wl);

    const int WN = DMODEL * DMODEL;
    const float* Ws[4] = { Wq, Wk, Wv, Wo };

    split_bf16<<<(MTOT * DMODEL / 4 + 255) / 256, 256>>>(x, xh, xl, MTOT * DMODEL / 4);
    for (int i = 0; i < 4; i++)
        split_bf16<<<(WN / 4 + 255) / 256, 256>>>(Ws[i], wh + (size_t)i * WN, wl + (size_t)i * WN, WN / 4);

    cudaFuncSetAttribute(gemm_hmma_split, cudaFuncAttributeMaxDynamicSharedMemorySize, GEMM_SMEM);
    dim3 gg(DMODEL / 128, MTOT / 128);       // (8, 64)
    gemm_hmma_split<<<gg, 256, GEMM_SMEM>>>(xh, xl, wh + 0 * (size_t)WN, wl + 0 * (size_t)WN, bq, q);
    gemm_hmma_split<<<gg, 256, GEMM_SMEM>>>(xh, xl, wh + 1 * (size_t)WN, wl + 1 * (size_t)WN, bk, k);
    gemm_hmma_split<<<gg, 256, GEMM_SMEM>>>(xh, xl, wh + 2 * (size_t)WN, wl + 2 * (size_t)WN, bv, v);

    const int smem = 4 * 64 * AKS * sizeof(float);
    cudaFuncSetAttribute(attn_causal, cudaFuncAttributeMaxDynamicSharedMemorySize, smem);
    attn_causal<<<dim3(SEQ / 64, BATCH * NHEADS), 256, smem>>>(q, k, v, att);

    split_bf16<<<(MTOT * DMODEL / 4 + 255) / 256, 256>>>(att, ath, atl, MTOT * DMODEL / 4);
    gemm_hmma_split<<<gg, 256, GEMM_SMEM>>>(ath, atl, wh + 3 * (size_t)WN, wl + 3 * (size_t)WN, bo, out);
}

// round 5
// speedup vs baseline: 6.2838x; 1.4472x over previous
#include <cuda_runtime.h>
#include <cuda_bf16.h>
#include <cstdint>
#include <math.h>

// Problem constants
#define BATCH   4
#define SEQ     2048
#define DMODEL  1024
#define NHEADS  16
#define HDIM    64
#define MTOT    (BATCH * SEQ)          // 8192 rows

// ---------------------------------------------------------------------------
// Scratch (static __device__ — no allocations allowed)
// ---------------------------------------------------------------------------
__device__ __nv_bfloat16 g_xh[MTOT * DMODEL];
__device__ __nv_bfloat16 g_xl[MTOT * DMODEL];
__device__ __nv_bfloat16 g_qh[MTOT * DMODEL];
__device__ __nv_bfloat16 g_ql[MTOT * DMODEL];
__device__ __nv_bfloat16 g_kh[MTOT * DMODEL];
__device__ __nv_bfloat16 g_kl[MTOT * DMODEL];
__device__ __nv_bfloat16 g_vth[MTOT * DMODEL];   // [b*16+h][64 dims][2048 T]
__device__ __nv_bfloat16 g_vtl[MTOT * DMODEL];
__device__ __nv_bfloat16 g_ath[MTOT * DMODEL];
__device__ __nv_bfloat16 g_atl[MTOT * DMODEL];
__device__ __nv_bfloat16 g_wh[4][DMODEL * DMODEL];
__device__ __nv_bfloat16 g_wl[4][DMODEL * DMODEL];

// ---------------------------------------------------------------------------
// mma.sync / ldmatrix helpers (target-portable PTX, valid on plain sm_103)
// ---------------------------------------------------------------------------
__device__ __forceinline__ uint32_t smem_to_u32(const void* p) {
    uint32_t a;
    asm("{ .reg .u64 t; cvta.to.shared.u64 t, %1; cvt.u32.u64 %0, t; }" : "=r"(a) : "l"(p));
    return a;
}
__device__ __forceinline__ void ldsm4(uint32_t* d, uint32_t addr) {
    asm volatile("ldmatrix.sync.aligned.m8n8.x4.shared.b16 {%0,%1,%2,%3}, [%4];"
                 : "=r"(d[0]), "=r"(d[1]), "=r"(d[2]), "=r"(d[3]) : "r"(addr));
}
__device__ __forceinline__ void mma16816(float* c, const uint32_t* a, const uint32_t* b) {
    asm volatile("mma.sync.aligned.m16n8k16.row.col.f32.bf16.bf16.f32 "
                 "{%0,%1,%2,%3}, {%4,%5,%6,%7}, {%8,%9}, {%0,%1,%2,%3};"
                 : "+f"(c[0]), "+f"(c[1]), "+f"(c[2]), "+f"(c[3])
                 : "r"(a[0]), "r"(a[1]), "r"(a[2]), "r"(a[3]), "r"(b[0]), "r"(b[1]));
}
__device__ __forceinline__ uint32_t pack_bf2(float a, float b) {
    __nv_bfloat162 t = __floats2bfloat162_rn(a, b);   // .x(lo)=a, .y(hi)=b
    return *reinterpret_cast<uint32_t*>(&t);
}

// SW64-style swizzle for 64B rows (GEMM tiles)
#define SWZ64(o) ((o) ^ (((o) >> 3) & 0x30))
// SW128-style swizzle for 128B rows (attention tiles)
#define SWZ128(o) ((o) ^ (((o) >> 3) & 0x70))

// ---------------------------------------------------------------------------
// bf16 hi/lo split:  hi = bf16(x), lo = bf16(x - hi)   (x and weights only)
// ---------------------------------------------------------------------------
__global__ void split_bf16(const float* __restrict__ in,
                           __nv_bfloat16* __restrict__ hi,
                           __nv_bfloat16* __restrict__ lo, int n4)
{
    int i = blockIdx.x * blockDim.x + threadIdx.x;
    if (i >= n4) return;
    float4 x = ((const float4*)in)[i];
    __nv_bfloat16 h0 = __float2bfloat16(x.x);
    __nv_bfloat16 h1 = __float2bfloat16(x.y);
    __nv_bfloat16 h2 = __float2bfloat16(x.z);
    __nv_bfloat16 h3 = __float2bfloat16(x.w);
    __nv_bfloat162 hh0; hh0.x = h0; hh0.y = h1;
    __nv_bfloat162 hh1; hh1.x = h2; hh1.y = h3;
    ((__nv_bfloat162*)hi)[i * 2 + 0] = hh0;
    ((__nv_bfloat162*)hi)[i * 2 + 1] = hh1;
    __nv_bfloat162 ll0, ll1;
    ll0.x = __float2bfloat16(x.x - __bfloat162float(h0));
    ll0.y = __float2bfloat16(x.y - __bfloat162float(h1));
    ll1.x = __float2bfloat16(x.z - __bfloat162float(h2));
    ll1.y = __float2bfloat16(x.w - __bfloat162float(h3));
    ((__nv_bfloat162*)lo)[i * 2 + 0] = ll0;
    ((__nv_bfloat162*)lo)[i * 2 + 1] = ll1;
}

// ---------------------------------------------------------------------------
// HMMA bf16-split GEMM:  C[m,n] = sum_k A[m,k]*W[n,k] + bias[n]
// Epilogue modes: 0 = fp32 C;  1 = hi/lo bf16 row layout;
//                 2 = hi/lo bf16 transposed per-head [b,h,d,T] layout (V)
// ---------------------------------------------------------------------------
#define BK 32
#define NCHUNK (DMODEL / BK)           // 32
#define TILE_BYTES (128 * 64)          // 8 KB
#define STAGE_BYTES (4 * TILE_BYTES)   // 32 KB
#define GEMM_SMEM (2 * STAGE_BYTES)    // 64 KB

__global__ __launch_bounds__(256)
void gemm_hmma_split(const __nv_bfloat16* __restrict__ Ah, const __nv_bfloat16* __restrict__ Al,
                     const __nv_bfloat16* __restrict__ Bh, const __nv_bfloat16* __restrict__ Bl,
                     const float* __restrict__ bias, float* __restrict__ Cf,
                     __nv_bfloat16* __restrict__ Ch, __nv_bfloat16* __restrict__ Cl,
                     int mode)
{
    extern __shared__ __align__(16) char smem[];
    const uint32_t smem_u = smem_to_u32(smem);

    const int tid  = threadIdx.x;
    const int wid  = tid >> 5;
    const int lane = tid & 31;
    const int wm   = wid & 1;
    const int wn   = wid >> 1;
    const int m0 = blockIdx.y * 128;
    const int n0 = blockIdx.x * 128;

    const __nv_bfloat16* srcs[4] = { Ah, Al, Bh, Bl };

    uint32_t offA[4][2];
    {
        int rowA = (lane & 7) + ((lane >> 3) & 1) * 8;
        int chi  = (lane >> 4) & 1;
#pragma unroll
        for (int mt = 0; mt < 4; mt++)
#pragma unroll
            for (int kt = 0; kt < 2; kt++) {
                int row = wm * 64 + mt * 16 + rowA;
                int off = row * 64 + (kt * 2 + chi) * 16;
                offA[mt][kt] = SWZ64(off);
            }
    }
    uint32_t offB[2][2];
    {
        int rb  = (lane & 7) + ((lane >> 4) & 1) * 8;
        int chi = (lane >> 3) & 1;
#pragma unroll
        for (int np = 0; np < 2; np++)
#pragma unroll
            for (int kt = 0; kt < 2; kt++) {
                int row = wn * 32 + np * 16 + rb;
                int off = row * 64 + (kt * 2 + chi) * 16;
                offB[np][kt] = SWZ64(off);
            }
    }

    float acc[4][4][4];
#pragma unroll
    for (int mt = 0; mt < 4; mt++)
#pragma unroll
        for (int nt = 0; nt < 4; nt++)
#pragma unroll
            for (int e = 0; e < 4; e++) acc[mt][nt][e] = 0.f;

    float4 buf[8];

    auto ldg = [&](int c) {
        const int k0 = c * BK;
#pragma unroll
        for (int t = 0; t < 4; t++) {
            const __nv_bfloat16* src = srcs[t];
            const int r0 = (t < 2) ? m0 : n0;
#pragma unroll
            for (int i = 0; i < 2; i++) {
                int fid = tid + i * 256;
                int row = fid >> 2, cc = fid & 3;
                buf[t * 2 + i] = *(const float4*)(src + (size_t)(r0 + row) * DMODEL + k0 + cc * 8);
            }
        }
    };
    auto sts = [&](int s) {
        char* st = smem + s * STAGE_BYTES;
#pragma unroll
        for (int t = 0; t < 4; t++) {
            char* dst = st + t * TILE_BYTES;
#pragma unroll
            for (int i = 0; i < 2; i++) {
                int fid = tid + i * 256;
                int row = fid >> 2, cc = fid & 3;
                int off = row * 64 + cc * 16;
                *(float4*)(dst + SWZ64(off)) = buf[t * 2 + i];
            }
        }
    };
    auto mma_chunk = [&](int s) {
        const uint32_t sb = smem_u + s * STAGE_BYTES;
#pragma unroll
        for (int kt = 0; kt < 2; kt++) {
            uint32_t bh[8], bl[8];
#pragma unroll
            for (int np = 0; np < 2; np++) {
                ldsm4(&bh[np * 4], sb + 2 * TILE_BYTES + offB[np][kt]);
                ldsm4(&bl[np * 4], sb + 3 * TILE_BYTES + offB[np][kt]);
            }
            uint32_t a[4][4];
#pragma unroll
            for (int mt = 0; mt < 4; mt++)
                ldsm4(a[mt], sb + offA[mt][kt]);
#pragma unroll
            for (int mt = 0; mt < 4; mt++)
#pragma unroll
                for (int nt = 0; nt < 4; nt++) {
                    mma16816(acc[mt][nt], a[mt], &bh[(nt >> 1) * 4 + (nt & 1) * 2]);
                    mma16816(acc[mt][nt], a[mt], &bl[(nt >> 1) * 4 + (nt & 1) * 2]);
                }
#pragma unroll
            for (int mt = 0; mt < 4; mt++)
                ldsm4(a[mt], sb + TILE_BYTES + offA[mt][kt]);
#pragma unroll
            for (int mt = 0; mt < 4; mt++)
#pragma unroll
                for (int nt = 0; nt < 4; nt++)
                    mma16816(acc[mt][nt], a[mt], &bh[(nt >> 1) * 4 + (nt & 1) * 2]);
        }
    };

    ldg(0); sts(0);
    __syncthreads();
    for (int c = 0; c < NCHUNK; c++) {
        if (c + 1 < NCHUNK) ldg(c + 1);
        mma_chunk(c & 1);
        if (c + 1 < NCHUNK) sts((c + 1) & 1);
        __syncthreads();
    }

    // Epilogue
    const int g  = lane >> 2;
    const int t2 = (lane & 3) * 2;
#pragma unroll
    for (int mt = 0; mt < 4; mt++) {
#pragma unroll
        for (int nt = 0; nt < 4; nt++) {
            int row = m0 + wm * 64 + mt * 16 + g;
            int col = n0 + wn * 32 + nt * 8 + t2;
            float2 b = *(const float2*)&bias[col];
            float v0 = acc[mt][nt][0] + b.x;
            float v1 = acc[mt][nt][1] + b.y;
            float v2 = acc[mt][nt][2] + b.x;
            float v3 = acc[mt][nt][3] + b.y;
            if (mode == 0) {
                float2 o0 = { v0, v1 }, o1 = { v2, v3 };
                *(float2*)&Cf[(size_t)row * DMODEL + col] = o0;
                *(float2*)&Cf[(size_t)(row + 8) * DMODEL + col] = o1;
            } else if (mode == 1) {
                __nv_bfloat16 h0 = __float2bfloat16(v0), h1 = __float2bfloat16(v1);
                __nv_bfloat16 h2 = __float2bfloat16(v2), h3 = __float2bfloat16(v3);
                __nv_bfloat162 H0; H0.x = h0; H0.y = h1;
                __nv_bfloat162 H1; H1.x = h2; H1.y = h3;
                *(__nv_bfloat162*)(Ch + (size_t)row * DMODEL + col) = H0;
                *(__nv_bfloat162*)(Ch + (size_t)(row + 8) * DMODEL + col) = H1;
                __nv_bfloat162 L0, L1;
                L0.x = __float2bfloat16(v0 - __bfloat162float(h0));
                L0.y = __float2bfloat16(v1 - __bfloat162float(h1));
                L1.x = __float2bfloat16(v2 - __bfloat162float(h2));
                L1.y = __float2bfloat16(v3 - __bfloat162float(h3));
                *(__nv_bfloat162*)(Cl + (size_t)row * DMODEL + col) = L0;
                *(__nv_bfloat162*)(Cl + (size_t)(row + 8) * DMODEL + col) = L1;
            } else {
                // V transposed layout: idx = ((b*16+h)*64 + d)*2048 + t
#pragma unroll
                for (int e = 0; e < 4; e++) {
                    float v = (e == 0) ? v0 : (e == 1) ? v1 : (e == 2) ? v2 : v3;
                    int r = row + (e >= 2 ? 8 : 0);
                    int c = col + (e & 1);
                    int bb = r >> 11, t = r & 2047;
                    int hh = c >> 6, dl = c & 63;
                    size_t idx = ((size_t)((bb * 16 + hh) * 64 + dl)) * 2048 + t;
                    __nv_bfloat16 hv = __float2bfloat16(v);
                    Ch[idx] = hv;
                    Cl[idx] = __float2bfloat16(v - __bfloat162float(hv));
                }
            }
        }
    }
}

// ---------------------------------------------------------------------------
// HMMA bf16-split causal flash attention.
// Grid: (SEQ/128, B*H). 8 warps (warp owns 16 query rows). Key tiles of 64.
// S = Qh·Kh + Qh·Kl + Ql·Kh ; O = Ph·Vh + Ph·Vl + Pl·Vh (fp32 accum).
// Q tiles [128][64] bf16 (128B rows, SW128); K [64][64]; Vt [64 dims][64 keys]
// (V pre-transposed globally by the V-projection epilogue).
// Output written as bf16 hi/lo for the output projection.
// ---------------------------------------------------------------------------
#define AQ_B (128 * 128)               // 16 KB per Q tile
#define AK_B (64 * 128)                // 8 KB per K/V tile
#define ATT_SMEM (2 * AQ_B + 4 * AK_B) // 64 KB

__global__ __launch_bounds__(256)
void attn_hmma(const __nv_bfloat16* __restrict__ qh, const __nv_bfloat16* __restrict__ ql,
               const __nv_bfloat16* __restrict__ kh, const __nv_bfloat16* __restrict__ kl,
               const __nv_bfloat16* __restrict__ vth, const __nv_bfloat16* __restrict__ vtl,
               __nv_bfloat16* __restrict__ oh, __nv_bfloat16* __restrict__ ol)
{
    extern __shared__ __align__(16) char smem[];
    const uint32_t smem_u = smem_to_u32(smem);
    char* sQh = smem;
    char* sQl = sQh + AQ_B;
    char* sKh = sQl + AQ_B;
    char* sKl = sKh + AK_B;
    char* sVh = sKl + AK_B;
    char* sVl = sVh + AK_B;
    const uint32_t uQh = smem_u;
    const uint32_t uQl = uQh + AQ_B;
    const uint32_t uKh = uQl + AQ_B;
    const uint32_t uKl = uKh + AK_B;
    const uint32_t uVh = uKl + AK_B;
    const uint32_t uVl = uVh + AK_B;

    const int tid  = threadIdx.x;
    const int wid  = tid >> 5;
    const int lane = tid & 31;
    const int g    = lane >> 2;
    const int t2   = (lane & 3) * 2;

    const int qb = (gridDim.x - 1) - blockIdx.x;   // heavy CTAs first
    const int bh = blockIdx.y;
    const int b  = bh >> 4;
    const int h  = bh & 15;

    const int q0loc  = qb * 128;                   // within batch
    const int rowg   = b * SEQ + q0loc;            // global token row of tile
    const __nv_bfloat16* qhb = qh + (size_t)rowg * DMODEL + h * HDIM;
    const __nv_bfloat16* qlb = ql + (size_t)rowg * DMODEL + h * HDIM;
    const __nv_bfloat16* khb = kh + (size_t)(b * SEQ) * DMODEL + h * HDIM;
    const __nv_bfloat16* klb = kl + (size_t)(b * SEQ) * DMODEL + h * HDIM;
    const __nv_bfloat16* vhb = vth + (size_t)bh * 64 * SEQ;
    const __nv_bfloat16* vlb = vtl + (size_t)bh * 64 * SEQ;

    // ldmatrix offset tables (within a [rows][128B] SW128 tile)
    uint32_t offA[4];
    {
        int rowA = (lane & 7) + ((lane >> 3) & 1) * 8;
        int chi  = (lane >> 4) & 1;
#pragma unroll
        for (int kt = 0; kt < 4; kt++)
            offA[kt] = SWZ128((wid * 16 + rowA) * 128 + (kt * 2 + chi) * 16);
    }
    uint32_t offB[4][4];   // [np: 16-row group][kt]
    {
        int rb  = (lane & 7) + ((lane >> 4) & 1) * 8;
        int chi = (lane >> 3) & 1;
#pragma unroll
        for (int np = 0; np < 4; np++)
#pragma unroll
            for (int kt = 0; kt < 4; kt++)
                offB[np][kt] = SWZ128((np * 16 + rb) * 128 + (kt * 2 + chi) * 16);
    }

    // Load Q tile (hi+lo): 128 rows x 8 chunks of 16B
    for (int it = tid; it < 1024; it += 256) {
        int row = it >> 3, c = it & 7;
        size_t goff = (size_t)row * DMODEL + c * 8;
        uint32_t soff = SWZ128(row * 128 + c * 16);
        *(float4*)(sQh + soff) = *(const float4*)(qhb + goff);
        *(float4*)(sQl + soff) = *(const float4*)(qlb + goff);
    }

    float O[8][4];
#pragma unroll
    for (int nt = 0; nt < 8; nt++)
#pragma unroll
        for (int e = 0; e < 4; e++) O[nt][e] = 0.f;
    float m0 = -1e30f, m1 = -1e30f, l0 = 0.f, l1 = 0.f;

    const int jmax = 2 * qb + 1;
    const float scale = 0.125f;

    for (int j = 0; j <= jmax; j++) {
        const int k0 = j * 64;
        // Load K (hi+lo) and Vt (hi+lo) tiles: 64 rows x 8 chunks each
        for (int it = tid; it < 512; it += 256) {
            int row = it >> 3, c = it & 7;
            uint32_t soff = SWZ128(row * 128 + c * 16);
            *(float4*)(sKh + soff) = *(const float4*)(khb + (size_t)(k0 + row) * DMODEL + c * 8);
            *(float4*)(sKl + soff) = *(const float4*)(klb + (size_t)(k0 + row) * DMODEL + c * 8);
            *(float4*)(sVh + soff) = *(const float4*)(vhb + (size_t)row * SEQ + k0 + c * 8);
            *(float4*)(sVl + soff) = *(const float4*)(vlb + (size_t)row * SEQ + k0 + c * 8);
        }
        __syncthreads();

        // ---- S = Q . K^T (3-pass split), S[nt][e], nt over 8 key-octets
        float S[8][4];
#pragma unroll
        for (int nt = 0; nt < 8; nt++)
#pragma unroll
            for (int e = 0; e < 4; e++) S[nt][e] = 0.f;

#pragma unroll
        for (int kt = 0; kt < 4; kt++) {
            uint32_t aH[4], aL[4];
            ldsm4(aH, uQh + offA[kt]);
            ldsm4(aL, uQl + offA[kt]);
            uint32_t bH[16], bL[16];
#pragma unroll
            for (int np = 0; np < 4; np++) {
                ldsm4(&bH[np * 4], uKh + offB[np][kt]);
                ldsm4(&bL[np * 4], uKl + offB[np][kt]);
            }
#pragma unroll
            for (int nt = 0; nt < 8; nt++) {
                uint32_t* ph = &bH[(nt >> 1) * 4 + (nt & 1) * 2];
                uint32_t* pl = &bL[(nt >> 1) * 4 + (nt & 1) * 2];
                mma16816(S[nt], aH, ph);
                mma16816(S[nt], aH, pl);
                mma16816(S[nt], aL, ph);
            }
        }

        // ---- scale + mask
        const bool masked = (j >= 2 * qb);
        const int qrow0 = q0loc + wid * 16 + g;
#pragma unroll
        for (int nt = 0; nt < 8; nt++) {
#pragma unroll
            for (int e = 0; e < 4; e++) {
                float s = S[nt][e] * scale;
                if (masked) {
                    int key = k0 + nt * 8 + t2 + (e & 1);
                    int qr  = qrow0 + ((e >> 1) * 8);
                    if (key > qr) s = -1e30f;
                }
                S[nt][e] = s;
            }
        }

        // ---- online softmax (rows g and g+8)
        float tm0 = -1e30f, tm1 = -1e30f;
#pragma unroll
        for (int nt = 0; nt < 8; nt++) {
            tm0 = fmaxf(tm0, fmaxf(S[nt][0], S[nt][1]));
            tm1 = fmaxf(tm1, fmaxf(S[nt][2], S[nt][3]));
        }
        tm0 = fmaxf(tm0, __shfl_xor_sync(0xffffffffu, tm0, 1));
        tm0 = fmaxf(tm0, __shfl_xor_sync(0xffffffffu, tm0, 2));
        tm1 = fmaxf(tm1, __shfl_xor_sync(0xffffffffu, tm1, 1));
        tm1 = fmaxf(tm1, __shfl_xor_sync(0xffffffffu, tm1, 2));
        float mn0 = fmaxf(m0, tm0), mn1 = fmaxf(m1, tm1);
        float al0 = __expf(m0 - mn0), al1 = __expf(m1 - mn1);
        float ls0 = 0.f, ls1 = 0.f;
#pragma unroll
        for (int nt = 0; nt < 8; nt++) {
            float p0 = __expf(S[nt][0] - mn0);
            float p1 = __expf(S[nt][1] - mn0);
            float p2 = __expf(S[nt][2] - mn1);
            float p3 = __expf(S[nt][3] - mn1);
            ls0 += p0 + p1; ls1 += p2 + p3;
            S[nt][0] = p0; S[nt][1] = p1; S[nt][2] = p2; S[nt][3] = p3;
        }
        ls0 += __shfl_xor_sync(0xffffffffu, ls0, 1);
        ls0 += __shfl_xor_sync(0xffffffffu, ls0, 2);
        ls1 += __shfl_xor_sync(0xffffffffu, ls1, 1);
        ls1 += __shfl_xor_sync(0xffffffffu, ls1, 2);
        l0 = l0 * al0 + ls0;  m0 = mn0;
        l1 = l1 * al1 + ls1;  m1 = mn1;
#pragma unroll
        for (int nt = 0; nt < 8; nt++) {
            O[nt][0] *= al0; O[nt][1] *= al0;
            O[nt][2] *= al1; O[nt][3] *= al1;
        }

        // ---- pack P hi/lo into A-fragments (per k16 chunk kc)
        uint32_t pH[4][4], pL[4][4];
#pragma unroll
        for (int kc = 0; kc < 4; kc++) {
            float c00 = S[2 * kc][0],     c01 = S[2 * kc][1];
            float c02 = S[2 * kc][2],     c03 = S[2 * kc][3];
            float c10 = S[2 * kc + 1][0], c11 = S[2 * kc + 1][1];
            float c12 = S[2 * kc + 1][2], c13 = S[2 * kc + 1][3];
            pH[kc][0] = pack_bf2(c00, c01);
            pH[kc][1] = pack_bf2(c02, c03);
            pH[kc][2] = pack_bf2(c10, c11);
            pH[kc][3] = pack_bf2(c12, c13);
            // residuals
            __nv_bfloat162* t;
            t = (__nv_bfloat162*)&pH[kc][0];
            pL[kc][0] = pack_bf2(c00 - __bfloat162float(t->x), c01 - __bfloat162float(t->y));
            t = (__nv_bfloat162*)&pH[kc][1];
            pL[kc][1] = pack_bf2(c02 - __bfloat162float(t->x), c03 - __bfloat162float(t->y));
            t = (__nv_bfloat162*)&pH[kc][2];
            pL[kc][2] = pack_bf2(c10 - __bfloat162float(t->x), c11 - __bfloat162float(t->y));
            t = (__nv_bfloat162*)&pH[kc][3];
            pL[kc][3] = pack_bf2(c12 - __bfloat162float(t->x), c13 - __bfloat162float(t->y));
        }

        // ---- O += P . V  (3-pass split); nt over 8 dim-octets
#pragma unroll
        for (int kc = 0; kc < 4; kc++) {
            uint32_t vH[16], vL[16];
#pragma unroll
            for (int np = 0; np < 4; np++) {
                ldsm4(&vH[np * 4], uVh + offB[np][kc]);
                ldsm4(&vL[np * 4], uVl + offB[np][kc]);
            }
#pragma unroll
            for (int nt = 0; nt < 8; nt++) {
                uint32_t* bv = &vH[(nt >> 1) * 4 + (nt & 1) * 2];
                uint32_t* bw = &vL[(nt >> 1) * 4 + (nt & 1) * 2];
                mma16816(O[nt], pH[kc], bv);
                mma16816(O[nt], pH[kc], bw);
                mma16816(O[nt], pL[kc], bv);
            }
        }
        __syncthreads();   // before next tile overwrites K/V
    }

    // ---- epilogue: normalize, split hi/lo, store
    const float inv0 = 1.f / l0, inv1 = 1.f / l1;
    const int row0 = rowg + wid * 16 + g;
    const int row1 = row0 + 8;
#pragma unroll
    for (int nt = 0; nt < 8; nt++) {
        int col = h * HDIM + nt * 8 + t2;
        float v0 = O[nt][0] * inv0, v1 = O[nt][1] * inv0;
        float v2 = O[nt][2] * inv1, v3 = O[nt][3] * inv1;
        __nv_bfloat16 h0 = __float2bfloat16(v0), h1 = __float2bfloat16(v1);
        __nv_bfloat16 h2 = __float2bfloat16(v2), h3 = __float2bfloat16(v3);
        __nv_bfloat162 H0; H0.x = h0; H0.y = h1;
        __nv_bfloat162 H1; H1.x = h2; H1.y = h3;
        *(__nv_bfloat162*)(oh + (size_t)row0 * DMODEL + col) = H0;
        *(__nv_bfloat162*)(oh + (size_t)row1 * DMODEL + col) = H1;
        __nv_bfloat162 L0, L1;
        L0.x = __float2bfloat16(v0 - __bfloat162float(h0));
        L0.y = __float2bfloat16(v1 - __bfloat162float(h1));
        L1.x = __float2bfloat16(v2 - __bfloat162float(h2));
        L1.y = __float2bfloat16(v3 - __bfloat162float(h3));
        *(__nv_bfloat162*)(ol + (size_t)row0 * DMODEL + col) = L0;
        *(__nv_bfloat162*)(ol + (size_t)row1 * DMODEL + col) = L1;
    }
}

// ---------------------------------------------------------------------------
// Launch
// ---------------------------------------------------------------------------
extern "C" void kernel_launch(void* const* d_in, const int* in_sizes, int n_in,
                              void* d_out, int out_size)
{
    const float* x  = (const float*)d_in[0];
    const float* Wq = (const float*)d_in[1];
    const float* bq = (const float*)d_in[2];
    const float* Wk = (const float*)d_in[3];
    const float* bk = (const float*)d_in[4];
    const float* Wv = (const float*)d_in[5];
    const float* bv = (const float*)d_in[6];
    const float* Wo = (const float*)d_in[7];
    const float* bo = (const float*)d_in[8];
    float* out = (float*)d_out;

    __nv_bfloat16 *xh, *xl, *qh, *ql, *kh, *kl, *vth, *vtl, *ath, *atl, *wh, *wl;
    cudaGetSymbolAddress((void**)&xh,  g_xh);
    cudaGetSymbolAddress((void**)&xl,  g_xl);
    cudaGetSymbolAddress((void**)&qh,  g_qh);
    cudaGetSymbolAddress((void**)&ql,  g_ql);
    cudaGetSymbolAddress((void**)&kh,  g_kh);
    cudaGetSymbolAddress((void**)&kl,  g_kl);
    cudaGetSymbolAddress((void**)&vth, g_vth);
    cudaGetSymbolAddress((void**)&vtl, g_vtl);
    cudaGetSymbolAddress((void**)&ath, g_ath);
    cudaGetSymbolAddress((void**)&atl, g_atl);
    cudaGetSymbolAddress((void**)&wh,  g_wh);
    cudaGetSymbolAddress((void**)&wl,  g_wl);

    const int WN = DMODEL * DMODEL;
    const float* Ws[4] = { Wq, Wk, Wv, Wo };

    split_bf16<<<(MTOT * DMODEL / 4 + 255) / 256, 256>>>(x, xh, xl, MTOT * DMODEL / 4);
    for (int i = 0; i < 4; i++)
        split_bf16<<<(WN / 4 + 255) / 256, 256>>>(Ws[i], wh + (size_t)i * WN, wl + (size_t)i * WN, WN / 4);

    cudaFuncSetAttribute(gemm_hmma_split, cudaFuncAttributeMaxDynamicSharedMemorySize, GEMM_SMEM);
    cudaFuncSetAttribute(attn_hmma, cudaFuncAttributeMaxDynamicSharedMemorySize, ATT_SMEM);

    dim3 gg(DMODEL / 128, MTOT / 128);       // (8, 64)
    gemm_hmma_split<<<gg, 256, GEMM_SMEM>>>(xh, xl, wh + 0 * (size_t)WN, wl + 0 * (size_t)WN, bq,
                                            nullptr, qh, ql, 1);
    gemm_hmma_split<<<gg, 256, GEMM_SMEM>>>(xh, xl, wh + 1 * (size_t)WN, wl + 1 * (size_t)WN, bk,
                                            nullptr, kh, kl, 1);
    gemm_hmma_split<<<gg, 256, GEMM_SMEM>>>(xh, xl, wh + 2 * (size_t)WN, wl + 2 * (size_t)WN, bv,
                                            nullptr, vth, vtl, 2);

    attn_hmma<<<dim3(SEQ / 128, BATCH * NHEADS), 256, ATT_SMEM>>>(qh, ql, kh, kl, vth, vtl, ath, atl);

    gemm_hmma_split<<<gg, 256, GEMM_SMEM>>>(ath, atl, wh + 3 * (size_t)WN, wl + 3 * (size_t)WN, bo,
                                            out, nullptr, nullptr, 0);
}

// round 6
// speedup vs baseline: 10.1585x; 1.6166x over previous
#include <cuda_runtime.h>
#include <cuda_fp16.h>
#include <cstdint>
#include <math.h>

// Problem constants
#define BATCH   4
#define SEQ     2048
#define DMODEL  1024
#define NHEADS  16
#define HDIM    64
#define MTOT    (BATCH * SEQ)          // 8192 rows

// ---------------------------------------------------------------------------
// Scratch (static __device__ — no allocations allowed)
// ---------------------------------------------------------------------------
__device__ __half g_xh[MTOT * DMODEL];
__device__ __half g_qh[MTOT * DMODEL];
__device__ __half g_ql[MTOT * DMODEL];
__device__ __half g_kh[MTOT * DMODEL];
__device__ __half g_kl[MTOT * DMODEL];
__device__ __half g_vth[MTOT * DMODEL];   // [b*16+h][64 dims][2048 T]
__device__ __half g_vtl[MTOT * DMODEL];
__device__ __half g_ath[MTOT * DMODEL];
__device__ __half g_wh[4][DMODEL * DMODEL];
__device__ __half g_wl[4][DMODEL * DMODEL];

// ---------------------------------------------------------------------------
// mma.sync / ldmatrix / cp.async helpers (portable PTX, valid on plain sm_103)
// ---------------------------------------------------------------------------
__device__ __forceinline__ uint32_t smem_to_u32(const void* p) {
    uint32_t a;
    asm("{ .reg .u64 t; cvta.to.shared.u64 t, %1; cvt.u32.u64 %0, t; }" : "=r"(a) : "l"(p));
    return a;
}
__device__ __forceinline__ void ldsm4(uint32_t* d, uint32_t addr) {
    asm volatile("ldmatrix.sync.aligned.m8n8.x4.shared.b16 {%0,%1,%2,%3}, [%4];"
                 : "=r"(d[0]), "=r"(d[1]), "=r"(d[2]), "=r"(d[3]) : "r"(addr));
}
__device__ __forceinline__ void mma16816(float* c, const uint32_t* a, const uint32_t* b) {
    asm volatile("mma.sync.aligned.m16n8k16.row.col.f32.f16.f16.f32 "
                 "{%0,%1,%2,%3}, {%4,%5,%6,%7}, {%8,%9}, {%0,%1,%2,%3};"
                 : "+f"(c[0]), "+f"(c[1]), "+f"(c[2]), "+f"(c[3])
                 : "r"(a[0]), "r"(a[1]), "r"(a[2]), "r"(a[3]), "r"(b[0]), "r"(b[1]));
}
__device__ __forceinline__ uint32_t pack_h2(float a, float b) {
    __half2 t = __floats2half2_rn(a, b);
    return *reinterpret_cast<uint32_t*>(&t);
}
#define CP_ASYNC16(dst, src) \
    asm volatile("cp.async.cg.shared.global [%0], [%1], 16;" \
                 :: "r"(dst), "l"(__cvta_generic_to_global(src)) : "memory")
#define CP_COMMIT() asm volatile("cp.async.commit_group;" ::: "memory")
#define CP_WAIT(n)  asm volatile("cp.async.wait_group %0;" :: "n"(n) : "memory")

// SW64-style swizzle for 64B rows (GEMM tiles)
#define SWZ64(o) ((o) ^ (((o) >> 3) & 0x30))
// SW128-style swizzle for 128B rows (attention tiles)
#define SWZ128(o) ((o) ^ (((o) >> 3) & 0x70))

// ---------------------------------------------------------------------------
// fp16 splits:  hi = fp16(x) [, lo = fp16(x - hi)]
// ---------------------------------------------------------------------------
__global__ void split_h(const float* __restrict__ in, __half* __restrict__ hi, int n4)
{
    int i = blockIdx.x * blockDim.x + threadIdx.x;
    if (i >= n4) return;
    float4 x = ((const float4*)in)[i];
    __half2 h0 = __floats2half2_rn(x.x, x.y);
    __half2 h1 = __floats2half2_rn(x.z, x.w);
    ((__half2*)hi)[i * 2 + 0] = h0;
    ((__half2*)hi)[i * 2 + 1] = h1;
}

__global__ void split_hl(const float* __restrict__ in,
                         __half* __restrict__ hi, __half* __restrict__ lo, int n4)
{
    int i = blockIdx.x * blockDim.x + threadIdx.x;
    if (i >= n4) return;
    float4 x = ((const float4*)in)[i];
    __half2 h0 = __floats2half2_rn(x.x, x.y);
    __half2 h1 = __floats2half2_rn(x.z, x.w);
    ((__half2*)hi)[i * 2 + 0] = h0;
    ((__half2*)hi)[i * 2 + 1] = h1;
    __half2 l0 = __floats2half2_rn(x.x - __half2float(h0.x), x.y - __half2float(h0.y));
    __half2 l1 = __floats2half2_rn(x.z - __half2float(h1.x), x.w - __half2float(h1.y));
    ((__half2*)lo)[i * 2 + 0] = l0;
    ((__half2*)lo)[i * 2 + 1] = l1;
}

// ---------------------------------------------------------------------------
// HMMA fp16 2-pass GEMM:  C[m,n] = sum_k A[m,k]*W[n,k] + bias[n]
//   C ≈ Ah·Wh^T + Ah·Wl^T  (A residual dropped; W = Wh + Wl to 2^-22)
// CTA 128x128, 8 warps (2m x 4n), warp tile 64x32, mma m16n8k16.
// K-chunk 32; stage = {Ah, Bh, Bl} 128x32 fp16 tiles (64B rows, SW64),
// 3-stage cp.async ring.
// Epilogues: 0 = fp32 C; 1 = hi/lo fp16 rows; 2 = hi/lo fp16 [b,h,d,T] (V)
// ---------------------------------------------------------------------------
#define BK 32
#define NCHUNK (DMODEL / BK)           // 32
#define TILE_BYTES (128 * 64)          // 8 KB
#define STAGE_BYTES (3 * TILE_BYTES)   // 24 KB
#define GEMM_SMEM (3 * STAGE_BYTES)    // 72 KB

__global__ __launch_bounds__(256)
void gemm_hmma2(const __half* __restrict__ Ah,
                const __half* __restrict__ Bh, const __half* __restrict__ Bl,
                const float* __restrict__ bias, float* __restrict__ Cf,
                __half* __restrict__ Ch, __half* __restrict__ Cl, int mode)
{
    extern __shared__ __align__(16) char smem[];
    const uint32_t smem_u = smem_to_u32(smem);

    const int tid  = threadIdx.x;
    const int wid  = tid >> 5;
    const int lane = tid & 31;
    const int wm   = wid & 1;
    const int wn   = wid >> 1;
    const int m0 = blockIdx.y * 128;
    const int n0 = blockIdx.x * 128;

    uint32_t offA[4][2];
    {
        int rowA = (lane & 7) + ((lane >> 3) & 1) * 8;
        int chi  = (lane >> 4) & 1;
#pragma unroll
        for (int mt = 0; mt < 4; mt++)
#pragma unroll
            for (int kt = 0; kt < 2; kt++)
                offA[mt][kt] = SWZ64((wm * 64 + mt * 16 + rowA) * 64 + (kt * 2 + chi) * 16);
    }
    uint32_t offB[2][2];
    {
        int rb  = (lane & 7) + ((lane >> 4) & 1) * 8;
        int chi = (lane >> 3) & 1;
#pragma unroll
        for (int np = 0; np < 2; np++)
#pragma unroll
            for (int kt = 0; kt < 2; kt++)
                offB[np][kt] = SWZ64((wn * 32 + np * 16 + rb) * 64 + (kt * 2 + chi) * 16);
    }

    float acc[4][4][4];
#pragma unroll
    for (int mt = 0; mt < 4; mt++)
#pragma unroll
        for (int nt = 0; nt < 4; nt++)
#pragma unroll
            for (int e = 0; e < 4; e++) acc[mt][nt][e] = 0.f;

    const __half* srcs[3] = { Ah, Bh, Bl };

    auto cpa = [&](int c, int s) {
        const int k0 = c * BK;
        const uint32_t st = smem_u + s * STAGE_BYTES;
#pragma unroll
        for (int t = 0; t < 3; t++) {
            const __half* src = srcs[t];
            const int r0 = (t == 0) ? m0 : n0;
#pragma unroll
            for (int i = 0; i < 2; i++) {
                int fid = tid + i * 256;
                int row = fid >> 2, cc = fid & 3;
                uint32_t dst = st + t * TILE_BYTES + SWZ64(row * 64 + cc * 16);
                CP_ASYNC16(dst, src + (size_t)(r0 + row) * DMODEL + k0 + cc * 8);
            }
        }
    };

    auto mma_chunk = [&](int s) {
        const uint32_t sb = smem_u + s * STAGE_BYTES;
#pragma unroll
        for (int kt = 0; kt < 2; kt++) {
            uint32_t bh[8], bl[8];
#pragma unroll
            for (int np = 0; np < 2; np++) {
                ldsm4(&bh[np * 4], sb + TILE_BYTES + offB[np][kt]);
                ldsm4(&bl[np * 4], sb + 2 * TILE_BYTES + offB[np][kt]);
            }
            uint32_t a[4][4];
#pragma unroll
            for (int mt = 0; mt < 4; mt++)
                ldsm4(a[mt], sb + offA[mt][kt]);
#pragma unroll
            for (int mt = 0; mt < 4; mt++)
#pragma unroll
                for (int nt = 0; nt < 4; nt++) {
                    mma16816(acc[mt][nt], a[mt], &bh[(nt >> 1) * 4 + (nt & 1) * 2]);
                    mma16816(acc[mt][nt], a[mt], &bl[(nt >> 1) * 4 + (nt & 1) * 2]);
                }
        }
    };

    cpa(0, 0); CP_COMMIT();
    cpa(1, 1); CP_COMMIT();
    for (int c = 0; c < NCHUNK; c++) {
        if (c == NCHUNK - 1) { CP_WAIT(0); } else { CP_WAIT(1); }
        __syncthreads();
        if (c + 2 < NCHUNK) { cpa(c + 2, (c + 2) % 3); CP_COMMIT(); }
        mma_chunk(c % 3);
        __syncthreads();
    }

    // Epilogue
    const int g  = lane >> 2;
    const int t2 = (lane & 3) * 2;
#pragma unroll
    for (int mt = 0; mt < 4; mt++) {
#pragma unroll
        for (int nt = 0; nt < 4; nt++) {
            int row = m0 + wm * 64 + mt * 16 + g;
            int col = n0 + wn * 32 + nt * 8 + t2;
            float2 b = *(const float2*)&bias[col];
            float v0 = acc[mt][nt][0] + b.x;
            float v1 = acc[mt][nt][1] + b.y;
            float v2 = acc[mt][nt][2] + b.x;
            float v3 = acc[mt][nt][3] + b.y;
            if (mode == 0) {
                float2 o0 = { v0, v1 }, o1 = { v2, v3 };
                *(float2*)&Cf[(size_t)row * DMODEL + col] = o0;
                *(float2*)&Cf[(size_t)(row + 8) * DMODEL + col] = o1;
            } else if (mode == 1) {
                __half2 H0 = __floats2half2_rn(v0, v1);
                __half2 H1 = __floats2half2_rn(v2, v3);
                *(__half2*)(Ch + (size_t)row * DMODEL + col) = H0;
                *(__half2*)(Ch + (size_t)(row + 8) * DMODEL + col) = H1;
                __half2 L0 = __floats2half2_rn(v0 - __half2float(H0.x), v1 - __half2float(H0.y));
                __half2 L1 = __floats2half2_rn(v2 - __half2float(H1.x), v3 - __half2float(H1.y));
                *(__half2*)(Cl + (size_t)row * DMODEL + col) = L0;
                *(__half2*)(Cl + (size_t)(row + 8) * DMODEL + col) = L1;
            } else {
                // V transposed layout: idx = ((b*16+h)*64 + d)*2048 + t
#pragma unroll
                for (int e = 0; e < 4; e++) {
                    float v = (e == 0) ? v0 : (e == 1) ? v1 : (e == 2) ? v2 : v3;
                    int r = row + (e >= 2 ? 8 : 0);
                    int c = col + (e & 1);
                    int bb = r >> 11, t = r & 2047;
                    int hh = c >> 6, dl = c & 63;
                    size_t idx = ((size_t)((bb * 16 + hh) * 64 + dl)) * 2048 + t;
                    __half hv = __float2half_rn(v);
                    Ch[idx] = hv;
                    Cl[idx] = __float2half_rn(v - __half2float(hv));
                }
            }
        }
    }
}

// ---------------------------------------------------------------------------
// HMMA fp16 3-pass causal flash attention (cp.async double-buffered K/V).
// Grid: (SEQ/128, B*H), 8 warps. Key tiles of 64.
// S = Qh·Kh + Qh·Kl + Ql·Kh ; O = Ph·Vh + Ph·Vl + Pl·Vh (fp32 accum).
// Output: fp16 hi only (consumed as the A operand of the 2-pass Wo GEMM).
// ---------------------------------------------------------------------------
#define AQ_B (128 * 128)               // 16 KB per Q tile
#define AK_B (64 * 128)                // 8 KB per K/V tile
#define KV_STAGE (4 * AK_B)            // 32 KB
#define ATT_SMEM (2 * AQ_B + 2 * KV_STAGE)   // 96 KB

__global__ __launch_bounds__(256)
void attn_hmma(const __half* __restrict__ qh, const __half* __restrict__ ql,
               const __half* __restrict__ kh, const __half* __restrict__ kl,
               const __half* __restrict__ vth, const __half* __restrict__ vtl,
               __half* __restrict__ oh)
{
    extern __shared__ __align__(16) char smem[];
    const uint32_t smem_u = smem_to_u32(smem);
    char* sQh = smem;
    char* sQl = sQh + AQ_B;
    const uint32_t uQh = smem_u;
    const uint32_t uQl = uQh + AQ_B;
    const uint32_t uKV = uQl + AQ_B;

    const int tid  = threadIdx.x;
    const int wid  = tid >> 5;
    const int lane = tid & 31;
    const int g    = lane >> 2;
    const int t2   = (lane & 3) * 2;

    const int qb = (gridDim.x - 1) - blockIdx.x;   // heavy CTAs first
    const int bh = blockIdx.y;
    const int b  = bh >> 4;
    const int h  = bh & 15;

    const int q0loc  = qb * 128;
    const int rowg   = b * SEQ + q0loc;
    const __half* qhb = qh + (size_t)rowg * DMODEL + h * HDIM;
    const __half* qlb = ql + (size_t)rowg * DMODEL + h * HDIM;
    const __half* khb = kh + (size_t)(b * SEQ) * DMODEL + h * HDIM;
    const __half* klb = kl + (size_t)(b * SEQ) * DMODEL + h * HDIM;
    const __half* vhb = vth + (size_t)bh * 64 * SEQ;
    const __half* vlb = vtl + (size_t)bh * 64 * SEQ;

    uint32_t offA[4];
    {
        int rowA = (lane & 7) + ((lane >> 3) & 1) * 8;
        int chi  = (lane >> 4) & 1;
#pragma unroll
        for (int kt = 0; kt < 4; kt++)
            offA[kt] = SWZ128((wid * 16 + rowA) * 128 + (kt * 2 + chi) * 16);
    }
    uint32_t offB[4][4];   // [np: 16-row group][kt]
    {
        int rb  = (lane & 7) + ((lane >> 4) & 1) * 8;
        int chi = (lane >> 3) & 1;
#pragma unroll
        for (int np = 0; np < 4; np++)
#pragma unroll
            for (int kt = 0; kt < 4; kt++)
                offB[np][kt] = SWZ128((np * 16 + rb) * 128 + (kt * 2 + chi) * 16);
    }

    // Load Q tile (hi+lo)
    for (int it = tid; it < 1024; it += 256) {
        int row = it >> 3, c = it & 7;
        size_t goff = (size_t)row * DMODEL + c * 8;
        uint32_t soff = SWZ128(row * 128 + c * 16);
        *(float4*)(sQh + soff) = *(const float4*)(qhb + goff);
        *(float4*)(sQl + soff) = *(const float4*)(qlb + goff);
    }

    auto cpa_kv = [&](int j, int s) {
        const int k0 = j * 64;
        const uint32_t st = uKV + s * KV_STAGE;
#pragma unroll
        for (int i = 0; i < 2; i++) {
            int it = tid + i * 256;
            int row = it >> 3, c = it & 7;
            uint32_t soff = SWZ128(row * 128 + c * 16);
            CP_ASYNC16(st + 0 * AK_B + soff, khb + (size_t)(k0 + row) * DMODEL + c * 8);
            CP_ASYNC16(st + 1 * AK_B + soff, klb + (size_t)(k0 + row) * DMODEL + c * 8);
            CP_ASYNC16(st + 2 * AK_B + soff, vhb + (size_t)row * SEQ + k0 + c * 8);
            CP_ASYNC16(st + 3 * AK_B + soff, vlb + (size_t)row * SEQ + k0 + c * 8);
        }
    };

    float O[8][4];
#pragma unroll
    for (int nt = 0; nt < 8; nt++)
#pragma unroll
        for (int e = 0; e < 4; e++) O[nt][e] = 0.f;
    float m0 = -1e30f, m1 = -1e30f, l0 = 0.f, l1 = 0.f;

    const int jmax = 2 * qb + 1;
    const float scale = 0.125f;

    cpa_kv(0, 0); CP_COMMIT();

    for (int j = 0; j <= jmax; j++) {
        CP_WAIT(0);
        __syncthreads();
        if (j < jmax) { cpa_kv(j + 1, (j + 1) & 1); CP_COMMIT(); }

        const uint32_t uKh = uKV + (j & 1) * KV_STAGE;
        const uint32_t uKl = uKh + AK_B;
        const uint32_t uVh = uKh + 2 * AK_B;
        const uint32_t uVl = uKh + 3 * AK_B;
        const int k0 = j * 64;

        // ---- S = Q . K^T (3-pass)
        float S[8][4];
#pragma unroll
        for (int nt = 0; nt < 8; nt++)
#pragma unroll
            for (int e = 0; e < 4; e++) S[nt][e] = 0.f;

#pragma unroll
        for (int kt = 0; kt < 4; kt++) {
            uint32_t aH[4], aL[4];
            ldsm4(aH, uQh + offA[kt]);
            ldsm4(aL, uQl + offA[kt]);
            uint32_t bH[16], bL[16];
#pragma unroll
            for (int np = 0; np < 4; np++) {
                ldsm4(&bH[np * 4], uKh + offB[np][kt]);
                ldsm4(&bL[np * 4], uKl + offB[np][kt]);
            }
#pragma unroll
            for (int nt = 0; nt < 8; nt++) {
                uint32_t* ph = &bH[(nt >> 1) * 4 + (nt & 1) * 2];
                uint32_t* pl = &bL[(nt >> 1) * 4 + (nt & 1) * 2];
                mma16816(S[nt], aH, ph);
                mma16816(S[nt], aH, pl);
                mma16816(S[nt], aL, ph);
            }
        }

        // ---- scale + mask
        const bool masked = (j >= 2 * qb);
        const int qrow0 = q0loc + wid * 16 + g;
#pragma unroll
        for (int nt = 0; nt < 8; nt++) {
#pragma unroll
            for (int e = 0; e < 4; e++) {
                float s = S[nt][e] * scale;
                if (masked) {
                    int key = k0 + nt * 8 + t2 + (e & 1);
                    int qr  = qrow0 + ((e >> 1) * 8);
                    if (key > qr) s = -1e30f;
                }
                S[nt][e] = s;
            }
        }

        // ---- online softmax (rows g and g+8)
        float tm0 = -1e30f, tm1 = -1e30f;
#pragma unroll
        for (int nt = 0; nt < 8; nt++) {
            tm0 = fmaxf(tm0, fmaxf(S[nt][0], S[nt][1]));
            tm1 = fmaxf(tm1, fmaxf(S[nt][2], S[nt][3]));
        }
        tm0 = fmaxf(tm0, __shfl_xor_sync(0xffffffffu, tm0, 1));
        tm0 = fmaxf(tm0, __shfl_xor_sync(0xffffffffu, tm0, 2));
        tm1 = fmaxf(tm1, __shfl_xor_sync(0xffffffffu, tm1, 1));
        tm1 = fmaxf(tm1, __shfl_xor_sync(0xffffffffu, tm1, 2));
        float mn0 = fmaxf(m0, tm0), mn1 = fmaxf(m1, tm1);
        float al0 = __expf(m0 - mn0), al1 = __expf(m1 - mn1);
        float ls0 = 0.f, ls1 = 0.f;
#pragma unroll
        for (int nt = 0; nt < 8; nt++) {
            float p0 = __expf(S[nt][0] - mn0);
            float p1 = __expf(S[nt][1] - mn0);
            float p2 = __expf(S[nt][2] - mn1);
            float p3 = __expf(S[nt][3] - mn1);
            ls0 += p0 + p1; ls1 += p2 + p3;
            S[nt][0] = p0; S[nt][1] = p1; S[nt][2] = p2; S[nt][3] = p3;
        }
        ls0 += __shfl_xor_sync(0xffffffffu, ls0, 1);
        ls0 += __shfl_xor_sync(0xffffffffu, ls0, 2);
        ls1 += __shfl_xor_sync(0xffffffffu, ls1, 1);
        ls1 += __shfl_xor_sync(0xffffffffu, ls1, 2);
        l0 = l0 * al0 + ls0;  m0 = mn0;
        l1 = l1 * al1 + ls1;  m1 = mn1;
#pragma unroll
        for (int nt = 0; nt < 8; nt++) {
            O[nt][0] *= al0; O[nt][1] *= al0;
            O[nt][2] *= al1; O[nt][3] *= al1;
        }

        // ---- pack P hi/lo into A-fragments
        uint32_t pH[4][4], pL[4][4];
#pragma unroll
        for (int kc = 0; kc < 4; kc++) {
            float c00 = S[2 * kc][0],     c01 = S[2 * kc][1];
            float c02 = S[2 * kc][2],     c03 = S[2 * kc][3];
            float c10 = S[2 * kc + 1][0], c11 = S[2 * kc + 1][1];
            float c12 = S[2 * kc + 1][2], c13 = S[2 * kc + 1][3];
            pH[kc][0] = pack_h2(c00, c01);
            pH[kc][1] = pack_h2(c02, c03);
            pH[kc][2] = pack_h2(c10, c11);
            pH[kc][3] = pack_h2(c12, c13);
            __half2* t;
            t = (__half2*)&pH[kc][0];
            pL[kc][0] = pack_h2(c00 - __half2float(t->x), c01 - __half2float(t->y));
            t = (__half2*)&pH[kc][1];
            pL[kc][1] = pack_h2(c02 - __half2float(t->x), c03 - __half2float(t->y));
            t = (__half2*)&pH[kc][2];
            pL[kc][2] = pack_h2(c10 - __half2float(t->x), c11 - __half2float(t->y));
            t = (__half2*)&pH[kc][3];
            pL[kc][3] = pack_h2(c12 - __half2float(t->x), c13 - __half2float(t->y));
        }

        // ---- O += P . V  (3-pass)
#pragma unroll
        for (int kc = 0; kc < 4; kc++) {
            uint32_t vH[16], vL[16];
#pragma unroll
            for (int np = 0; np < 4; np++) {
                ldsm4(&vH[np * 4], uVh + offB[np][kc]);
                ldsm4(&vL[np * 4], uVl + offB[np][kc]);
            }
#pragma unroll
            for (int nt = 0; nt < 8; nt++) {
                uint32_t* bv = &vH[(nt >> 1) * 4 + (nt & 1) * 2];
                uint32_t* bw = &vL[(nt >> 1) * 4 + (nt & 1) * 2];
                mma16816(O[nt], pH[kc], bv);
                mma16816(O[nt], pH[kc], bw);
                mma16816(O[nt], pL[kc], bv);
            }
        }
    }

    // ---- epilogue: normalize, fp16, store (hi only)
    const float inv0 = 1.f / l0, inv1 = 1.f / l1;
    const int row0 = rowg + wid * 16 + g;
    const int row1 = row0 + 8;
#pragma unroll
    for (int nt = 0; nt < 8; nt++) {
        int col = h * HDIM + nt * 8 + t2;
        __half2 H0 = __floats2half2_rn(O[nt][0] * inv0, O[nt][1] * inv0);
        __half2 H1 = __floats2half2_rn(O[nt][2] * inv1, O[nt][3] * inv1);
        *(__half2*)(oh + (size_t)row0 * DMODEL + col) = H0;
        *(__half2*)(oh + (size_t)row1 * DMODEL + col) = H1;
    }
}

// ---------------------------------------------------------------------------
// Launch
// ---------------------------------------------------------------------------
extern "C" void kernel_launch(void* const* d_in, const int* in_sizes, int n_in,
                              void* d_out, int out_size)
{
    const float* x  = (const float*)d_in[0];
    const float* Wq = (const float*)d_in[1];
    const float* bq = (const float*)d_in[2];
    const float* Wk = (const float*)d_in[3];
    const float* bk = (const float*)d_in[4];
    const float* Wv = (const float*)d_in[5];
    const float* bv = (const float*)d_in[6];
    const float* Wo = (const float*)d_in[7];
    const float* bo = (const float*)d_in[8];
    float* out = (float*)d_out;

    __half *xh, *qh, *ql, *kh, *kl, *vth, *vtl, *ath, *wh, *wl;
    cudaGetSymbolAddress((void**)&xh,  g_xh);
    cudaGetSymbolAddress((void**)&qh,  g_qh);
    cudaGetSymbolAddress((void**)&ql,  g_ql);
    cudaGetSymbolAddress((void**)&kh,  g_kh);
    cudaGetSymbolAddress((void**)&kl,  g_kl);
    cudaGetSymbolAddress((void**)&vth, g_vth);
    cudaGetSymbolAddress((void**)&vtl, g_vtl);
    cudaGetSymbolAddress((void**)&ath, g_ath);
    cudaGetSymbolAddress((void**)&wh,  g_wh);
    cudaGetSymbolAddress((void**)&wl,  g_wl);

    const int WN = DMODEL * DMODEL;
    const float* Ws[4] = { Wq, Wk, Wv, Wo };

    split_h<<<(MTOT * DMODEL / 4 + 255) / 256, 256>>>(x, xh, MTOT * DMODEL / 4);
    for (int i = 0; i < 4; i++)
        split_hl<<<(WN / 4 + 255) / 256, 256>>>(Ws[i], wh + (size_t)i * WN, wl + (size_t)i * WN, WN / 4);

    cudaFuncSetAttribute(gemm_hmma2, cudaFuncAttributeMaxDynamicSharedMemorySize, GEMM_SMEM);
    cudaFuncSetAttribute(attn_hmma, cudaFuncAttributeMaxDynamicSharedMemorySize, ATT_SMEM);

    dim3 gg(DMODEL / 128, MTOT / 128);       // (8, 64)
    gemm_hmma2<<<gg, 256, GEMM_SMEM>>>(xh, wh + 0 * (size_t)WN, wl + 0 * (size_t)WN, bq,
                                       nullptr, qh, ql, 1);
    gemm_hmma2<<<gg, 256, GEMM_SMEM>>>(xh, wh + 1 * (size_t)WN, wl + 1 * (size_t)WN, bk,
                                       nullptr, kh, kl, 1);
    gemm_hmma2<<<gg, 256, GEMM_SMEM>>>(xh, wh + 2 * (size_t)WN, wl + 2 * (size_t)WN, bv,
                                       nullptr, vth, vtl, 2);

    attn_hmma<<<dim3(SEQ / 128, BATCH * NHEADS), 256, ATT_SMEM>>>(qh, ql, kh, kl, vth, vtl, ath);

    gemm_hmma2<<<gg, 256, GEMM_SMEM>>>(ath, wh + 3 * (size_t)WN, wl + 3 * (size_t)WN, bo,
                                       out, nullptr, nullptr, 0);
}

// round 7
// speedup vs baseline: 10.8630x; 1.0693x over previous
#include <cuda_runtime.h>
#include <cuda_fp16.h>
#include <cstdint>
#include <math.h>

// Problem constants
#define BATCH   4
#define SEQ     2048
#define DMODEL  1024
#define NHEADS  16
#define HDIM    64
#define MTOT    (BATCH * SEQ)          // 8192 rows

// ---------------------------------------------------------------------------
// Scratch (static __device__ — no allocations allowed)
// ---------------------------------------------------------------------------
__device__ __half g_xh[MTOT * DMODEL];
__device__ __half g_qh[MTOT * DMODEL];
__device__ __half g_ql[MTOT * DMODEL];
__device__ __half g_kh[MTOT * DMODEL];
__device__ __half g_kl[MTOT * DMODEL];
__device__ __half g_vth[MTOT * DMODEL];   // [b*16+h][64 dims][2048 T]
__device__ __half g_vtl[MTOT * DMODEL];
__device__ __half g_ath[MTOT * DMODEL];
__device__ __half g_wh[4][DMODEL * DMODEL];
__device__ __half g_wl[4][DMODEL * DMODEL];

// ---------------------------------------------------------------------------
// mma.sync / ldmatrix / cp.async helpers (portable PTX, valid on plain sm_103)
// ---------------------------------------------------------------------------
__device__ __forceinline__ uint32_t smem_to_u32(const void* p) {
    uint32_t a;
    asm("{ .reg .u64 t; cvta.to.shared.u64 t, %1; cvt.u32.u64 %0, t; }" : "=r"(a) : "l"(p));
    return a;
}
__device__ __forceinline__ void ldsm4(uint32_t* d, uint32_t addr) {
    asm volatile("ldmatrix.sync.aligned.m8n8.x4.shared.b16 {%0,%1,%2,%3}, [%4];"
                 : "=r"(d[0]), "=r"(d[1]), "=r"(d[2]), "=r"(d[3]) : "r"(addr));
}
__device__ __forceinline__ void mma16816(float* c, const uint32_t* a, const uint32_t* b) {
    asm volatile("mma.sync.aligned.m16n8k16.row.col.f32.f16.f16.f32 "
                 "{%0,%1,%2,%3}, {%4,%5,%6,%7}, {%8,%9}, {%0,%1,%2,%3};"
                 : "+f"(c[0]), "+f"(c[1]), "+f"(c[2]), "+f"(c[3])
                 : "r"(a[0]), "r"(a[1]), "r"(a[2]), "r"(a[3]), "r"(b[0]), "r"(b[1]));
}
__device__ __forceinline__ uint32_t pack_h2(float a, float b) {
    __half2 t = __floats2half2_rn(a, b);
    return *reinterpret_cast<uint32_t*>(&t);
}
#define CP_ASYNC16(dst, src) \
    asm volatile("cp.async.cg.shared.global [%0], [%1], 16;" \
                 :: "r"(dst), "l"(__cvta_generic_to_global(src)) : "memory")
#define CP_COMMIT() asm volatile("cp.async.commit_group;" ::: "memory")
#define CP_WAIT(n)  asm volatile("cp.async.wait_group %0;" :: "n"(n) : "memory")

// SW64-style swizzle for 64B rows (GEMM tiles)
#define SWZ64(o) ((o) ^ (((o) >> 3) & 0x30))
// SW128-style swizzle for 128B rows (attention tiles)
#define SWZ128(o) ((o) ^ (((o) >> 3) & 0x70))

// ---------------------------------------------------------------------------
// fp16 splits
// ---------------------------------------------------------------------------
__global__ void split_h(const float* __restrict__ in, __half* __restrict__ hi, int n4)
{
    int i = blockIdx.x * blockDim.x + threadIdx.x;
    if (i >= n4) return;
    float4 x = ((const float4*)in)[i];
    ((__half2*)hi)[i * 2 + 0] = __floats2half2_rn(x.x, x.y);
    ((__half2*)hi)[i * 2 + 1] = __floats2half2_rn(x.z, x.w);
}

// 4 weights in one launch (blockIdx.y selects the weight)
__global__ void split_w4(const float* __restrict__ w0, const float* __restrict__ w1,
                         const float* __restrict__ w2, const float* __restrict__ w3,
                         __half* __restrict__ hi, __half* __restrict__ lo)
{
    const int n4 = DMODEL * DMODEL / 4;
    int i = blockIdx.x * blockDim.x + threadIdx.x;
    if (i >= n4) return;
    int z = blockIdx.y;
    const float* src = (z == 0) ? w0 : (z == 1) ? w1 : (z == 2) ? w2 : w3;
    size_t base = (size_t)z * (DMODEL * DMODEL / 2);   // in __half2 units
    float4 x = ((const float4*)src)[i];
    __half2 h0 = __floats2half2_rn(x.x, x.y);
    __half2 h1 = __floats2half2_rn(x.z, x.w);
    ((__half2*)hi)[base + i * 2 + 0] = h0;
    ((__half2*)hi)[base + i * 2 + 1] = h1;
    __half2 l0 = __floats2half2_rn(x.x - __half2float(h0.x), x.y - __half2float(h0.y));
    __half2 l1 = __floats2half2_rn(x.z - __half2float(h1.x), x.w - __half2float(h1.y));
    ((__half2*)lo)[base + i * 2 + 0] = l0;
    ((__half2*)lo)[base + i * 2 + 1] = l1;
}

// ---------------------------------------------------------------------------
// HMMA fp16 2-pass GEMM:  C[m,n] = sum_k A[m,k]*W[n,k] + bias[n]
//   C ≈ Ah·Wh^T + Ah·Wl^T.  CTA 128x128, 8 warps, mma m16n8k16.
// 2-stage cp.async ring (48 KB smem) -> 2 CTAs/SM.
// blockIdx.z picks the problem (batched Q/K/V in one launch).
// Epilogues: 0 = fp32 C; 1 = hi/lo fp16 rows; 2 = hi/lo fp16 [b,h,d,T] (V)
// ---------------------------------------------------------------------------
#define BK 32
#define NCHUNK (DMODEL / BK)           // 32
#define TILE_BYTES (128 * 64)          // 8 KB
#define STAGE_BYTES (3 * TILE_BYTES)   // 24 KB
#define GEMM_SMEM (2 * STAGE_BYTES)    // 48 KB

struct GemmArgs {
    const __half* Ah;
    const __half* Bh;
    const __half* Bl;
    const float*  bias;
    float*        Cf;
    __half*       Ch;
    __half*       Cl;
    int           mode;
};
struct GemmArgs3 { GemmArgs g[3]; };

__global__ __launch_bounds__(256, 2)
void gemm_hmma2(GemmArgs3 A3)
{
    const GemmArgs ga = A3.g[blockIdx.z];
    extern __shared__ __align__(16) char smem[];
    const uint32_t smem_u = smem_to_u32(smem);

    const int tid  = threadIdx.x;
    const int wid  = tid >> 5;
    const int lane = tid & 31;
    const int wm   = wid & 1;
    const int wn   = wid >> 1;
    const int m0 = blockIdx.y * 128;
    const int n0 = blockIdx.x * 128;

    uint32_t offA[4][2];
    {
        int rowA = (lane & 7) + ((lane >> 3) & 1) * 8;
        int chi  = (lane >> 4) & 1;
#pragma unroll
        for (int mt = 0; mt < 4; mt++)
#pragma unroll
            for (int kt = 0; kt < 2; kt++)
                offA[mt][kt] = SWZ64((wm * 64 + mt * 16 + rowA) * 64 + (kt * 2 + chi) * 16);
    }
    uint32_t offB[2][2];
    {
        int rb  = (lane & 7) + ((lane >> 4) & 1) * 8;
        int chi = (lane >> 3) & 1;
#pragma unroll
        for (int np = 0; np < 2; np++)
#pragma unroll
            for (int kt = 0; kt < 2; kt++)
                offB[np][kt] = SWZ64((wn * 32 + np * 16 + rb) * 64 + (kt * 2 + chi) * 16);
    }

    float acc[4][4][4];
#pragma unroll
    for (int mt = 0; mt < 4; mt++)
#pragma unroll
        for (int nt = 0; nt < 4; nt++)
#pragma unroll
            for (int e = 0; e < 4; e++) acc[mt][nt][e] = 0.f;

    const __half* srcs[3] = { ga.Ah, ga.Bh, ga.Bl };

    auto cpa = [&](int c, int s) {
        const int k0 = c * BK;
        const uint32_t st = smem_u + s * STAGE_BYTES;
#pragma unroll
        for (int t = 0; t < 3; t++) {
            const __half* src = srcs[t];
            const int r0 = (t == 0) ? m0 : n0;
#pragma unroll
            for (int i = 0; i < 2; i++) {
                int fid = tid + i * 256;
                int row = fid >> 2, cc = fid & 3;
                uint32_t dst = st + t * TILE_BYTES + SWZ64(row * 64 + cc * 16);
                CP_ASYNC16(dst, src + (size_t)(r0 + row) * DMODEL + k0 + cc * 8);
            }
        }
    };

    auto mma_chunk = [&](int s) {
        const uint32_t sb = smem_u + s * STAGE_BYTES;
#pragma unroll
        for (int kt = 0; kt < 2; kt++) {
            uint32_t bh[8], bl[8];
#pragma unroll
            for (int np = 0; np < 2; np++) {
                ldsm4(&bh[np * 4], sb + TILE_BYTES + offB[np][kt]);
                ldsm4(&bl[np * 4], sb + 2 * TILE_BYTES + offB[np][kt]);
            }
            uint32_t a[4][4];
#pragma unroll
            for (int mt = 0; mt < 4; mt++)
                ldsm4(a[mt], sb + offA[mt][kt]);
#pragma unroll
            for (int mt = 0; mt < 4; mt++)
#pragma unroll
                for (int nt = 0; nt < 4; nt++) {
                    mma16816(acc[mt][nt], a[mt], &bh[(nt >> 1) * 4 + (nt & 1) * 2]);
                    mma16816(acc[mt][nt], a[mt], &bl[(nt >> 1) * 4 + (nt & 1) * 2]);
                }
        }
    };

    cpa(0, 0); CP_COMMIT();
    for (int c = 0; c < NCHUNK; c++) {
        if (c + 1 < NCHUNK) {
            cpa(c + 1, (c + 1) & 1); CP_COMMIT();
            CP_WAIT(1);
        } else {
            CP_WAIT(0);
        }
        __syncthreads();
        mma_chunk(c & 1);
        __syncthreads();
    }

    // Epilogue
    const int g  = lane >> 2;
    const int t2 = (lane & 3) * 2;
#pragma unroll
    for (int mt = 0; mt < 4; mt++) {
#pragma unroll
        for (int nt = 0; nt < 4; nt++) {
            int row = m0 + wm * 64 + mt * 16 + g;
            int col = n0 + wn * 32 + nt * 8 + t2;
            float2 b = *(const float2*)&ga.bias[col];
            float v0 = acc[mt][nt][0] + b.x;
            float v1 = acc[mt][nt][1] + b.y;
            float v2 = acc[mt][nt][2] + b.x;
            float v3 = acc[mt][nt][3] + b.y;
            if (ga.mode == 0) {
                float2 o0 = { v0, v1 }, o1 = { v2, v3 };
                *(float2*)&ga.Cf[(size_t)row * DMODEL + col] = o0;
                *(float2*)&ga.Cf[(size_t)(row + 8) * DMODEL + col] = o1;
            } else if (ga.mode == 1) {
                __half2 H0 = __floats2half2_rn(v0, v1);
                __half2 H1 = __floats2half2_rn(v2, v3);
                *(__half2*)(ga.Ch + (size_t)row * DMODEL + col) = H0;
                *(__half2*)(ga.Ch + (size_t)(row + 8) * DMODEL + col) = H1;
                __half2 L0 = __floats2half2_rn(v0 - __half2float(H0.x), v1 - __half2float(H0.y));
                __half2 L1 = __floats2half2_rn(v2 - __half2float(H1.x), v3 - __half2float(H1.y));
                *(__half2*)(ga.Cl + (size_t)row * DMODEL + col) = L0;
                *(__half2*)(ga.Cl + (size_t)(row + 8) * DMODEL + col) = L1;
            } else {
                // V transposed layout: idx = ((b*16+h)*64 + d)*2048 + t
#pragma unroll
                for (int e = 0; e < 4; e++) {
                    float v = (e == 0) ? v0 : (e == 1) ? v1 : (e == 2) ? v2 : v3;
                    int r = row + (e >= 2 ? 8 : 0);
                    int c = col + (e & 1);
                    int bb = r >> 11, t = r & 2047;
                    int hh = c >> 6, dl = c & 63;
                    size_t idx = ((size_t)((bb * 16 + hh) * 64 + dl)) * 2048 + t;
                    __half hv = __float2half_rn(v);
                    ga.Ch[idx] = hv;
                    ga.Cl[idx] = __float2half_rn(v - __half2float(hv));
                }
            }
        }
    }
}

// ---------------------------------------------------------------------------
// HMMA fp16 3-pass causal flash attention (cp.async double-buffered K/V).
// Grid: (SEQ/128, B*H), 8 warps, 2 CTAs/SM. Key tiles of 64.
// S = Qh·Kh + Qh·Kl + Ql·Kh ; O = Ph·Vh + Ph·Vl + Pl·Vh (fp32 accum).
// Output: fp16 hi only (A operand of the 2-pass Wo GEMM).
// ---------------------------------------------------------------------------
#define AQ_B (128 * 128)               // 16 KB per Q tile
#define AK_B (64 * 128)                // 8 KB per K/V tile
#define KV_STAGE (4 * AK_B)            // 32 KB
#define ATT_SMEM (2 * AQ_B + 2 * KV_STAGE)   // 96 KB

__global__ __launch_bounds__(256, 2)
void attn_hmma(const __half* __restrict__ qh, const __half* __restrict__ ql,
               const __half* __restrict__ kh, const __half* __restrict__ kl,
               const __half* __restrict__ vth, const __half* __restrict__ vtl,
               __half* __restrict__ oh)
{
    extern __shared__ __align__(16) char smem[];
    const uint32_t smem_u = smem_to_u32(smem);
    char* sQh = smem;
    char* sQl = sQh + AQ_B;
    const uint32_t uQh = smem_u;
    const uint32_t uQl = uQh + AQ_B;
    const uint32_t uKV = uQl + AQ_B;

    const int tid  = threadIdx.x;
    const int wid  = tid >> 5;
    const int lane = tid & 31;
    const int g    = lane >> 2;
    const int t2   = (lane & 3) * 2;

    const int qb = (gridDim.x - 1) - blockIdx.x;   // heavy CTAs first
    const int bh = blockIdx.y;
    const int b  = bh >> 4;
    const int h  = bh & 15;

    const int q0loc  = qb * 128;
    const int rowg   = b * SEQ + q0loc;
    const __half* qhb = qh + (size_t)rowg * DMODEL + h * HDIM;
    const __half* qlb = ql + (size_t)rowg * DMODEL + h * HDIM;
    const __half* khb = kh + (size_t)(b * SEQ) * DMODEL + h * HDIM;
    const __half* klb = kl + (size_t)(b * SEQ) * DMODEL + h * HDIM;
    const __half* vhb = vth + (size_t)bh * 64 * SEQ;
    const __half* vlb = vtl + (size_t)bh * 64 * SEQ;

    uint32_t offA[4];
    {
        int rowA = (lane & 7) + ((lane >> 3) & 1) * 8;
        int chi  = (lane >> 4) & 1;
#pragma unroll
        for (int kt = 0; kt < 4; kt++)
            offA[kt] = SWZ128((wid * 16 + rowA) * 128 + (kt * 2 + chi) * 16);
    }
    uint32_t offB[4][4];   // [np: 16-row group][kt]
    {
        int rb  = (lane & 7) + ((lane >> 4) & 1) * 8;
        int chi = (lane >> 3) & 1;
#pragma unroll
        for (int np = 0; np < 4; np++)
#pragma unroll
            for (int kt = 0; kt < 4; kt++)
                offB[np][kt] = SWZ128((np * 16 + rb) * 128 + (kt * 2 + chi) * 16);
    }

    // Load Q tile (hi+lo)
    for (int it = tid; it < 1024; it += 256) {
        int row = it >> 3, c = it & 7;
        size_t goff = (size_t)row * DMODEL + c * 8;
        uint32_t soff = SWZ128(row * 128 + c * 16);
        *(float4*)(sQh + soff) = *(const float4*)(qhb + goff);
        *(float4*)(sQl + soff) = *(const float4*)(qlb + goff);
    }

    auto cpa_kv = [&](int j, int s) {
        const int k0 = j * 64;
        const uint32_t st = uKV + s * KV_STAGE;
#pragma unroll
        for (int i = 0; i < 2; i++) {
            int it = tid + i * 256;
            int row = it >> 3, c = it & 7;
            uint32_t soff = SWZ128(row * 128 + c * 16);
            CP_ASYNC16(st + 0 * AK_B + soff, khb + (size_t)(k0 + row) * DMODEL + c * 8);
            CP_ASYNC16(st + 1 * AK_B + soff, klb + (size_t)(k0 + row) * DMODEL + c * 8);
            CP_ASYNC16(st + 2 * AK_B + soff, vhb + (size_t)row * SEQ + k0 + c * 8);
            CP_ASYNC16(st + 3 * AK_B + soff, vlb + (size_t)row * SEQ + k0 + c * 8);
        }
    };

    float O[8][4];
#pragma unroll
    for (int nt = 0; nt < 8; nt++)
#pragma unroll
        for (int e = 0; e < 4; e++) O[nt][e] = 0.f;
    float m0 = -1e30f, m1 = -1e30f, l0 = 0.f, l1 = 0.f;

    const int jmax = 2 * qb + 1;
    const float scale = 0.125f;

    cpa_kv(0, 0); CP_COMMIT();

    for (int j = 0; j <= jmax; j++) {
        CP_WAIT(0);
        __syncthreads();
        if (j < jmax) { cpa_kv(j + 1, (j + 1) & 1); CP_COMMIT(); }

        const uint32_t uKh = uKV + (j & 1) * KV_STAGE;
        const uint32_t uKl = uKh + AK_B;
        const uint32_t uVh = uKh + 2 * AK_B;
        const uint32_t uVl = uKh + 3 * AK_B;
        const int k0 = j * 64;

        // ---- S = Q . K^T (3-pass)
        float S[8][4];
#pragma unroll
        for (int nt = 0; nt < 8; nt++)
#pragma unroll
            for (int e = 0; e < 4; e++) S[nt][e] = 0.f;

#pragma unroll
        for (int kt = 0; kt < 4; kt++) {
            uint32_t aH[4], aL[4];
            ldsm4(aH, uQh + offA[kt]);
            ldsm4(aL, uQl + offA[kt]);
            uint32_t bH[16], bL[16];
#pragma unroll
            for (int np = 0; np < 4; np++) {
                ldsm4(&bH[np * 4], uKh + offB[np][kt]);
                ldsm4(&bL[np * 4], uKl + offB[np][kt]);
            }
#pragma unroll
            for (int nt = 0; nt < 8; nt++) {
                uint32_t* ph = &bH[(nt >> 1) * 4 + (nt & 1) * 2];
                uint32_t* pl = &bL[(nt >> 1) * 4 + (nt & 1) * 2];
                mma16816(S[nt], aH, ph);
                mma16816(S[nt], aH, pl);
                mma16816(S[nt], aL, ph);
            }
        }

        // ---- scale + mask
        const bool masked = (j >= 2 * qb);
        const int qrow0 = q0loc + wid * 16 + g;
#pragma unroll
        for (int nt = 0; nt < 8; nt++) {
#pragma unroll
            for (int e = 0; e < 4; e++) {
                float s = S[nt][e] * scale;
                if (masked) {
                    int key = k0 + nt * 8 + t2 + (e & 1);
                    int qr  = qrow0 + ((e >> 1) * 8);
                    if (key > qr) s = -1e30f;
                }
                S[nt][e] = s;
            }
        }

        // ---- online softmax (rows g and g+8)
        float tm0 = -1e30f, tm1 = -1e30f;
#pragma unroll
        for (int nt = 0; nt < 8; nt++) {
            tm0 = fmaxf(tm0, fmaxf(S[nt][0], S[nt][1]));
            tm1 = fmaxf(tm1, fmaxf(S[nt][2], S[nt][3]));
        }
        tm0 = fmaxf(tm0, __shfl_xor_sync(0xffffffffu, tm0, 1));
        tm0 = fmaxf(tm0, __shfl_xor_sync(0xffffffffu, tm0, 2));
        tm1 = fmaxf(tm1, __shfl_xor_sync(0xffffffffu, tm1, 1));
        tm1 = fmaxf(tm1, __shfl_xor_sync(0xffffffffu, tm1, 2));
        float mn0 = fmaxf(m0, tm0), mn1 = fmaxf(m1, tm1);
        float al0 = __expf(m0 - mn0), al1 = __expf(m1 - mn1);
        float ls0 = 0.f, ls1 = 0.f;
#pragma unroll
        for (int nt = 0; nt < 8; nt++) {
            float p0 = __expf(S[nt][0] - mn0);
            float p1 = __expf(S[nt][1] - mn0);
            float p2 = __expf(S[nt][2] - mn1);
            float p3 = __expf(S[nt][3] - mn1);
            ls0 += p0 + p1; ls1 += p2 + p3;
            S[nt][0] = p0; S[nt][1] = p1; S[nt][2] = p2; S[nt][3] = p3;
        }
        ls0 += __shfl_xor_sync(0xffffffffu, ls0, 1);
        ls0 += __shfl_xor_sync(0xffffffffu, ls0, 2);
        ls1 += __shfl_xor_sync(0xffffffffu, ls1, 1);
        ls1 += __shfl_xor_sync(0xffffffffu, ls1, 2);
        l0 = l0 * al0 + ls0;  m0 = mn0;
        l1 = l1 * al1 + ls1;  m1 = mn1;
#pragma unroll
        for (int nt = 0; nt < 8; nt++) {
            O[nt][0] *= al0; O[nt][1] *= al0;
            O[nt][2] *= al1; O[nt][3] *= al1;
        }

        // ---- pack P hi/lo into A-fragments
        uint32_t pH[4][4], pL[4][4];
#pragma unroll
        for (int kc = 0; kc < 4; kc++) {
            float c00 = S[2 * kc][0],     c01 = S[2 * kc][1];
            float c02 = S[2 * kc][2],     c03 = S[2 * kc][3];
            float c10 = S[2 * kc + 1][0], c11 = S[2 * kc + 1][1];
            float c12 = S[2 * kc + 1][2], c13 = S[2 * kc + 1][3];
            pH[kc][0] = pack_h2(c00, c01);
            pH[kc][1] = pack_h2(c02, c03);
            pH[kc][2] = pack_h2(c10, c11);
            pH[kc][3] = pack_h2(c12, c13);
            __half2* t;
            t = (__half2*)&pH[kc][0];
            pL[kc][0] = pack_h2(c00 - __half2float(t->x), c01 - __half2float(t->y));
            t = (__half2*)&pH[kc][1];
            pL[kc][1] = pack_h2(c02 - __half2float(t->x), c03 - __half2float(t->y));
            t = (__half2*)&pH[kc][2];
            pL[kc][2] = pack_h2(c10 - __half2float(t->x), c11 - __half2float(t->y));
            t = (__half2*)&pH[kc][3];
            pL[kc][3] = pack_h2(c12 - __half2float(t->x), c13 - __half2float(t->y));
        }

        // ---- O += P . V  (3-pass)
#pragma unroll
        for (int kc = 0; kc < 4; kc++) {
            uint32_t vH[16], vL[16];
#pragma unroll
            for (int np = 0; np < 4; np++) {
                ldsm4(&vH[np * 4], uVh + offB[np][kc]);
                ldsm4(&vL[np * 4], uVl + offB[np][kc]);
            }
#pragma unroll
            for (int nt = 0; nt < 8; nt++) {
                uint32_t* bv = &vH[(nt >> 1) * 4 + (nt & 1) * 2];
                uint32_t* bw = &vL[(nt >> 1) * 4 + (nt & 1) * 2];
                mma16816(O[nt], pH[kc], bv);
                mma16816(O[nt], pH[kc], bw);
                mma16816(O[nt], pL[kc], bv);
            }
        }
    }

    // ---- epilogue: normalize, fp16, store (hi only)
    const float inv0 = 1.f / l0, inv1 = 1.f / l1;
    const int row0 = rowg + wid * 16 + g;
    const int row1 = row0 + 8;
#pragma unroll
    for (int nt = 0; nt < 8; nt++) {
        int col = h * HDIM + nt * 8 + t2;
        __half2 H0 = __floats2half2_rn(O[nt][0] * inv0, O[nt][1] * inv0);
        __half2 H1 = __floats2half2_rn(O[nt][2] * inv1, O[nt][3] * inv1);
        *(__half2*)(oh + (size_t)row0 * DMODEL + col) = H0;
        *(__half2*)(oh + (size_t)row1 * DMODEL + col) = H1;
    }
}

// ---------------------------------------------------------------------------
// Launch
// ---------------------------------------------------------------------------
extern "C" void kernel_launch(void* const* d_in, const int* in_sizes, int n_in,
                              void* d_out, int out_size)
{
    const float* x  = (const float*)d_in[0];
    const float* Wq = (const float*)d_in[1];
    const float* bq = (const float*)d_in[2];
    const float* Wk = (const float*)d_in[3];
    const float* bk = (const float*)d_in[4];
    const float* Wv = (const float*)d_in[5];
    const float* bv = (const float*)d_in[6];
    const float* Wo = (const float*)d_in[7];
    const float* bo = (const float*)d_in[8];
    float* out = (float*)d_out;

    __half *xh, *qh, *ql, *kh, *kl, *vth, *vtl, *ath, *wh, *wl;
    cudaGetSymbolAddress((void**)&xh,  g_xh);
    cudaGetSymbolAddress((void**)&qh,  g_qh);
    cudaGetSymbolAddress((void**)&ql,  g_ql);
    cudaGetSymbolAddress((void**)&kh,  g_kh);
    cudaGetSymbolAddress((void**)&kl,  g_kl);
    cudaGetSymbolAddress((void**)&vth, g_vth);
    cudaGetSymbolAddress((void**)&vtl, g_vtl);
    cudaGetSymbolAddress((void**)&ath, g_ath);
    cudaGetSymbolAddress((void**)&wh,  g_wh);
    cudaGetSymbolAddress((void**)&wl,  g_wl);

    const size_t WN = DMODEL * DMODEL;

    split_h<<<(MTOT * DMODEL / 4 + 255) / 256, 256>>>(x, xh, MTOT * DMODEL / 4);
    split_w4<<<dim3((WN / 4 + 255) / 256, 4), 256>>>(Wq, Wk, Wv, Wo, wh, wl);

    cudaFuncSetAttribute(gemm_hmma2, cudaFuncAttributeMaxDynamicSharedMemorySize, GEMM_SMEM);
    cudaFuncSetAttribute(attn_hmma, cudaFuncAttributeMaxDynamicSharedMemorySize, ATT_SMEM);

    // Batched Q/K/V projection GEMMs (one launch, grid.z = 3)
    GemmArgs3 qkv;
    qkv.g[0] = { xh, wh + 0 * WN, wl + 0 * WN, bq, nullptr, qh,  ql,  1 };
    qkv.g[1] = { xh, wh + 1 * WN, wl + 1 * WN, bk, nullptr, kh,  kl,  1 };
    qkv.g[2] = { xh, wh + 2 * WN, wl + 2 * WN, bv, nullptr, vth, vtl, 2 };
    gemm_hmma2<<<dim3(DMODEL / 128, MTOT / 128, 3), 256, GEMM_SMEM>>>(qkv);

    attn_hmma<<<dim3(SEQ / 128, BATCH * NHEADS), 256, ATT_SMEM>>>(qh, ql, kh, kl, vth, vtl, ath);

    GemmArgs3 oproj;
    oproj.g[0] = { ath, wh + 3 * WN, wl + 3 * WN, bo, out, nullptr, nullptr, 0 };
    oproj.g[1] = oproj.g[0];
    oproj.g[2] = oproj.g[0];
    gemm_hmma2<<<dim3(DMODEL / 128, MTOT / 128, 1), 256, GEMM_SMEM>>>(oproj);
}

// round 9
// speedup vs baseline: 11.0040x; 1.0130x over previous
#include <cuda_runtime.h>
#include <cuda_fp16.h>
#include <cstdint>
#include <math.h>

// Problem constants
#define BATCH   4
#define SEQ     2048
#define DMODEL  1024
#define NHEADS  16
#define HDIM    64
#define MTOT    (BATCH * SEQ)          // 8192 rows

// ---------------------------------------------------------------------------
// Scratch (static __device__ — no allocations allowed)
// ---------------------------------------------------------------------------
__device__ __half g_xh[MTOT * DMODEL];
__device__ __half g_qh[MTOT * DMODEL];
__device__ __half g_ql[MTOT * DMODEL];
__device__ __half g_kh[MTOT * DMODEL];
__device__ __half g_kl[MTOT * DMODEL];
__device__ __half g_vth[MTOT * DMODEL];   // [b*16+h][64 dims][2048 T]
__device__ __half g_vtl[MTOT * DMODEL];
__device__ __half g_ath[MTOT * DMODEL];
__device__ __half g_wh[4][DMODEL * DMODEL];
__device__ __half g_wl[4][DMODEL * DMODEL];

// ---------------------------------------------------------------------------
// mma.sync / ldmatrix / cp.async helpers (portable PTX, valid on plain sm_103)
// ---------------------------------------------------------------------------
__device__ __forceinline__ uint32_t smem_to_u32(const void* p) {
    uint32_t a;
    asm("{ .reg .u64 t; cvta.to.shared.u64 t, %1; cvt.u32.u64 %0, t; }" : "=r"(a) : "l"(p));
    return a;
}
__device__ __forceinline__ void ldsm4(uint32_t* d, uint32_t addr) {
    asm volatile("ldmatrix.sync.aligned.m8n8.x4.shared.b16 {%0,%1,%2,%3}, [%4];"
                 : "=r"(d[0]), "=r"(d[1]), "=r"(d[2]), "=r"(d[3]) : "r"(addr));
}
__device__ __forceinline__ void mma16816(float* c, const uint32_t* a, const uint32_t* b) {
    asm volatile("mma.sync.aligned.m16n8k16.row.col.f32.f16.f16.f32 "
                 "{%0,%1,%2,%3}, {%4,%5,%6,%7}, {%8,%9}, {%0,%1,%2,%3};"
                 : "+f"(c[0]), "+f"(c[1]), "+f"(c[2]), "+f"(c[3])
                 : "r"(a[0]), "r"(a[1]), "r"(a[2]), "r"(a[3]), "r"(b[0]), "r"(b[1]));
}
__device__ __forceinline__ uint32_t pack_h2(float a, float b) {
    __half2 t = __floats2half2_rn(a, b);
    return *reinterpret_cast<uint32_t*>(&t);
}
#define CP_ASYNC16(dst, src) \
    asm volatile("cp.async.cg.shared.global [%0], [%1], 16;" \
                 :: "r"(dst), "l"(__cvta_generic_to_global(src)) : "memory")
#define CP_COMMIT() asm volatile("cp.async.commit_group;" ::: "memory")
#define CP_WAIT(n)  asm volatile("cp.async.wait_group %0;" :: "n"(n) : "memory")

// SW64-style swizzle for 64B rows (GEMM tiles)
#define SWZ64(o) ((o) ^ (((o) >> 3) & 0x30))
// SW128-style swizzle for 128B rows (attention tiles)
#define SWZ128(o) ((o) ^ (((o) >> 3) & 0x70))

// ---------------------------------------------------------------------------
// fp16 splits
// ---------------------------------------------------------------------------
__global__ void split_h(const float* __restrict__ in, __half* __restrict__ hi, int n4)
{
    int i = blockIdx.x * blockDim.x + threadIdx.x;
    if (i >= n4) return;
    float4 x = ((const float4*)in)[i];
    ((__half2*)hi)[i * 2 + 0] = __floats2half2_rn(x.x, x.y);
    ((__half2*)hi)[i * 2 + 1] = __floats2half2_rn(x.z, x.w);
}

__global__ void split_w4(const float* __restrict__ w0, const float* __restrict__ w1,
                         const float* __restrict__ w2, const float* __restrict__ w3,
                         __half* __restrict__ hi, __half* __restrict__ lo)
{
    const int n4 = DMODEL * DMODEL / 4;
    int i = blockIdx.x * blockDim.x + threadIdx.x;
    if (i >= n4) return;
    int z = blockIdx.y;
    const float* src = (z == 0) ? w0 : (z == 1) ? w1 : (z == 2) ? w2 : w3;
    size_t base = (size_t)z * (DMODEL * DMODEL / 2);   // in __half2 units
    float4 x = ((const float4*)src)[i];
    __half2 h0 = __floats2half2_rn(x.x, x.y);
    __half2 h1 = __floats2half2_rn(x.z, x.w);
    ((__half2*)hi)[base + i * 2 + 0] = h0;
    ((__half2*)hi)[base + i * 2 + 1] = h1;
    __half2 l0 = __floats2half2_rn(x.x - __half2float(h0.x), x.y - __half2float(h0.y));
    __half2 l1 = __floats2half2_rn(x.z - __half2float(h1.x), x.w - __half2float(h1.y));
    ((__half2*)lo)[base + i * 2 + 0] = l0;
    ((__half2*)lo)[base + i * 2 + 1] = l1;
}

// ---------------------------------------------------------------------------
// HMMA fp16 2-pass GEMM (register-lean mma loop; B fragments streamed per-np)
// ---------------------------------------------------------------------------
#define BK 32
#define NCHUNK (DMODEL / BK)           // 32
#define TILE_BYTES (128 * 64)          // 8 KB
#define STAGE_BYTES (3 * TILE_BYTES)   // 24 KB
#define GEMM_SMEM (2 * STAGE_BYTES)    // 48 KB

struct GemmArgs {
    const __half* Ah;
    const __half* Bh;
    const __half* Bl;
    const float*  bias;
    float*        Cf;
    __half*       Ch;
    __half*       Cl;
    int           mode;
};
struct GemmArgs3 { GemmArgs g[3]; };

__global__ __launch_bounds__(256, 2)
void gemm_hmma2(GemmArgs3 A3)
{
    const GemmArgs ga = A3.g[blockIdx.z];
    extern __shared__ __align__(16) char smem[];
    const uint32_t smem_u = smem_to_u32(smem);

    const int tid  = threadIdx.x;
    const int wid  = tid >> 5;
    const int lane = tid & 31;
    const int wm   = wid & 1;
    const int wn   = wid >> 1;
    const int m0 = blockIdx.y * 128;
    const int n0 = blockIdx.x * 128;

    // Swizzle-constant addressing (64B rows): SWZ64 mask bits [5:4] come from
    // o bits [8:7] = row bits [2:1]  ->  mask = ((row>>1)&3)<<4
    const int rowA_l = (lane & 7) + ((lane >> 3) & 1) * 8;   // A frag row within 16
    const int chiA   = (lane >> 4) & 1;
    const int rbB_l  = (lane & 7) + ((lane >> 4) & 1) * 8;   // B frag row within 16
    const int chiB   = (lane >> 3) & 1;
    const uint32_t mA = (uint32_t)((rowA_l >> 1) & 3) << 4;
    const uint32_t mB = (uint32_t)((rbB_l >> 1) & 3) << 4;
    const uint32_t rowbaseA = (uint32_t)(wm * 64 + rowA_l) * 64;
    const uint32_t rowbaseB = (uint32_t)(wn * 32 + rbB_l) * 64;
    uint32_t colA[2], colB[2];
#pragma unroll
    for (int kt = 0; kt < 2; kt++) {
        colA[kt] = ((uint32_t)((kt * 2 + chiA) * 16)) ^ mA;
        colB[kt] = ((uint32_t)((kt * 2 + chiB) * 16)) ^ mB;
    }

    float acc[4][4][4];
#pragma unroll
    for (int mt = 0; mt < 4; mt++)
#pragma unroll
        for (int nt = 0; nt < 4; nt++)
#pragma unroll
            for (int e = 0; e < 4; e++) acc[mt][nt][e] = 0.f;

    const __half* srcs[3] = { ga.Ah, ga.Bh, ga.Bl };

    auto cpa = [&](int c, int s) {
        const int k0 = c * BK;
        const uint32_t st = smem_u + s * STAGE_BYTES;
#pragma unroll
        for (int t = 0; t < 3; t++) {
            const __half* src = srcs[t];
            const int r0 = (t == 0) ? m0 : n0;
#pragma unroll
            for (int i = 0; i < 2; i++) {
                int fid = tid + i * 256;
                int row = fid >> 2, cc = fid & 3;
                uint32_t dst = st + t * TILE_BYTES + SWZ64(row * 64 + cc * 16);
                CP_ASYNC16(dst, src + (size_t)(r0 + row) * DMODEL + k0 + cc * 8);
            }
        }
    };

    auto mma_chunk = [&](int s) {
        const uint32_t sb = smem_u + s * STAGE_BYTES;
#pragma unroll
        for (int kt = 0; kt < 2; kt++) {
            uint32_t a[4][4];
#pragma unroll
            for (int mt = 0; mt < 4; mt++)
                ldsm4(a[mt], sb + rowbaseA + mt * 1024 + colA[kt]);
#pragma unroll
            for (int np = 0; np < 2; np++) {
                uint32_t bh[4], bl[4];
                ldsm4(bh, sb + TILE_BYTES + rowbaseB + np * 1024 + colB[kt]);
                ldsm4(bl, sb + 2 * TILE_BYTES + rowbaseB + np * 1024 + colB[kt]);
#pragma unroll
                for (int mt = 0; mt < 4; mt++) {
                    mma16816(acc[mt][2 * np + 0], a[mt], &bh[0]);
                    mma16816(acc[mt][2 * np + 1], a[mt], &bh[2]);
                    mma16816(acc[mt][2 * np + 0], a[mt], &bl[0]);
                    mma16816(acc[mt][2 * np + 1], a[mt], &bl[2]);
                }
            }
        }
    };

    cpa(0, 0); CP_COMMIT();
    for (int c = 0; c < NCHUNK; c++) {
        if (c + 1 < NCHUNK) {
            cpa(c + 1, (c + 1) & 1); CP_COMMIT();
            CP_WAIT(1);
        } else {
            CP_WAIT(0);
        }
        __syncthreads();
        mma_chunk(c & 1);
        __syncthreads();
    }

    // Epilogue
    const int g  = lane >> 2;
    const int t2 = (lane & 3) * 2;
#pragma unroll
    for (int mt = 0; mt < 4; mt++) {
#pragma unroll
        for (int nt = 0; nt < 4; nt++) {
            int row = m0 + wm * 64 + mt * 16 + g;
            int col = n0 + wn * 32 + nt * 8 + t2;
            float2 b = *(const float2*)&ga.bias[col];
            float v0 = acc[mt][nt][0] + b.x;
            float v1 = acc[mt][nt][1] + b.y;
            float v2 = acc[mt][nt][2] + b.x;
            float v3 = acc[mt][nt][3] + b.y;
            if (ga.mode == 0) {
                float2 o0 = { v0, v1 }, o1 = { v2, v3 };
                *(float2*)&ga.Cf[(size_t)row * DMODEL + col] = o0;
                *(float2*)&ga.Cf[(size_t)(row + 8) * DMODEL + col] = o1;
            } else if (ga.mode == 1) {
                __half2 H0 = __floats2half2_rn(v0, v1);
                __half2 H1 = __floats2half2_rn(v2, v3);
                *(__half2*)(ga.Ch + (size_t)row * DMODEL + col) = H0;
                *(__half2*)(ga.Ch + (size_t)(row + 8) * DMODEL + col) = H1;
                __half2 L0 = __floats2half2_rn(v0 - __half2float(H0.x), v1 - __half2float(H0.y));
                __half2 L1 = __floats2half2_rn(v2 - __half2float(H1.x), v3 - __half2float(H1.y));
                *(__half2*)(ga.Cl + (size_t)row * DMODEL + col) = L0;
                *(__half2*)(ga.Cl + (size_t)(row + 8) * DMODEL + col) = L1;
            } else {
                // V transposed layout: idx = ((b*16+h)*64 + d)*2048 + t
#pragma unroll
                for (int e = 0; e < 4; e++) {
                    float v = (e == 0) ? v0 : (e == 1) ? v1 : (e == 2) ? v2 : v3;
                    int r = row + (e >= 2 ? 8 : 0);
                    int c = col + (e & 1);
                    int bb = r >> 11, t = r & 2047;
                    int hh = c >> 6, dl = c & 63;
                    size_t idx = ((size_t)((bb * 16 + hh) * 64 + dl)) * 2048 + t;
                    __half hv = __float2half_rn(v);
                    ga.Ch[idx] = hv;
                    ga.Cl[idx] = __float2half_rn(v - __half2float(hv));
                }
            }
        }
    }
}

// ---------------------------------------------------------------------------
// HMMA fp16 3-pass causal flash attention — register-lean version.
// Swizzle-constant addressing (SW128: mask = (row&7)<<4, row&7 == lane&7);
// two-pass S; transient P packing in PV.
// ---------------------------------------------------------------------------
#define AQ_B (128 * 128)               // 16 KB per Q tile
#define AK_B (64 * 128)                // 8 KB per K/V tile
#define KV_STAGE (4 * AK_B)            // 32 KB
#define ATT_SMEM (2 * AQ_B + 2 * KV_STAGE)   // 96 KB

__global__ __launch_bounds__(256, 2)
void attn_hmma(const __half* __restrict__ qh, const __half* __restrict__ ql,
               const __half* __restrict__ kh, const __half* __restrict__ kl,
               const __half* __restrict__ vth, const __half* __restrict__ vtl,
               __half* __restrict__ oh)
{
    extern __shared__ __align__(16) char smem[];
    const uint32_t smem_u = smem_to_u32(smem);
    char* sQh = smem;
    char* sQl = sQh + AQ_B;
    const uint32_t uQh = smem_u;
    const uint32_t uQl = uQh + AQ_B;
    const uint32_t uKV = uQl + AQ_B;

    const int tid  = threadIdx.x;
    const int wid  = tid >> 5;
    const int lane = tid & 31;
    const int g    = lane >> 2;
    const int t2   = (lane & 3) * 2;

    const int qb = (gridDim.x - 1) - blockIdx.x;   // heavy CTAs first
    const int bh = blockIdx.y;
    const int b  = bh >> 4;
    const int h  = bh & 15;

    const int q0loc  = qb * 128;
    const int rowg   = b * SEQ + q0loc;
    const __half* qhb = qh + (size_t)rowg * DMODEL + h * HDIM;
    const __half* qlb = ql + (size_t)rowg * DMODEL + h * HDIM;
    const __half* khb = kh + (size_t)(b * SEQ) * DMODEL + h * HDIM;
    const __half* klb = kl + (size_t)(b * SEQ) * DMODEL + h * HDIM;
    const __half* vhb = vth + (size_t)bh * 64 * SEQ;
    const __half* vlb = vtl + (size_t)bh * 64 * SEQ;

    const uint32_t mS = (uint32_t)(lane & 7) << 4;
    const int rowA_l = (lane & 7) + ((lane >> 3) & 1) * 8;
    const int chiA   = (lane >> 4) & 1;
    const int rbB_l  = (lane & 7) + ((lane >> 4) & 1) * 8;
    const int chiB   = (lane >> 3) & 1;
    const uint32_t rowbaseA = (uint32_t)(wid * 16 + rowA_l) * 128;
    const uint32_t rowbaseB = (uint32_t)rbB_l * 128;
    uint32_t colA[4], colB[4];
#pragma unroll
    for (int kt = 0; kt < 4; kt++) {
        colA[kt] = ((uint32_t)((kt * 2 + chiA) * 16)) ^ mS;
        colB[kt] = ((uint32_t)((kt * 2 + chiB) * 16)) ^ mS;
    }

    // Load Q tile (hi+lo)
    for (int it = tid; it < 1024; it += 256) {
        int row = it >> 3, c = it & 7;
        size_t goff = (size_t)row * DMODEL + c * 8;
        uint32_t soff = SWZ128(row * 128 + c * 16);
        *(float4*)(sQh + soff) = *(const float4*)(qhb + goff);
        *(float4*)(sQl + soff) = *(const float4*)(qlb + goff);
    }

    auto cpa_kv = [&](int j, int s) {
        const int k0 = j * 64;
        const uint32_t st = uKV + s * KV_STAGE;
#pragma unroll
        for (int i = 0; i < 2; i++) {
            int it = tid + i * 256;
            int row = it >> 3, c = it & 7;
            uint32_t soff = SWZ128(row * 128 + c * 16);
            CP_ASYNC16(st + 0 * AK_B + soff, khb + (size_t)(k0 + row) * DMODEL + c * 8);
            CP_ASYNC16(st + 1 * AK_B + soff, klb + (size_t)(k0 + row) * DMODEL + c * 8);
            CP_ASYNC16(st + 2 * AK_B + soff, vhb + (size_t)row * SEQ + k0 + c * 8);
            CP_ASYNC16(st + 3 * AK_B + soff, vlb + (size_t)row * SEQ + k0 + c * 8);
        }
    };

    float O[8][4];
#pragma unroll
    for (int nt = 0; nt < 8; nt++)
#pragma unroll
        for (int e = 0; e < 4; e++) O[nt][e] = 0.f;
    float m0 = -1e30f, m1 = -1e30f, l0 = 0.f, l1 = 0.f;

    const int jmax = 2 * qb + 1;
    const float scale = 0.125f;

    cpa_kv(0, 0); CP_COMMIT();

    for (int j = 0; j <= jmax; j++) {
        CP_WAIT(0);
        __syncthreads();
        if (j < jmax) { cpa_kv(j + 1, (j + 1) & 1); CP_COMMIT(); }

        const uint32_t uKh = uKV + (j & 1) * KV_STAGE;
        const uint32_t uKl = uKh + AK_B;
        const uint32_t uVh = uKh + 2 * AK_B;
        const uint32_t uVl = uKh + 3 * AK_B;
        const int k0 = j * 64;

        // ---- S = Q . K^T: pass A (Qh·Kh + Ql·Kh), pass B (Qh·Kl)
        float S[8][4];
#pragma unroll
        for (int nt = 0; nt < 8; nt++)
#pragma unroll
            for (int e = 0; e < 4; e++) S[nt][e] = 0.f;

#pragma unroll
        for (int kt = 0; kt < 4; kt++) {
            uint32_t aH[4], aL[4];
            ldsm4(aH, uQh + rowbaseA + colA[kt]);
            ldsm4(aL, uQl + rowbaseA + colA[kt]);
#pragma unroll
            for (int np = 0; np < 4; np++) {
                uint32_t bf[4];
                ldsm4(bf, uKh + rowbaseB + np * 2048 + colB[kt]);
                mma16816(S[2 * np + 0], aH, &bf[0]);
                mma16816(S[2 * np + 1], aH, &bf[2]);
                mma16816(S[2 * np + 0], aL, &bf[0]);
                mma16816(S[2 * np + 1], aL, &bf[2]);
            }
        }
#pragma unroll
        for (int kt = 0; kt < 4; kt++) {
            uint32_t aH[4];
            ldsm4(aH, uQh + rowbaseA + colA[kt]);
#pragma unroll
            for (int np = 0; np < 4; np++) {
                uint32_t bf[4];
                ldsm4(bf, uKl + rowbaseB + np * 2048 + colB[kt]);
                mma16816(S[2 * np + 0], aH, &bf[0]);
                mma16816(S[2 * np + 1], aH, &bf[2]);
            }
        }

        // ---- scale + mask
        const bool masked = (j >= 2 * qb);
        const int qrow0 = q0loc + wid * 16 + g;
#pragma unroll
        for (int nt = 0; nt < 8; nt++) {
#pragma unroll
            for (int e = 0; e < 4; e++) {
                float s = S[nt][e] * scale;
                if (masked) {
                    int key = k0 + nt * 8 + t2 + (e & 1);
                    int qr  = qrow0 + ((e >> 1) * 8);
                    if (key > qr) s = -1e30f;
                }
                S[nt][e] = s;
            }
        }

        // ---- online softmax (rows g and g+8)
        float tm0 = -1e30f, tm1 = -1e30f;
#pragma unroll
        for (int nt = 0; nt < 8; nt++) {
            tm0 = fmaxf(tm0, fmaxf(S[nt][0], S[nt][1]));
            tm1 = fmaxf(tm1, fmaxf(S[nt][2], S[nt][3]));
        }
        tm0 = fmaxf(tm0, __shfl_xor_sync(0xffffffffu, tm0, 1));
        tm0 = fmaxf(tm0, __shfl_xor_sync(0xffffffffu, tm0, 2));
        tm1 = fmaxf(tm1, __shfl_xor_sync(0xffffffffu, tm1, 1));
        tm1 = fmaxf(tm1, __shfl_xor_sync(0xffffffffu, tm1, 2));
        float mn0 = fmaxf(m0, tm0), mn1 = fmaxf(m1, tm1);
        float al0 = __expf(m0 - mn0), al1 = __expf(m1 - mn1);
        float ls0 = 0.f, ls1 = 0.f;
#pragma unroll
        for (int nt = 0; nt < 8; nt++) {
            float p0 = __expf(S[nt][0] - mn0);
            float p1 = __expf(S[nt][1] - mn0);
            float p2 = __expf(S[nt][2] - mn1);
            float p3 = __expf(S[nt][3] - mn1);
            ls0 += p0 + p1; ls1 += p2 + p3;
            S[nt][0] = p0; S[nt][1] = p1; S[nt][2] = p2; S[nt][3] = p3;
        }
        ls0 += __shfl_xor_sync(0xffffffffu, ls0, 1);
        ls0 += __shfl_xor_sync(0xffffffffu, ls0, 2);
        ls1 += __shfl_xor_sync(0xffffffffu, ls1, 1);
        ls1 += __shfl_xor_sync(0xffffffffu, ls1, 2);
        l0 = l0 * al0 + ls0;  m0 = mn0;
        l1 = l1 * al1 + ls1;  m1 = mn1;
#pragma unroll
        for (int nt = 0; nt < 8; nt++) {
            O[nt][0] *= al0; O[nt][1] *= al0;
            O[nt][2] *= al1; O[nt][3] *= al1;
        }

        // ---- O += P . V  (3-pass; P packed transiently per k16-chunk)
#pragma unroll
        for (int kc = 0; kc < 4; kc++) {
            uint32_t pH[4], pL[4];
            {
                float c00 = S[2 * kc][0],     c01 = S[2 * kc][1];
                float c02 = S[2 * kc][2],     c03 = S[2 * kc][3];
                float c10 = S[2 * kc + 1][0], c11 = S[2 * kc + 1][1];
                float c12 = S[2 * kc + 1][2], c13 = S[2 * kc + 1][3];
                pH[0] = pack_h2(c00, c01);
                pH[1] = pack_h2(c02, c03);
                pH[2] = pack_h2(c10, c11);
                pH[3] = pack_h2(c12, c13);
                __half2* t;
                t = (__half2*)&pH[0];
                pL[0] = pack_h2(c00 - __half2float(t->x), c01 - __half2float(t->y));
                t = (__half2*)&pH[1];
                pL[1] = pack_h2(c02 - __half2float(t->x), c03 - __half2float(t->y));
                t = (__half2*)&pH[2];
                pL[2] = pack_h2(c10 - __half2float(t->x), c11 - __half2float(t->y));
                t = (__half2*)&pH[3];
                pL[3] = pack_h2(c12 - __half2float(t->x), c13 - __half2float(t->y));
            }
#pragma unroll
            for (int np = 0; np < 4; np++) {
                uint32_t vH[4], vL[4];
                ldsm4(vH, uVh + rowbaseB + np * 2048 + colB[kc]);
                ldsm4(vL, uVl + rowbaseB + np * 2048 + colB[kc]);
                mma16816(O[2 * np + 0], pH, &vH[0]);
                mma16816(O[2 * np + 1], pH, &vH[2]);
                mma16816(O[2 * np + 0], pH, &vL[0]);
                mma16816(O[2 * np + 1], pH, &vL[2]);
                mma16816(O[2 * np + 0], pL, &vH[0]);
                mma16816(O[2 * np + 1], pL, &vH[2]);
            }
        }
    }

    // ---- epilogue: normalize, fp16, store (hi only)
    const float inv0 = 1.f / l0, inv1 = 1.f / l1;
    const int row0 = rowg + wid * 16 + g;
    const int row1 = row0 + 8;
#pragma unroll
    for (int nt = 0; nt < 8; nt++) {
        int col = h * HDIM + nt * 8 + t2;
        __half2 H0 = __floats2half2_rn(O[nt][0] * inv0, O[nt][1] * inv0);
        __half2 H1 = __floats2half2_rn(O[nt][2] * inv1, O[nt][3] * inv1);
        *(__half2*)(oh + (size_t)row0 * DMODEL + col) = H0;
        *(__half2*)(oh + (size_t)row1 * DMODEL + col) = H1;
    }
}

// ---------------------------------------------------------------------------
// Launch
// ---------------------------------------------------------------------------
extern "C" void kernel_launch(void* const* d_in, const int* in_sizes, int n_in,
                              void* d_out, int out_size)
{
    const float* x  = (const float*)d_in[0];
    const float* Wq = (const float*)d_in[1];
    const float* bq = (const float*)d_in[2];
    const float* Wk = (const float*)d_in[3];
    const float* bk = (const float*)d_in[4];
    const float* Wv = (const float*)d_in[5];
    const float* bv = (const float*)d_in[6];
    const float* Wo = (const float*)d_in[7];
    const float* bo = (const float*)d_in[8];
    float* out = (float*)d_out;

    __half *xh, *qh, *ql, *kh, *kl, *vth, *vtl, *ath, *wh, *wl;
    cudaGetSymbolAddress((void**)&xh,  g_xh);
    cudaGetSymbolAddress((void**)&qh,  g_qh);
    cudaGetSymbolAddress((void**)&ql,  g_ql);
    cudaGetSymbolAddress((void**)&kh,  g_kh);
    cudaGetSymbolAddress((void**)&kl,  g_kl);
    cudaGetSymbolAddress((void**)&vth, g_vth);
    cudaGetSymbolAddress((void**)&vtl, g_vtl);
    cudaGetSymbolAddress((void**)&ath, g_ath);
    cudaGetSymbolAddress((void**)&wh,  g_wh);
    cudaGetSymbolAddress((void**)&wl,  g_wl);

    const size_t WN = DMODEL * DMODEL;

    split_h<<<(MTOT * DMODEL / 4 + 255) / 256, 256>>>(x, xh, MTOT * DMODEL / 4);
    split_w4<<<dim3((WN / 4 + 255) / 256, 4), 256>>>(Wq, Wk, Wv, Wo, wh, wl);

    cudaFuncSetAttribute(gemm_hmma2, cudaFuncAttributeMaxDynamicSharedMemorySize, GEMM_SMEM);
    cudaFuncSetAttribute(attn_hmma, cudaFuncAttributeMaxDynamicSharedMemorySize, ATT_SMEM);

    GemmArgs3 qkv;
    qkv.g[0] = { xh, wh + 0 * WN, wl + 0 * WN, bq, nullptr, qh,  ql,  1 };
    qkv.g[1] = { xh, wh + 1 * WN, wl + 1 * WN, bk, nullptr, kh,  kl,  1 };
    qkv.g[2] = { xh, wh + 2 * WN, wl + 2 * WN, bv, nullptr, vth, vtl, 2 };
    gemm_hmma2<<<dim3(DMODEL / 128, MTOT / 128, 3), 256, GEMM_SMEM>>>(qkv);

    attn_hmma<<<dim3(SEQ / 128, BATCH * NHEADS), 256, ATT_SMEM>>>(qh, ql, kh, kl, vth, vtl, ath);

    GemmArgs3 oproj;
    oproj.g[0] = { ath, wh + 3 * WN, wl + 3 * WN, bo, out, nullptr, nullptr, 0 };
    oproj.g[1] = oproj.g[0];
    oproj.g[2] = oproj.g[0];
    gemm_hmma2<<<dim3(DMODEL / 128, MTOT / 128, 1), 256, GEMM_SMEM>>>(oproj);
}

// round 10
// speedup vs baseline: 12.8166x; 1.1647x over previous
#include <cuda_runtime.h>
#include <cuda_fp16.h>
#include <cstdint>
#include <math.h>

// Problem constants
#define BATCH   4
#define SEQ     2048
#define DMODEL  1024
#define NHEADS  16
#define HDIM    64
#define MTOT    (BATCH * SEQ)          // 8192 rows

// ---------------------------------------------------------------------------
// Scratch (static __device__ — no allocations allowed)
// ---------------------------------------------------------------------------
__device__ __half g_xh[MTOT * DMODEL];
__device__ __half g_qh[MTOT * DMODEL];
__device__ __half g_kh[MTOT * DMODEL];
__device__ __half g_kl[MTOT * DMODEL];
__device__ __half g_vth[MTOT * DMODEL];   // [b*16+h][64 dims][2048 T]
__device__ __half g_vtl[MTOT * DMODEL];
__device__ __half g_ath[MTOT * DMODEL];
__device__ __half g_wh[4][DMODEL * DMODEL];
__device__ __half g_wl[4][DMODEL * DMODEL];

// ---------------------------------------------------------------------------
// mma.sync / ldmatrix / cp.async helpers (portable PTX, valid on plain sm_103)
// ---------------------------------------------------------------------------
__device__ __forceinline__ uint32_t smem_to_u32(const void* p) {
    uint32_t a;
    asm("{ .reg .u64 t; cvta.to.shared.u64 t, %1; cvt.u32.u64 %0, t; }" : "=r"(a) : "l"(p));
    return a;
}
__device__ __forceinline__ void ldsm4(uint32_t* d, uint32_t addr) {
    asm volatile("ldmatrix.sync.aligned.m8n8.x4.shared.b16 {%0,%1,%2,%3}, [%4];"
                 : "=r"(d[0]), "=r"(d[1]), "=r"(d[2]), "=r"(d[3]) : "r"(addr));
}
__device__ __forceinline__ void mma16816(float* c, const uint32_t* a, const uint32_t* b) {
    asm volatile("mma.sync.aligned.m16n8k16.row.col.f32.f16.f16.f32 "
                 "{%0,%1,%2,%3}, {%4,%5,%6,%7}, {%8,%9}, {%0,%1,%2,%3};"
                 : "+f"(c[0]), "+f"(c[1]), "+f"(c[2]), "+f"(c[3])
                 : "r"(a[0]), "r"(a[1]), "r"(a[2]), "r"(a[3]), "r"(b[0]), "r"(b[1]));
}
__device__ __forceinline__ uint32_t pack_h2(float a, float b) {
    __half2 t = __floats2half2_rn(a, b);
    return *reinterpret_cast<uint32_t*>(&t);
}
#define CP_ASYNC16(dst, src) \
    asm volatile("cp.async.cg.shared.global [%0], [%1], 16;" \
                 :: "r"(dst), "l"(__cvta_generic_to_global(src)) : "memory")
#define CP_COMMIT() asm volatile("cp.async.commit_group;" ::: "memory")
#define CP_WAIT(n)  asm volatile("cp.async.wait_group %0;" :: "n"(n) : "memory")

// SW64-style swizzle for 64B rows (GEMM tiles)
#define SWZ64(o) ((o) ^ (((o) >> 3) & 0x30))
// SW128-style swizzle for 128B rows (attention tiles)
#define SWZ128(o) ((o) ^ (((o) >> 3) & 0x70))

// ---------------------------------------------------------------------------
// fp16 splits
// ---------------------------------------------------------------------------
__global__ void split_h(const float* __restrict__ in, __half* __restrict__ hi, int n4)
{
    int i = blockIdx.x * blockDim.x + threadIdx.x;
    if (i >= n4) return;
    float4 x = ((const float4*)in)[i];
    ((__half2*)hi)[i * 2 + 0] = __floats2half2_rn(x.x, x.y);
    ((__half2*)hi)[i * 2 + 1] = __floats2half2_rn(x.z, x.w);
}

__global__ void split_w4(const float* __restrict__ w0, const float* __restrict__ w1,
                         const float* __restrict__ w2, const float* __restrict__ w3,
                         __half* __restrict__ hi, __half* __restrict__ lo)
{
    const int n4 = DMODEL * DMODEL / 4;
    int i = blockIdx.x * blockDim.x + threadIdx.x;
    if (i >= n4) return;
    int z = blockIdx.y;
    const float* src = (z == 0) ? w0 : (z == 1) ? w1 : (z == 2) ? w2 : w3;
    size_t base = (size_t)z * (DMODEL * DMODEL / 2);   // in __half2 units
    float4 x = ((const float4*)src)[i];
    __half2 h0 = __floats2half2_rn(x.x, x.y);
    __half2 h1 = __floats2half2_rn(x.z, x.w);
    ((__half2*)hi)[base + i * 2 + 0] = h0;
    ((__half2*)hi)[base + i * 2 + 1] = h1;
    __half2 l0 = __floats2half2_rn(x.x - __half2float(h0.x), x.y - __half2float(h0.y));
    __half2 l1 = __floats2half2_rn(x.z - __half2float(h1.x), x.w - __half2float(h1.y));
    ((__half2*)lo)[base + i * 2 + 0] = l0;
    ((__half2*)lo)[base + i * 2 + 1] = l1;
}

// ---------------------------------------------------------------------------
// HMMA fp16 2-pass GEMM (register-lean mma loop; B fragments streamed per-np)
// ---------------------------------------------------------------------------
#define BK 32
#define NCHUNK (DMODEL / BK)           // 32
#define TILE_BYTES (128 * 64)          // 8 KB
#define STAGE_BYTES (3 * TILE_BYTES)   // 24 KB
#define GEMM_SMEM (2 * STAGE_BYTES)    // 48 KB

struct GemmArgs {
    const __half* Ah;
    const __half* Bh;
    const __half* Bl;
    const float*  bias;
    float*        Cf;
    __half*       Ch;
    __half*       Cl;
    int           mode;
};
struct GemmArgs3 { GemmArgs g[3]; };

__global__ __launch_bounds__(256, 2)
void gemm_hmma2(GemmArgs3 A3)
{
    const GemmArgs ga = A3.g[blockIdx.z];
    extern __shared__ __align__(16) char smem[];
    const uint32_t smem_u = smem_to_u32(smem);

    const int tid  = threadIdx.x;
    const int wid  = tid >> 5;
    const int lane = tid & 31;
    const int wm   = wid & 1;
    const int wn   = wid >> 1;
    const int m0 = blockIdx.y * 128;
    const int n0 = blockIdx.x * 128;

    // SWZ64 mask bits [5:4] = o bits [8:7] = row bits [2:1]
    const int rowA_l = (lane & 7) + ((lane >> 3) & 1) * 8;
    const int chiA   = (lane >> 4) & 1;
    const int rbB_l  = (lane & 7) + ((lane >> 4) & 1) * 8;
    const int chiB   = (lane >> 3) & 1;
    const uint32_t mA = (uint32_t)((rowA_l >> 1) & 3) << 4;
    const uint32_t mB = (uint32_t)((rbB_l >> 1) & 3) << 4;
    const uint32_t rowbaseA = (uint32_t)(wm * 64 + rowA_l) * 64;
    const uint32_t rowbaseB = (uint32_t)(wn * 32 + rbB_l) * 64;
    uint32_t colA[2], colB[2];
#pragma unroll
    for (int kt = 0; kt < 2; kt++) {
        colA[kt] = ((uint32_t)((kt * 2 + chiA) * 16)) ^ mA;
        colB[kt] = ((uint32_t)((kt * 2 + chiB) * 16)) ^ mB;
    }

    float acc[4][4][4];
#pragma unroll
    for (int mt = 0; mt < 4; mt++)
#pragma unroll
        for (int nt = 0; nt < 4; nt++)
#pragma unroll
            for (int e = 0; e < 4; e++) acc[mt][nt][e] = 0.f;

    const __half* srcs[3] = { ga.Ah, ga.Bh, ga.Bl };

    auto cpa = [&](int c, int s) {
        const int k0 = c * BK;
        const uint32_t st = smem_u + s * STAGE_BYTES;
#pragma unroll
        for (int t = 0; t < 3; t++) {
            const __half* src = srcs[t];
            const int r0 = (t == 0) ? m0 : n0;
#pragma unroll
            for (int i = 0; i < 2; i++) {
                int fid = tid + i * 256;
                int row = fid >> 2, cc = fid & 3;
                uint32_t dst = st + t * TILE_BYTES + SWZ64(row * 64 + cc * 16);
                CP_ASYNC16(dst, src + (size_t)(r0 + row) * DMODEL + k0 + cc * 8);
            }
        }
    };

    auto mma_chunk = [&](int s) {
        const uint32_t sb = smem_u + s * STAGE_BYTES;
#pragma unroll
        for (int kt = 0; kt < 2; kt++) {
            uint32_t a[4][4];
#pragma unroll
            for (int mt = 0; mt < 4; mt++)
                ldsm4(a[mt], sb + rowbaseA + mt * 1024 + colA[kt]);
#pragma unroll
            for (int np = 0; np < 2; np++) {
                uint32_t bh[4], bl[4];
                ldsm4(bh, sb + TILE_BYTES + rowbaseB + np * 1024 + colB[kt]);
                ldsm4(bl, sb + 2 * TILE_BYTES + rowbaseB + np * 1024 + colB[kt]);
#pragma unroll
                for (int mt = 0; mt < 4; mt++) {
                    mma16816(acc[mt][2 * np + 0], a[mt], &bh[0]);
                    mma16816(acc[mt][2 * np + 1], a[mt], &bh[2]);
                    mma16816(acc[mt][2 * np + 0], a[mt], &bl[0]);
                    mma16816(acc[mt][2 * np + 1], a[mt], &bl[2]);
                }
            }
        }
    };

    cpa(0, 0); CP_COMMIT();
    for (int c = 0; c < NCHUNK; c++) {
        if (c + 1 < NCHUNK) {
            cpa(c + 1, (c + 1) & 1); CP_COMMIT();
            CP_WAIT(1);
        } else {
            CP_WAIT(0);
        }
        __syncthreads();
        mma_chunk(c & 1);
        __syncthreads();
    }

    // Epilogue: mode 0 = fp32; 1 = fp16 hi/lo rows; 2 = hi/lo [b,h,d,T]; 3 = fp16 hi rows
    const int g  = lane >> 2;
    const int t2 = (lane & 3) * 2;
#pragma unroll
    for (int mt = 0; mt < 4; mt++) {
#pragma unroll
        for (int nt = 0; nt < 4; nt++) {
            int row = m0 + wm * 64 + mt * 16 + g;
            int col = n0 + wn * 32 + nt * 8 + t2;
            float2 b = *(const float2*)&ga.bias[col];
            float v0 = acc[mt][nt][0] + b.x;
            float v1 = acc[mt][nt][1] + b.y;
            float v2 = acc[mt][nt][2] + b.x;
            float v3 = acc[mt][nt][3] + b.y;
            if (ga.mode == 0) {
                float2 o0 = { v0, v1 }, o1 = { v2, v3 };
                *(float2*)&ga.Cf[(size_t)row * DMODEL + col] = o0;
                *(float2*)&ga.Cf[(size_t)(row + 8) * DMODEL + col] = o1;
            } else if (ga.mode == 1) {
                __half2 H0 = __floats2half2_rn(v0, v1);
                __half2 H1 = __floats2half2_rn(v2, v3);
                *(__half2*)(ga.Ch + (size_t)row * DMODEL + col) = H0;
                *(__half2*)(ga.Ch + (size_t)(row + 8) * DMODEL + col) = H1;
                __half2 L0 = __floats2half2_rn(v0 - __half2float(H0.x), v1 - __half2float(H0.y));
                __half2 L1 = __floats2half2_rn(v2 - __half2float(H1.x), v3 - __half2float(H1.y));
                *(__half2*)(ga.Cl + (size_t)row * DMODEL + col) = L0;
                *(__half2*)(ga.Cl + (size_t)(row + 8) * DMODEL + col) = L1;
            } else if (ga.mode == 3) {
                __half2 H0 = __floats2half2_rn(v0, v1);
                __half2 H1 = __floats2half2_rn(v2, v3);
                *(__half2*)(ga.Ch + (size_t)row * DMODEL + col) = H0;
                *(__half2*)(ga.Ch + (size_t)(row + 8) * DMODEL + col) = H1;
            } else {
                // V transposed layout: idx = ((b*16+h)*64 + d)*2048 + t
#pragma unroll
                for (int e = 0; e < 4; e++) {
                    float v = (e == 0) ? v0 : (e == 1) ? v1 : (e == 2) ? v2 : v3;
                    int r = row + (e >= 2 ? 8 : 0);
                    int c = col + (e & 1);
                    int bb = r >> 11, t = r & 2047;
                    int hh = c >> 6, dl = c & 63;
                    size_t idx = ((size_t)((bb * 16 + hh) * 64 + dl)) * 2048 + t;
                    __half hv = __float2half_rn(v);
                    ga.Ch[idx] = hv;
                    ga.Cl[idx] = __float2half_rn(v - __half2float(hv));
                }
            }
        }
    }
}

// ---------------------------------------------------------------------------
// HMMA fp16 2-pass causal flash attention.
// S = Qh·Kh + Qh·Kl   (Q residual dropped — K-side precision kept)
// O = Ph·Vh + Ph·Vl   (P residual dropped — V-side precision kept)
// fp32 accumulation throughout. Q tile hi only (16 KB); K/V hi+lo double-
// buffered (2 x 32 KB). 80 KB smem, 2 CTAs/SM.
// ---------------------------------------------------------------------------
#define AQ_B (128 * 128)               // 16 KB Q tile
#define AK_B (64 * 128)                // 8 KB per K/V tile
#define KV_STAGE (4 * AK_B)            // 32 KB
#define ATT_SMEM (AQ_B + 2 * KV_STAGE) // 80 KB

__global__ __launch_bounds__(256, 2)
void attn_hmma(const __half* __restrict__ qh,
               const __half* __restrict__ kh, const __half* __restrict__ kl,
               const __half* __restrict__ vth, const __half* __restrict__ vtl,
               __half* __restrict__ oh)
{
    extern __shared__ __align__(16) char smem[];
    const uint32_t smem_u = smem_to_u32(smem);
    char* sQh = smem;
    const uint32_t uQh = smem_u;
    const uint32_t uKV = uQh + AQ_B;

    const int tid  = threadIdx.x;
    const int wid  = tid >> 5;
    const int lane = tid & 31;
    const int g    = lane >> 2;
    const int t2   = (lane & 3) * 2;

    const int qb = (gridDim.x - 1) - blockIdx.x;   // heavy CTAs first
    const int bh = blockIdx.y;
    const int b  = bh >> 4;
    const int h  = bh & 15;

    const int q0loc  = qb * 128;
    const int rowg   = b * SEQ + q0loc;
    const __half* qhb = qh + (size_t)rowg * DMODEL + h * HDIM;
    const __half* khb = kh + (size_t)(b * SEQ) * DMODEL + h * HDIM;
    const __half* klb = kl + (size_t)(b * SEQ) * DMODEL + h * HDIM;
    const __half* vhb = vth + (size_t)bh * 64 * SEQ;
    const __half* vlb = vtl + (size_t)bh * 64 * SEQ;

    const uint32_t mS = (uint32_t)(lane & 7) << 4;
    const int rowA_l = (lane & 7) + ((lane >> 3) & 1) * 8;
    const int chiA   = (lane >> 4) & 1;
    const int rbB_l  = (lane & 7) + ((lane >> 4) & 1) * 8;
    const int chiB   = (lane >> 3) & 1;
    const uint32_t rowbaseA = (uint32_t)(wid * 16 + rowA_l) * 128;
    const uint32_t rowbaseB = (uint32_t)rbB_l * 128;
    uint32_t colA[4], colB[4];
#pragma unroll
    for (int kt = 0; kt < 4; kt++) {
        colA[kt] = ((uint32_t)((kt * 2 + chiA) * 16)) ^ mS;
        colB[kt] = ((uint32_t)((kt * 2 + chiB) * 16)) ^ mS;
    }

    // Load Q tile (hi only)
    for (int it = tid; it < 1024; it += 256) {
        int row = it >> 3, c = it & 7;
        uint32_t soff = SWZ128(row * 128 + c * 16);
        *(float4*)(sQh + soff) = *(const float4*)(qhb + (size_t)row * DMODEL + c * 8);
    }

    auto cpa_kv = [&](int j, int s) {
        const int k0 = j * 64;
        const uint32_t st = uKV + s * KV_STAGE;
#pragma unroll
        for (int i = 0; i < 2; i++) {
            int it = tid + i * 256;
            int row = it >> 3, c = it & 7;
            uint32_t soff = SWZ128(row * 128 + c * 16);
            CP_ASYNC16(st + 0 * AK_B + soff, khb + (size_t)(k0 + row) * DMODEL + c * 8);
            CP_ASYNC16(st + 1 * AK_B + soff, klb + (size_t)(k0 + row) * DMODEL + c * 8);
            CP_ASYNC16(st + 2 * AK_B + soff, vhb + (size_t)row * SEQ + k0 + c * 8);
            CP_ASYNC16(st + 3 * AK_B + soff, vlb + (size_t)row * SEQ + k0 + c * 8);
        }
    };

    float O[8][4];
#pragma unroll
    for (int nt = 0; nt < 8; nt++)
#pragma unroll
        for (int e = 0; e < 4; e++) O[nt][e] = 0.f;
    float m0 = -1e30f, m1 = -1e30f, l0 = 0.f, l1 = 0.f;

    const int jmax = 2 * qb + 1;
    const float scale = 0.125f;

    cpa_kv(0, 0); CP_COMMIT();

    for (int j = 0; j <= jmax; j++) {
        CP_WAIT(0);
        __syncthreads();
        if (j < jmax) { cpa_kv(j + 1, (j + 1) & 1); CP_COMMIT(); }

        const uint32_t uKh = uKV + (j & 1) * KV_STAGE;
        const uint32_t uKl = uKh + AK_B;
        const uint32_t uVh = uKh + 2 * AK_B;
        const uint32_t uVl = uKh + 3 * AK_B;
        const int k0 = j * 64;

        // ---- S = Qh·Kh + Qh·Kl
        float S[8][4];
#pragma unroll
        for (int nt = 0; nt < 8; nt++)
#pragma unroll
            for (int e = 0; e < 4; e++) S[nt][e] = 0.f;

#pragma unroll
        for (int kt = 0; kt < 4; kt++) {
            uint32_t aH[4];
            ldsm4(aH, uQh + rowbaseA + colA[kt]);
#pragma unroll
            for (int np = 0; np < 4; np++) {
                uint32_t bf[4];
                ldsm4(bf, uKh + rowbaseB + np * 2048 + colB[kt]);
                mma16816(S[2 * np + 0], aH, &bf[0]);
                mma16816(S[2 * np + 1], aH, &bf[2]);
                ldsm4(bf, uKl + rowbaseB + np * 2048 + colB[kt]);
                mma16816(S[2 * np + 0], aH, &bf[0]);
                mma16816(S[2 * np + 1], aH, &bf[2]);
            }
        }

        // ---- scale + mask
        const bool masked = (j >= 2 * qb);
        const int qrow0 = q0loc + wid * 16 + g;
#pragma unroll
        for (int nt = 0; nt < 8; nt++) {
#pragma unroll
            for (int e = 0; e < 4; e++) {
                float s = S[nt][e] * scale;
                if (masked) {
                    int key = k0 + nt * 8 + t2 + (e & 1);
                    int qr  = qrow0 + ((e >> 1) * 8);
                    if (key > qr) s = -1e30f;
                }
                S[nt][e] = s;
            }
        }

        // ---- online softmax (rows g and g+8)
        float tm0 = -1e30f, tm1 = -1e30f;
#pragma unroll
        for (int nt = 0; nt < 8; nt++) {
            tm0 = fmaxf(tm0, fmaxf(S[nt][0], S[nt][1]));
            tm1 = fmaxf(tm1, fmaxf(S[nt][2], S[nt][3]));
        }
        tm0 = fmaxf(tm0, __shfl_xor_sync(0xffffffffu, tm0, 1));
        tm0 = fmaxf(tm0, __shfl_xor_sync(0xffffffffu, tm0, 2));
        tm1 = fmaxf(tm1, __shfl_xor_sync(0xffffffffu, tm1, 1));
        tm1 = fmaxf(tm1, __shfl_xor_sync(0xffffffffu, tm1, 2));
        float mn0 = fmaxf(m0, tm0), mn1 = fmaxf(m1, tm1);
        float al0 = __expf(m0 - mn0), al1 = __expf(m1 - mn1);
        float ls0 = 0.f, ls1 = 0.f;
#pragma unroll
        for (int nt = 0; nt < 8; nt++) {
            float p0 = __expf(S[nt][0] - mn0);
            float p1 = __expf(S[nt][1] - mn0);
            float p2 = __expf(S[nt][2] - mn1);
            float p3 = __expf(S[nt][3] - mn1);
            ls0 += p0 + p1; ls1 += p2 + p3;
            S[nt][0] = p0; S[nt][1] = p1; S[nt][2] = p2; S[nt][3] = p3;
        }
        ls0 += __shfl_xor_sync(0xffffffffu, ls0, 1);
        ls0 += __shfl_xor_sync(0xffffffffu, ls0, 2);
        ls1 += __shfl_xor_sync(0xffffffffu, ls1, 1);
        ls1 += __shfl_xor_sync(0xffffffffu, ls1, 2);
        l0 = l0 * al0 + ls0;  m0 = mn0;
        l1 = l1 * al1 + ls1;  m1 = mn1;
#pragma unroll
        for (int nt = 0; nt < 8; nt++) {
            O[nt][0] *= al0; O[nt][1] *= al0;
            O[nt][2] *= al1; O[nt][3] *= al1;
        }

        // ---- O += Ph·Vh + Ph·Vl  (P packed transiently per k16-chunk)
#pragma unroll
        for (int kc = 0; kc < 4; kc++) {
            uint32_t pH[4];
            pH[0] = pack_h2(S[2 * kc][0],     S[2 * kc][1]);
            pH[1] = pack_h2(S[2 * kc][2],     S[2 * kc][3]);
            pH[2] = pack_h2(S[2 * kc + 1][0], S[2 * kc + 1][1]);
            pH[3] = pack_h2(S[2 * kc + 1][2], S[2 * kc + 1][3]);
#pragma unroll
            for (int np = 0; np < 4; np++) {
                uint32_t vf[4];
                ldsm4(vf, uVh + rowbaseB + np * 2048 + colB[kc]);
                mma16816(O[2 * np + 0], pH, &vf[0]);
                mma16816(O[2 * np + 1], pH, &vf[2]);
                ldsm4(vf, uVl + rowbaseB + np * 2048 + colB[kc]);
                mma16816(O[2 * np + 0], pH, &vf[0]);
                mma16816(O[2 * np + 1], pH, &vf[2]);
            }
        }
    }

    // ---- epilogue: normalize, fp16, store (hi only)
    const float inv0 = 1.f / l0, inv1 = 1.f / l1;
    const int row0 = rowg + wid * 16 + g;
    const int row1 = row0 + 8;
#pragma unroll
    for (int nt = 0; nt < 8; nt++) {
        int col = h * HDIM + nt * 8 + t2;
        __half2 H0 = __floats2half2_rn(O[nt][0] * inv0, O[nt][1] * inv0);
        __half2 H1 = __floats2half2_rn(O[nt][2] * inv1, O[nt][3] * inv1);
        *(__half2*)(oh + (size_t)row0 * DMODEL + col) = H0;
        *(__half2*)(oh + (size_t)row1 * DMODEL + col) = H1;
    }
}

// ---------------------------------------------------------------------------
// Launch
// ---------------------------------------------------------------------------
extern "C" void kernel_launch(void* const* d_in, const int* in_sizes, int n_in,
                              void* d_out, int out_size)
{
    const float* x  = (const float*)d_in[0];
    const float* Wq = (const float*)d_in[1];
    const float* bq = (const float*)d_in[2];
    const float* Wk = (const float*)d_in[3];
    const float* bk = (const float*)d_in[4];
    const float* Wv = (const float*)d_in[5];
    const float* bv = (const float*)d_in[6];
    const float* Wo = (const float*)d_in[7];
    const float* bo = (const float*)d_in[8];
    float* out = (float*)d_out;

    __half *xh, *qh, *kh, *kl, *vth, *vtl, *ath, *wh, *wl;
    cudaGetSymbolAddress((void**)&xh,  g_xh);
    cudaGetSymbolAddress((void**)&qh,  g_qh);
    cudaGetSymbolAddress((void**)&kh,  g_kh);
    cudaGetSymbolAddress((void**)&kl,  g_kl);
    cudaGetSymbolAddress((void**)&vth, g_vth);
    cudaGetSymbolAddress((void**)&vtl, g_vtl);
    cudaGetSymbolAddress((void**)&ath, g_ath);
    cudaGetSymbolAddress((void**)&wh,  g_wh);
    cudaGetSymbolAddress((void**)&wl,  g_wl);

    const size_t WN = DMODEL * DMODEL;

    split_h<<<(MTOT * DMODEL / 4 + 255) / 256, 256>>>(x, xh, MTOT * DMODEL / 4);
    split_w4<<<dim3((WN / 4 + 255) / 256, 4), 256>>>(Wq, Wk, Wv, Wo, wh, wl);

    cudaFuncSetAttribute(gemm_hmma2, cudaFuncAttributeMaxDynamicSharedMemorySize, GEMM_SMEM);
    cudaFuncSetAttribute(attn_hmma, cudaFuncAttributeMaxDynamicSharedMemorySize, ATT_SMEM);

    GemmArgs3 qkv;
    qkv.g[0] = { xh, wh + 0 * WN, wl + 0 * WN, bq, nullptr, qh,  nullptr, 3 };
    qkv.g[1] = { xh, wh + 1 * WN, wl + 1 * WN, bk, nullptr, kh,  kl,      1 };
    qkv.g[2] = { xh, wh + 2 * WN, wl + 2 * WN, bv, nullptr, vth, vtl,     2 };
    gemm_hmma2<<<dim3(DMODEL / 128, MTOT / 128, 3), 256, GEMM_SMEM>>>(qkv);

    attn_hmma<<<dim3(SEQ / 128, BATCH * NHEADS), 256, ATT_SMEM>>>(qh, kh, kl, vth, vtl, ath);

    GemmArgs3 oproj;
    oproj.g[0] = { ath, wh + 3 * WN, wl + 3 * WN, bo, out, nullptr, nullptr, 0 };
    oproj.g[1] = oproj.g[0];
    oproj.g[2] = oproj.g[0];
    gemm_hmma2<<<dim3(DMODEL / 128, MTOT / 128, 1), 256, GEMM_SMEM>>>(oproj);
}

// round 11
// speedup vs baseline: 13.2319x; 1.0324x over previous
#include <cuda_runtime.h>
#include <cuda_fp16.h>
#include <cstdint>
#include <math.h>

// Problem constants
#define BATCH   4
#define SEQ     2048
#define DMODEL  1024
#define NHEADS  16
#define HDIM    64
#define MTOT    (BATCH * SEQ)          // 8192 rows

// ---------------------------------------------------------------------------
// Scratch (static __device__ — no allocations allowed)
// ---------------------------------------------------------------------------
__device__ __half g_xh[MTOT * DMODEL];
__device__ __half g_qh[MTOT * DMODEL];
__device__ __half g_kh[MTOT * DMODEL];
__device__ __half g_kl[MTOT * DMODEL];
__device__ __half g_vth[MTOT * DMODEL];   // [b*16+h][64 dims][2048 T]
__device__ __half g_vtl[MTOT * DMODEL];
__device__ __half g_ath[MTOT * DMODEL];
__device__ __half g_wh[4][DMODEL * DMODEL];
__device__ __half g_wl[4][DMODEL * DMODEL];

// ---------------------------------------------------------------------------
// mma.sync / ldmatrix / cp.async helpers (portable PTX, valid on plain sm_103)
// ---------------------------------------------------------------------------
__device__ __forceinline__ uint32_t smem_to_u32(const void* p) {
    uint32_t a;
    asm("{ .reg .u64 t; cvta.to.shared.u64 t, %1; cvt.u32.u64 %0, t; }" : "=r"(a) : "l"(p));
    return a;
}
__device__ __forceinline__ void ldsm4(uint32_t* d, uint32_t addr) {
    asm volatile("ldmatrix.sync.aligned.m8n8.x4.shared.b16 {%0,%1,%2,%3}, [%4];"
                 : "=r"(d[0]), "=r"(d[1]), "=r"(d[2]), "=r"(d[3]) : "r"(addr));
}
__device__ __forceinline__ void mma16816(float* c, const uint32_t* a, const uint32_t* b) {
    asm volatile("mma.sync.aligned.m16n8k16.row.col.f32.f16.f16.f32 "
                 "{%0,%1,%2,%3}, {%4,%5,%6,%7}, {%8,%9}, {%0,%1,%2,%3};"
                 : "+f"(c[0]), "+f"(c[1]), "+f"(c[2]), "+f"(c[3])
                 : "r"(a[0]), "r"(a[1]), "r"(a[2]), "r"(a[3]), "r"(b[0]), "r"(b[1]));
}
__device__ __forceinline__ uint32_t pack_h2(float a, float b) {
    __half2 t = __floats2half2_rn(a, b);
    return *reinterpret_cast<uint32_t*>(&t);
}
#define CP_ASYNC16(dst, src) \
    asm volatile("cp.async.cg.shared.global [%0], [%1], 16;" \
                 :: "r"(dst), "l"(__cvta_generic_to_global(src)) : "memory")
#define CP_COMMIT() asm volatile("cp.async.commit_group;" ::: "memory")
#define CP_WAIT(n)  asm volatile("cp.async.wait_group %0;" :: "n"(n) : "memory")

// SW128-style swizzle for 128B rows (all tiles now)
#define SWZ128(o) ((o) ^ (((o) >> 3) & 0x70))

// scale (1/sqrt(64)) * log2(e) — folded into K at projection time
#define K_FOLD 0.18033688011112042f

// ---------------------------------------------------------------------------
// fp16 splits
// ---------------------------------------------------------------------------
__global__ void split_h(const float* __restrict__ in, __half* __restrict__ hi, int n4)
{
    int i = blockIdx.x * blockDim.x + threadIdx.x;
    if (i >= n4) return;
    float4 x = ((const float4*)in)[i];
    ((__half2*)hi)[i * 2 + 0] = __floats2half2_rn(x.x, x.y);
    ((__half2*)hi)[i * 2 + 1] = __floats2half2_rn(x.z, x.w);
}

__global__ void split_w4(const float* __restrict__ w0, const float* __restrict__ w1,
                         const float* __restrict__ w2, const float* __restrict__ w3,
                         __half* __restrict__ hi, __half* __restrict__ lo)
{
    const int n4 = DMODEL * DMODEL / 4;
    int i = blockIdx.x * blockDim.x + threadIdx.x;
    if (i >= n4) return;
    int z = blockIdx.y;
    const float* src = (z == 0) ? w0 : (z == 1) ? w1 : (z == 2) ? w2 : w3;
    size_t base = (size_t)z * (DMODEL * DMODEL / 2);   // in __half2 units
    float4 x = ((const float4*)src)[i];
    __half2 h0 = __floats2half2_rn(x.x, x.y);
    __half2 h1 = __floats2half2_rn(x.z, x.w);
    ((__half2*)hi)[base + i * 2 + 0] = h0;
    ((__half2*)hi)[base + i * 2 + 1] = h1;
    __half2 l0 = __floats2half2_rn(x.x - __half2float(h0.x), x.y - __half2float(h0.y));
    __half2 l1 = __floats2half2_rn(x.z - __half2float(h1.x), x.w - __half2float(h1.y));
    ((__half2*)lo)[base + i * 2 + 0] = l0;
    ((__half2*)lo)[base + i * 2 + 1] = l1;
}

// ---------------------------------------------------------------------------
// HMMA fp16 2-pass GEMM, BK=64 (16 chunks, half the barriers of BK=32).
// Chunk tiles are [rows][128B] SW128 — identical addressing to attention.
// ---------------------------------------------------------------------------
#define BK 64
#define NCHUNK (DMODEL / BK)           // 16
#define TILE_BYTES (128 * 128)         // 16 KB
#define STAGE_BYTES (3 * TILE_BYTES)   // 48 KB
#define GEMM_SMEM (2 * STAGE_BYTES)    // 96 KB

struct GemmArgs {
    const __half* Ah;
    const __half* Bh;
    const __half* Bl;
    const float*  bias;
    float*        Cf;
    __half*       Ch;
    __half*       Cl;
    int           mode;     // 0 fp32; 1 hi/lo rows; 2 hi/lo [b,h,d,T]; 3 hi rows
    float         cscale;   // output scale (K fold); 1.0 otherwise
};
struct GemmArgs3 { GemmArgs g[3]; };

__global__ __launch_bounds__(256, 2)
void gemm_hmma2(GemmArgs3 A3)
{
    const GemmArgs ga = A3.g[blockIdx.z];
    extern __shared__ __align__(16) char smem[];
    const uint32_t smem_u = smem_to_u32(smem);

    const int tid  = threadIdx.x;
    const int wid  = tid >> 5;
    const int lane = tid & 31;
    const int wm   = wid & 1;
    const int wn   = wid >> 1;
    const int m0 = blockIdx.y * 128;
    const int n0 = blockIdx.x * 128;

    // SW128 swizzle-constant addressing: mask = (row&7)<<4, row&7 == lane&7
    const uint32_t mS = (uint32_t)(lane & 7) << 4;
    const int rowA_l = (lane & 7) + ((lane >> 3) & 1) * 8;
    const int chiA   = (lane >> 4) & 1;
    const int rbB_l  = (lane & 7) + ((lane >> 4) & 1) * 8;
    const int chiB   = (lane >> 3) & 1;
    const uint32_t rowbaseA = (uint32_t)(wm * 64 + rowA_l) * 128;
    const uint32_t rowbaseB = (uint32_t)(wn * 32 + rbB_l) * 128;
    uint32_t colA[4], colB[4];
#pragma unroll
    for (int kt = 0; kt < 4; kt++) {
        colA[kt] = ((uint32_t)((kt * 2 + chiA) * 16)) ^ mS;
        colB[kt] = ((uint32_t)((kt * 2 + chiB) * 16)) ^ mS;
    }

    float acc[4][4][4];
#pragma unroll
    for (int mt = 0; mt < 4; mt++)
#pragma unroll
        for (int nt = 0; nt < 4; nt++)
#pragma unroll
            for (int e = 0; e < 4; e++) acc[mt][nt][e] = 0.f;

    const __half* srcs[3] = { ga.Ah, ga.Bh, ga.Bl };

    auto cpa = [&](int c, int s) {
        const int k0 = c * BK;
        const uint32_t st = smem_u + s * STAGE_BYTES;
#pragma unroll
        for (int t = 0; t < 3; t++) {
            const __half* src = srcs[t];
            const int r0 = (t == 0) ? m0 : n0;
#pragma unroll
            for (int i = 0; i < 4; i++) {
                int fid = tid + i * 256;
                int row = fid >> 3, cc = fid & 7;
                uint32_t dst = st + t * TILE_BYTES + SWZ128(row * 128 + cc * 16);
                CP_ASYNC16(dst, src + (size_t)(r0 + row) * DMODEL + k0 + cc * 8);
            }
        }
    };

    auto mma_chunk = [&](int s) {
        const uint32_t sb = smem_u + s * STAGE_BYTES;
#pragma unroll
        for (int kt = 0; kt < 4; kt++) {
            uint32_t a[4][4];
#pragma unroll
            for (int mt = 0; mt < 4; mt++)
                ldsm4(a[mt], sb + rowbaseA + mt * 2048 + colA[kt]);
#pragma unroll
            for (int np = 0; np < 2; np++) {
                uint32_t bh[4], bl[4];
                ldsm4(bh, sb + TILE_BYTES + rowbaseB + np * 2048 + colB[kt]);
                ldsm4(bl, sb + 2 * TILE_BYTES + rowbaseB + np * 2048 + colB[kt]);
#pragma unroll
                for (int mt = 0; mt < 4; mt++) {
                    mma16816(acc[mt][2 * np + 0], a[mt], &bh[0]);
                    mma16816(acc[mt][2 * np + 1], a[mt], &bh[2]);
                    mma16816(acc[mt][2 * np + 0], a[mt], &bl[0]);
                    mma16816(acc[mt][2 * np + 1], a[mt], &bl[2]);
                }
            }
        }
    };

    cpa(0, 0); CP_COMMIT();
    for (int c = 0; c < NCHUNK; c++) {
        if (c + 1 < NCHUNK) {
            cpa(c + 1, (c + 1) & 1); CP_COMMIT();
            CP_WAIT(1);
        } else {
            CP_WAIT(0);
        }
        __syncthreads();
        mma_chunk(c & 1);
        __syncthreads();
    }

    // Epilogue
    const int g  = lane >> 2;
    const int t2 = (lane & 3) * 2;
#pragma unroll
    for (int mt = 0; mt < 4; mt++) {
#pragma unroll
        for (int nt = 0; nt < 4; nt++) {
            int row = m0 + wm * 64 + mt * 16 + g;
            int col = n0 + wn * 32 + nt * 8 + t2;
            float2 b = *(const float2*)&ga.bias[col];
            float v0 = (acc[mt][nt][0] + b.x) * ga.cscale;
            float v1 = (acc[mt][nt][1] + b.y) * ga.cscale;
            float v2 = (acc[mt][nt][2] + b.x) * ga.cscale;
            float v3 = (acc[mt][nt][3] + b.y) * ga.cscale;
            if (ga.mode == 0) {
                float2 o0 = { v0, v1 }, o1 = { v2, v3 };
                *(float2*)&ga.Cf[(size_t)row * DMODEL + col] = o0;
                *(float2*)&ga.Cf[(size_t)(row + 8) * DMODEL + col] = o1;
            } else if (ga.mode == 1) {
                __half2 H0 = __floats2half2_rn(v0, v1);
                __half2 H1 = __floats2half2_rn(v2, v3);
                *(__half2*)(ga.Ch + (size_t)row * DMODEL + col) = H0;
                *(__half2*)(ga.Ch + (size_t)(row + 8) * DMODEL + col) = H1;
                __half2 L0 = __floats2half2_rn(v0 - __half2float(H0.x), v1 - __half2float(H0.y));
                __half2 L1 = __floats2half2_rn(v2 - __half2float(H1.x), v3 - __half2float(H1.y));
                *(__half2*)(ga.Cl + (size_t)row * DMODEL + col) = L0;
                *(__half2*)(ga.Cl + (size_t)(row + 8) * DMODEL + col) = L1;
            } else if (ga.mode == 3) {
                __half2 H0 = __floats2half2_rn(v0, v1);
                __half2 H1 = __floats2half2_rn(v2, v3);
                *(__half2*)(ga.Ch + (size_t)row * DMODEL + col) = H0;
                *(__half2*)(ga.Ch + (size_t)(row + 8) * DMODEL + col) = H1;
            } else {
                // V transposed layout: idx = ((b*16+h)*64 + d)*2048 + t
#pragma unroll
                for (int e = 0; e < 4; e++) {
                    float v = (e == 0) ? v0 : (e == 1) ? v1 : (e == 2) ? v2 : v3;
                    int r = row + (e >= 2 ? 8 : 0);
                    int c = col + (e & 1);
                    int bb = r >> 11, t = r & 2047;
                    int hh = c >> 6, dl = c & 63;
                    size_t idx = ((size_t)((bb * 16 + hh) * 64 + dl)) * 2048 + t;
                    __half hv = __float2half_rn(v);
                    ga.Ch[idx] = hv;
                    ga.Cl[idx] = __float2half_rn(v - __half2float(hv));
                }
            }
        }
    }
}

// ---------------------------------------------------------------------------
// HMMA fp16 2-pass causal flash attention (log2-domain softmax).
// K carries scale*log2e (folded at projection) -> S is the exp2 exponent.
// S = Qh·Kh + Qh·Kl ; O = Ph·Vh + Ph·Vl ; fp32 accumulation.
// ---------------------------------------------------------------------------
#define AQ_B (128 * 128)               // 16 KB Q tile
#define AK_B (64 * 128)                // 8 KB per K/V tile
#define KV_STAGE (4 * AK_B)            // 32 KB
#define ATT_SMEM (AQ_B + 2 * KV_STAGE) // 80 KB

__global__ __launch_bounds__(256, 2)
void attn_hmma(const __half* __restrict__ qh,
               const __half* __restrict__ kh, const __half* __restrict__ kl,
               const __half* __restrict__ vth, const __half* __restrict__ vtl,
               __half* __restrict__ oh)
{
    extern __shared__ __align__(16) char smem[];
    const uint32_t smem_u = smem_to_u32(smem);
    char* sQh = smem;
    const uint32_t uQh = smem_u;
    const uint32_t uKV = uQh + AQ_B;

    const int tid  = threadIdx.x;
    const int wid  = tid >> 5;
    const int lane = tid & 31;
    const int g    = lane >> 2;
    const int t2   = (lane & 3) * 2;

    const int qb = (gridDim.x - 1) - blockIdx.x;   // heavy CTAs first
    const int bh = blockIdx.y;
    const int b  = bh >> 4;
    const int h  = bh & 15;

    const int q0loc  = qb * 128;
    const int rowg   = b * SEQ + q0loc;
    const __half* qhb = qh + (size_t)rowg * DMODEL + h * HDIM;
    const __half* khb = kh + (size_t)(b * SEQ) * DMODEL + h * HDIM;
    const __half* klb = kl + (size_t)(b * SEQ) * DMODEL + h * HDIM;
    const __half* vhb = vth + (size_t)bh * 64 * SEQ;
    const __half* vlb = vtl + (size_t)bh * 64 * SEQ;

    const uint32_t mS = (uint32_t)(lane & 7) << 4;
    const int rowA_l = (lane & 7) + ((lane >> 3) & 1) * 8;
    const int chiA   = (lane >> 4) & 1;
    const int rbB_l  = (lane & 7) + ((lane >> 4) & 1) * 8;
    const int chiB   = (lane >> 3) & 1;
    const uint32_t rowbaseA = (uint32_t)(wid * 16 + rowA_l) * 128;
    const uint32_t rowbaseB = (uint32_t)rbB_l * 128;
    uint32_t colA[4], colB[4];
#pragma unroll
    for (int kt = 0; kt < 4; kt++) {
        colA[kt] = ((uint32_t)((kt * 2 + chiA) * 16)) ^ mS;
        colB[kt] = ((uint32_t)((kt * 2 + chiB) * 16)) ^ mS;
    }

    // Load Q tile (hi only)
    for (int it = tid; it < 1024; it += 256) {
        int row = it >> 3, c = it & 7;
        uint32_t soff = SWZ128(row * 128 + c * 16);
        *(float4*)(sQh + soff) = *(const float4*)(qhb + (size_t)row * DMODEL + c * 8);
    }

    auto cpa_kv = [&](int j, int s) {
        const int k0 = j * 64;
        const uint32_t st = uKV + s * KV_STAGE;
#pragma unroll
        for (int i = 0; i < 2; i++) {
            int it = tid + i * 256;
            int row = it >> 3, c = it & 7;
            uint32_t soff = SWZ128(row * 128 + c * 16);
            CP_ASYNC16(st + 0 * AK_B + soff, khb + (size_t)(k0 + row) * DMODEL + c * 8);
            CP_ASYNC16(st + 1 * AK_B + soff, klb + (size_t)(k0 + row) * DMODEL + c * 8);
            CP_ASYNC16(st + 2 * AK_B + soff, vhb + (size_t)row * SEQ + k0 + c * 8);
            CP_ASYNC16(st + 3 * AK_B + soff, vlb + (size_t)row * SEQ + k0 + c * 8);
        }
    };

    float O[8][4];
#pragma unroll
    for (int nt = 0; nt < 8; nt++)
#pragma unroll
        for (int e = 0; e < 4; e++) O[nt][e] = 0.f;
    float m0 = -1e30f, m1 = -1e30f, l0 = 0.f, l1 = 0.f;

    const int jmax = 2 * qb + 1;

    cpa_kv(0, 0); CP_COMMIT();

    for (int j = 0; j <= jmax; j++) {
        CP_WAIT(0);
        __syncthreads();
        if (j < jmax) { cpa_kv(j + 1, (j + 1) & 1); CP_COMMIT(); }

        const uint32_t uKh = uKV + (j & 1) * KV_STAGE;
        const uint32_t uKl = uKh + AK_B;
        const uint32_t uVh = uKh + 2 * AK_B;
        const uint32_t uVl = uKh + 3 * AK_B;
        const int k0 = j * 64;

        // ---- S = Qh·Kh + Qh·Kl  (log2-domain logits)
        float S[8][4];
#pragma unroll
        for (int nt = 0; nt < 8; nt++)
#pragma unroll
            for (int e = 0; e < 4; e++) S[nt][e] = 0.f;

#pragma unroll
        for (int kt = 0; kt < 4; kt++) {
            uint32_t aH[4];
            ldsm4(aH, uQh + rowbaseA + colA[kt]);
#pragma unroll
            for (int np = 0; np < 4; np++) {
                uint32_t bf[4];
                ldsm4(bf, uKh + rowbaseB + np * 2048 + colB[kt]);
                mma16816(S[2 * np + 0], aH, &bf[0]);
                mma16816(S[2 * np + 1], aH, &bf[2]);
                ldsm4(bf, uKl + rowbaseB + np * 2048 + colB[kt]);
                mma16816(S[2 * np + 0], aH, &bf[0]);
                mma16816(S[2 * np + 1], aH, &bf[2]);
            }
        }

        // ---- mask (diagonal tiles only)
        if (j >= 2 * qb) {
            const int qrow0 = q0loc + wid * 16 + g;
#pragma unroll
            for (int nt = 0; nt < 8; nt++) {
#pragma unroll
                for (int e = 0; e < 4; e++) {
                    int key = k0 + nt * 8 + t2 + (e & 1);
                    int qr  = qrow0 + ((e >> 1) * 8);
                    if (key > qr) S[nt][e] = -1e30f;
                }
            }
        }

        // ---- online softmax in log2 domain (rows g and g+8)
        float tm0 = -1e30f, tm1 = -1e30f;
#pragma unroll
        for (int nt = 0; nt < 8; nt++) {
            tm0 = fmaxf(tm0, fmaxf(S[nt][0], S[nt][1]));
            tm1 = fmaxf(tm1, fmaxf(S[nt][2], S[nt][3]));
        }
        tm0 = fmaxf(tm0, __shfl_xor_sync(0xffffffffu, tm0, 1));
        tm0 = fmaxf(tm0, __shfl_xor_sync(0xffffffffu, tm0, 2));
        tm1 = fmaxf(tm1, __shfl_xor_sync(0xffffffffu, tm1, 1));
        tm1 = fmaxf(tm1, __shfl_xor_sync(0xffffffffu, tm1, 2));
        float mn0 = fmaxf(m0, tm0), mn1 = fmaxf(m1, tm1);
        float al0 = exp2f(m0 - mn0), al1 = exp2f(m1 - mn1);
        float ls0 = 0.f, ls1 = 0.f;
#pragma unroll
        for (int nt = 0; nt < 8; nt++) {
            float p0 = exp2f(S[nt][0] - mn0);
            float p1 = exp2f(S[nt][1] - mn0);
            float p2 = exp2f(S[nt][2] - mn1);
            float p3 = exp2f(S[nt][3] - mn1);
            ls0 += p0 + p1; ls1 += p2 + p3;
            S[nt][0] = p0; S[nt][1] = p1; S[nt][2] = p2; S[nt][3] = p3;
        }
        ls0 += __shfl_xor_sync(0xffffffffu, ls0, 1);
        ls0 += __shfl_xor_sync(0xffffffffu, ls0, 2);
        ls1 += __shfl_xor_sync(0xffffffffu, ls1, 1);
        ls1 += __shfl_xor_sync(0xffffffffu, ls1, 2);
        l0 = l0 * al0 + ls0;  m0 = mn0;
        l1 = l1 * al1 + ls1;  m1 = mn1;
#pragma unroll
        for (int nt = 0; nt < 8; nt++) {
            O[nt][0] *= al0; O[nt][1] *= al0;
            O[nt][2] *= al1; O[nt][3] *= al1;
        }

        // ---- O += Ph·Vh + Ph·Vl  (P packed transiently per k16-chunk)
#pragma unroll
        for (int kc = 0; kc < 4; kc++) {
            uint32_t pH[4];
            pH[0] = pack_h2(S[2 * kc][0],     S[2 * kc][1]);
            pH[1] = pack_h2(S[2 * kc][2],     S[2 * kc][3]);
            pH[2] = pack_h2(S[2 * kc + 1][0], S[2 * kc + 1][1]);
            pH[3] = pack_h2(S[2 * kc + 1][2], S[2 * kc + 1][3]);
#pragma unroll
            for (int np = 0; np < 4; np++) {
                uint32_t vf[4];
                ldsm4(vf, uVh + rowbaseB + np * 2048 + colB[kc]);
                mma16816(O[2 * np + 0], pH, &vf[0]);
                mma16816(O[2 * np + 1], pH, &vf[2]);
                ldsm4(vf, uVl + rowbaseB + np * 2048 + colB[kc]);
                mma16816(O[2 * np + 0], pH, &vf[0]);
                mma16816(O[2 * np + 1], pH, &vf[2]);
            }
        }
    }

    // ---- epilogue: normalize, fp16, store (hi only)
    const float inv0 = 1.f / l0, inv1 = 1.f / l1;
    const int row0 = rowg + wid * 16 + g;
    const int row1 = row0 + 8;
#pragma unroll
    for (int nt = 0; nt < 8; nt++) {
        int col = h * HDIM + nt * 8 + t2;
        __half2 H0 = __floats2half2_rn(O[nt][0] * inv0, O[nt][1] * inv0);
        __half2 H1 = __floats2half2_rn(O[nt][2] * inv1, O[nt][3] * inv1);
        *(__half2*)(oh + (size_t)row0 * DMODEL + col) = H0;
        *(__half2*)(oh + (size_t)row1 * DMODEL + col) = H1;
    }
}

// ---------------------------------------------------------------------------
// Launch
// ---------------------------------------------------------------------------
extern "C" void kernel_launch(void* const* d_in, const int* in_sizes, int n_in,
                              void* d_out, int out_size)
{
    const float* x  = (const float*)d_in[0];
    const float* Wq = (const float*)d_in[1];
    const float* bq = (const float*)d_in[2];
    const float* Wk = (const float*)d_in[3];
    const float* bk = (const float*)d_in[4];
    const float* Wv = (const float*)d_in[5];
    const float* bv = (const float*)d_in[6];
    const float* Wo = (const float*)d_in[7];
    const float* bo = (const float*)d_in[8];
    float* out = (float*)d_out;

    __half *xh, *qh, *kh, *kl, *vth, *vtl, *ath, *wh, *wl;
    cudaGetSymbolAddress((void**)&xh,  g_xh);
    cudaGetSymbolAddress((void**)&qh,  g_qh);
    cudaGetSymbolAddress((void**)&kh,  g_kh);
    cudaGetSymbolAddress((void**)&kl,  g_kl);
    cudaGetSymbolAddress((void**)&vth, g_vth);
    cudaGetSymbolAddress((void**)&vtl, g_vtl);
    cudaGetSymbolAddress((void**)&ath, g_ath);
    cudaGetSymbolAddress((void**)&wh,  g_wh);
    cudaGetSymbolAddress((void**)&wl,  g_wl);

    const size_t WN = DMODEL * DMODEL;

    split_h<<<(MTOT * DMODEL / 4 + 255) / 256, 256>>>(x, xh, MTOT * DMODEL / 4);
    split_w4<<<dim3((WN / 4 + 255) / 256, 4), 256>>>(Wq, Wk, Wv, Wo, wh, wl);

    cudaFuncSetAttribute(gemm_hmma2, cudaFuncAttributeMaxDynamicSharedMemorySize, GEMM_SMEM);
    cudaFuncSetAttribute(attn_hmma, cudaFuncAttributeMaxDynamicSharedMemorySize, ATT_SMEM);

    GemmArgs3 qkv;
    qkv.g[0] = { xh, wh + 0 * WN, wl + 0 * WN, bq, nullptr, qh,  nullptr, 3, 1.0f };
    qkv.g[1] = { xh, wh + 1 * WN, wl + 1 * WN, bk, nullptr, kh,  kl,      1, K_FOLD };
    qkv.g[2] = { xh, wh + 2 * WN, wl + 2 * WN, bv, nullptr, vth, vtl,     2, 1.0f };
    gemm_hmma2<<<dim3(DMODEL / 128, MTOT / 128, 3), 256, GEMM_SMEM>>>(qkv);

    attn_hmma<<<dim3(SEQ / 128, BATCH * NHEADS), 256, ATT_SMEM>>>(qh, kh, kl, vth, vtl, ath);

    GemmArgs3 oproj;
    oproj.g[0] = { ath, wh + 3 * WN, wl + 3 * WN, bo, out, nullptr, nullptr, 0, 1.0f };
    oproj.g[1] = oproj.g[0];
    oproj.g[2] = oproj.g[0];
    gemm_hmma2<<<dim3(DMODEL / 128, MTOT / 128, 1), 256, GEMM_SMEM>>>(oproj);
}